// round 3
// baseline (speedup 1.0000x reference)
#include <cuda_runtime.h>
#include <cstddef>

// Problem constants
#define BB   4
#define TT   2048
#define DD   1024
#define HH   16
#define HDIM 64
#define MM   (BB*TT)   // 8192

// Scratch (device globals; no allocation allowed)
__device__ float g_q[BB*HH*TT*HDIM];   // [b][h][t][d]
__device__ float g_k[BB*HH*TT*HDIM];
__device__ float g_v[BB*HH*TT*HDIM];
__device__ float g_att[BB*TT*DD];      // [b][t][h*64+d]

// ---------------------------------------------------------------------------
// GEMM: C[M,N] = X[M,K] @ W[N,K]^T + bias[N]       (M=8192, N=K=1024)
// BM=BN=128, BK=16, 256 threads, 8x8 micro-tile per thread.
// HEAD_OUT=1 scatters output into [b][h][t][d] layout for attention.
// ---------------------------------------------------------------------------
template<int HEAD_OUT>
__global__ __launch_bounds__(256, 2)
void gemm_bias_kernel(const float* __restrict__ X, const float* __restrict__ W,
                      const float* __restrict__ bias, float* __restrict__ out)
{
    __shared__ float As[16][132];   // [k][m], +4 pad to reduce store conflicts
    __shared__ float Bs[16][132];   // [k][n]

    const int tid = threadIdx.x;
    const int bm  = blockIdx.y * 128;
    const int bn  = blockIdx.x * 128;
    const int tr  = tid >> 4;          // 0..15 -> rows tr*8..
    const int tc  = tid & 15;          // 0..15 -> cols tc*8..
    const int lr  = tid >> 2;          // 0..63 load row
    const int lc  = (tid & 3) << 2;    // 0,4,8,12 load col4

    float acc[8][8];
#pragma unroll
    for (int i = 0; i < 8; i++)
#pragma unroll
        for (int j = 0; j < 8; j++) acc[i][j] = 0.f;

    for (int k0 = 0; k0 < DD; k0 += 16) {
#pragma unroll
        for (int it = 0; it < 2; it++) {
            int r = lr + it * 64;
            float4 xv = *(const float4*)(X + (size_t)(bm + r) * DD + k0 + lc);
            As[lc+0][r] = xv.x; As[lc+1][r] = xv.y; As[lc+2][r] = xv.z; As[lc+3][r] = xv.w;
            float4 wv = *(const float4*)(W + (size_t)(bn + r) * DD + k0 + lc);
            Bs[lc+0][r] = wv.x; Bs[lc+1][r] = wv.y; Bs[lc+2][r] = wv.z; Bs[lc+3][r] = wv.w;
        }
        __syncthreads();
#pragma unroll
        for (int kk = 0; kk < 16; kk++) {
            float a[8], b[8];
            *(float4*)&a[0] = *(const float4*)&As[kk][tr*8];
            *(float4*)&a[4] = *(const float4*)&As[kk][tr*8 + 4];
            *(float4*)&b[0] = *(const float4*)&Bs[kk][tc*8];
            *(float4*)&b[4] = *(const float4*)&Bs[kk][tc*8 + 4];
#pragma unroll
            for (int i = 0; i < 8; i++)
#pragma unroll
                for (int j = 0; j < 8; j++) acc[i][j] += a[i] * b[j];
        }
        __syncthreads();
    }

#pragma unroll
    for (int i = 0; i < 8; i++) {
        int m = bm + tr*8 + i;
#pragma unroll
        for (int j = 0; j < 8; j++) {
            int n = bn + tc*8 + j;
            float v = acc[i][j] + bias[n];
            if (HEAD_OUT) {
                int b = m >> 11, t = m & (TT - 1);
                int h = n >> 6,  d = n & (HDIM - 1);
                out[((size_t)((b*HH + h)*TT + t) << 6) + d] = v;
            } else {
                out[(size_t)m * DD + n] = v;
            }
        }
    }
}

// ---------------------------------------------------------------------------
// Flash attention (causal), fp32. One block per (64 q rows, b*h).
// 256 threads; thread (tr,tc) owns 4 q rows x 4 k/d cols.
// Smem: Qt (d-major), KP (Kt d-major during S, aliased as P[q][k] for PV), Vs.
// Exactly 48 KB static smem.
// ---------------------------------------------------------------------------
__global__ __launch_bounds__(256, 2)
void flash_kernel(const float* __restrict__ Q, const float* __restrict__ K,
                  const float* __restrict__ V, float* __restrict__ Oout)
{
    __shared__ float Qt[64][64];   // [d][q]
    __shared__ float KP[64][64];   // Kt[d][k]  then  P[q][k]
    __shared__ float Vs[64][64];   // [k][d]

    const int tid = threadIdx.x;
    const int tr  = tid >> 4;      // 0..15  q rows tr*4..
    const int tc  = tid & 15;      // 0..15  k/d cols tc*4..
    const int bh  = blockIdx.y;    // b*16 + h
    const int qt  = blockIdx.x;
    const int q0  = qt * 64;

    const float* Qb = Q + (size_t)bh * TT * HDIM;
    const float* Kb = K + (size_t)bh * TT * HDIM;
    const float* Vb = V + (size_t)bh * TT * HDIM;

    // Load Q tile transposed into smem, pre-scaled by 1/sqrt(64)
#pragma unroll
    for (int it = 0; it < 4; it++) {
        int idx = tid + it * 256;
        int r   = idx & 63;
        int d4  = (idx >> 6) << 2;
        float4 v = *(const float4*)(Qb + (size_t)(q0 + r) * HDIM + d4);
        Qt[d4+0][r] = v.x * 0.125f;
        Qt[d4+1][r] = v.y * 0.125f;
        Qt[d4+2][r] = v.z * 0.125f;
        Qt[d4+3][r] = v.w * 0.125f;
    }

    float o[4][4] = {};
    float mi[4], li[4];
#pragma unroll
    for (int i = 0; i < 4; i++) { mi[i] = -1e30f; li[i] = 0.f; }

    for (int j = 0; j <= qt; j++) {
        const int k0 = j * 64;
        __syncthreads();   // protects KP/Vs reuse from previous iteration (and Qt on iter 0)

        // Load K (transposed) and V (straight)
#pragma unroll
        for (int it = 0; it < 4; it++) {
            int idx = tid + it * 256;
            int r   = idx & 63;
            int d4  = (idx >> 6) << 2;
            float4 kv = *(const float4*)(Kb + (size_t)(k0 + r) * HDIM + d4);
            KP[d4+0][r] = kv.x; KP[d4+1][r] = kv.y; KP[d4+2][r] = kv.z; KP[d4+3][r] = kv.w;
            float4 vv = *(const float4*)(Vb + (size_t)(k0 + r) * HDIM + d4);
            *(float4*)&Vs[r][d4] = vv;
        }
        __syncthreads();

        // S = Q @ K^T  (scaled)
        float s[4][4] = {};
#pragma unroll 16
        for (int d = 0; d < 64; d++) {
            float qv[4], kv[4];
            *(float4*)qv = *(const float4*)&Qt[d][tr*4];
            *(float4*)kv = *(const float4*)&KP[d][tc*4];
#pragma unroll
            for (int i = 0; i < 4; i++)
#pragma unroll
                for (int jj = 0; jj < 4; jj++) s[i][jj] += qv[i] * kv[jj];
        }

        // Causal mask (diagonal tile only)
        if (j == qt) {
#pragma unroll
            for (int i = 0; i < 4; i++) {
                int qg = tr*4 + i;
#pragma unroll
                for (int jj = 0; jj < 4; jj++)
                    if (tc*4 + jj > qg) s[i][jj] = -1e30f;
            }
        }

        // Online softmax (row groups = 16 contiguous lanes)
        float p[4][4];
#pragma unroll
        for (int i = 0; i < 4; i++) {
            float mx = fmaxf(fmaxf(s[i][0], s[i][1]), fmaxf(s[i][2], s[i][3]));
#pragma unroll
            for (int off = 8; off > 0; off >>= 1)
                mx = fmaxf(mx, __shfl_xor_sync(0xffffffffu, mx, off, 16));
            float mn = fmaxf(mi[i], mx);
            float c  = __expf(mi[i] - mn);
            float sum = 0.f;
#pragma unroll
            for (int jj = 0; jj < 4; jj++) { p[i][jj] = __expf(s[i][jj] - mn); sum += p[i][jj]; }
#pragma unroll
            for (int off = 8; off > 0; off >>= 1)
                sum += __shfl_xor_sync(0xffffffffu, sum, off, 16);
            li[i] = li[i] * c + sum;
            mi[i] = mn;
#pragma unroll
            for (int jj = 0; jj < 4; jj++) o[i][jj] *= c;
        }

        __syncthreads();   // all threads done reading KP as Kt
#pragma unroll
        for (int i = 0; i < 4; i++)
            *(float4*)&KP[tr*4 + i][tc*4] = *(const float4*)&p[i][0];  // P[q][k]
        __syncthreads();

        // O += P @ V
#pragma unroll 8
        for (int k4 = 0; k4 < 64; k4 += 4) {
            float pv[4][4], vv[4][4];
#pragma unroll
            for (int i = 0; i < 4; i++)
                *(float4*)pv[i] = *(const float4*)&KP[tr*4 + i][k4];
#pragma unroll
            for (int kk = 0; kk < 4; kk++)
                *(float4*)vv[kk] = *(const float4*)&Vs[k4 + kk][tc*4];
#pragma unroll
            for (int i = 0; i < 4; i++)
#pragma unroll
                for (int jj = 0; jj < 4; jj++)
#pragma unroll
                    for (int kk = 0; kk < 4; kk++)
                        o[i][jj] += pv[i][kk] * vv[kk][jj];
        }
    }

    // Write O / l back as [b][t][h*64+d]
    const int b = bh >> 4, h = bh & 15;
#pragma unroll
    for (int i = 0; i < 4; i++) {
        int t = q0 + tr*4 + i;
        float inv = 1.f / li[i];
        float4 vv;
        vv.x = o[i][0]*inv; vv.y = o[i][1]*inv; vv.z = o[i][2]*inv; vv.w = o[i][3]*inv;
        *(float4*)(Oout + (size_t)(b*TT + t) * DD + h*HDIM + tc*4) = vv;
    }
}

// ---------------------------------------------------------------------------
extern "C" void kernel_launch(void* const* d_in, const int* in_sizes, int n_in,
                              void* d_out, int out_size)
{
    const float* q  = (const float*)d_in[0];
    const float* k  = (const float*)d_in[1];
    const float* v  = (const float*)d_in[2];
    const float* wq = (const float*)d_in[3];
    const float* bq = (const float*)d_in[4];
    const float* wk = (const float*)d_in[5];
    const float* bk = (const float*)d_in[6];
    const float* wv = (const float*)d_in[7];
    const float* bv = (const float*)d_in[8];
    const float* wo = (const float*)d_in[9];
    const float* bo = (const float*)d_in[10];
    float* out = (float*)d_out;

    float *gq, *gk, *gv, *gatt;
    cudaGetSymbolAddress((void**)&gq,   g_q);
    cudaGetSymbolAddress((void**)&gk,   g_k);
    cudaGetSymbolAddress((void**)&gv,   g_v);
    cudaGetSymbolAddress((void**)&gatt, g_att);

    dim3 gg(DD/128, MM/128);           // (8, 64)
    gemm_bias_kernel<1><<<gg, 256>>>(q, wq, bq, gq);
    gemm_bias_kernel<1><<<gg, 256>>>(k, wk, bk, gk);
    gemm_bias_kernel<1><<<gg, 256>>>(v, wv, bv, gv);

    flash_kernel<<<dim3(TT/64, BB*HH), 256>>>(gq, gk, gv, gatt);

    gemm_bias_kernel<0><<<gg, 256>>>(gatt, wo, bo, out);
}

// round 7
// speedup vs baseline: 1.5778x; 1.5778x over previous
#include <cuda_runtime.h>
#include <cuda_bf16.h>
#include <cstdint>
#include <cstddef>

// Problem constants
#define BB   4
#define TT   2048
#define DD   1024
#define HH   16
#define HDIM 64
#define MM   (BB*TT)   // 8192
#define GK   3072      // split-bf16 concatenated K ( [h|l|h] x [h|h|l] )
#define BKC  64        // bf16 K per pipeline stage (128B rows, SW128)
#define NCHUNK (GK/BKC) // 48
#define STAGES 3
#define STAGE_BYTES 32768          // A 16KB + B 16KB
#define GEMM_SMEM_SZ (STAGES*STAGE_BYTES)   // 96KB

// Scratch (device globals; no allocation allowed)
__device__ float g_q[BB*HH*TT*HDIM];            // [b][h][t][d]
__device__ float g_k[BB*HH*TT*HDIM];
__device__ float g_v[BB*HH*TT*HDIM];
__device__ float g_att[BB*TT*DD];               // [b][t][h*64+d]
__device__ __nv_bfloat16 g_xc[(size_t)MM*GK];   // converted activations
__device__ __nv_bfloat16 g_wc[(size_t)DD*GK];   // converted weights

// ---------------------------------------------------------------------------
// Portable (non-'a') PTX helpers: cp.async, ldmatrix, mma.sync
// ---------------------------------------------------------------------------
__device__ __forceinline__ uint32_t smem_to_u32(const void* p) {
    uint32_t a;
    asm("{ .reg .u64 t; cvta.to.shared.u64 t, %1; cvt.u32.u64 %0, t; }" : "=r"(a) : "l"(p));
    return a;
}
__device__ __forceinline__ void cp16(uint32_t saddr, const void* g) {
    asm volatile("cp.async.cg.shared.global [%0], [%1], 16;" :: "r"(saddr), "l"(g));
}
__device__ __forceinline__ void cp_commit() {
    asm volatile("cp.async.commit_group;" ::: "memory");
}
__device__ __forceinline__ void ldsm_x4(uint32_t* r, uint32_t addr) {
    asm volatile("ldmatrix.sync.aligned.m8n8.x4.shared.b16 {%0,%1,%2,%3}, [%4];"
        : "=r"(r[0]), "=r"(r[1]), "=r"(r[2]), "=r"(r[3]) : "r"(addr));
}
__device__ __forceinline__ void ldsm_x2(uint32_t* r, uint32_t addr) {
    asm volatile("ldmatrix.sync.aligned.m8n8.x2.shared.b16 {%0,%1}, [%2];"
        : "=r"(r[0]), "=r"(r[1]) : "r"(addr));
}
__device__ __forceinline__ void mma_bf16(float* c, const uint32_t* a, const uint32_t* b) {
    asm volatile("mma.sync.aligned.m16n8k16.row.col.f32.bf16.bf16.f32 "
        "{%0,%1,%2,%3}, {%4,%5,%6,%7}, {%8,%9}, {%0,%1,%2,%3};"
        : "+f"(c[0]), "+f"(c[1]), "+f"(c[2]), "+f"(c[3])
        : "r"(a[0]), "r"(a[1]), "r"(a[2]), "r"(a[3]), "r"(b[0]), "r"(b[1]));
}
#define SMEM_SWIZZLE_128B(off) ((off) ^ (((off) >> 3) & 0x70))

// ---------------------------------------------------------------------------
// Split conversion: fp32 [rows,1024] -> bf16 [rows,3072]
// WMODE=0 (activations): [hi | lo | hi];  WMODE=1 (weights): [hi | hi | lo]
// ---------------------------------------------------------------------------
template<int WMODE>
__global__ void convert_split_kernel(const float* __restrict__ in,
                                     __nv_bfloat16* __restrict__ out, int rows)
{
    int i = blockIdx.x * 256 + threadIdx.x;
    int row = i >> 8;
    int c = (i & 255) << 2;
    if (row >= rows) return;
    float4 x = *(const float4*)(in + (size_t)row * 1024 + c);
    __nv_bfloat16 h0 = __float2bfloat16(x.x);
    __nv_bfloat16 h1 = __float2bfloat16(x.y);
    __nv_bfloat16 h2 = __float2bfloat16(x.z);
    __nv_bfloat16 h3 = __float2bfloat16(x.w);
    __nv_bfloat16 l0 = __float2bfloat16(x.x - __bfloat162float(h0));
    __nv_bfloat16 l1 = __float2bfloat16(x.y - __bfloat162float(h1));
    __nv_bfloat16 l2 = __float2bfloat16(x.z - __bfloat162float(h2));
    __nv_bfloat16 l3 = __float2bfloat16(x.w - __bfloat162float(h3));
    __nv_bfloat162 hA = __halves2bfloat162(h0, h1), hB = __halves2bfloat162(h2, h3);
    __nv_bfloat162 lA = __halves2bfloat162(l0, l1), lB = __halves2bfloat162(l2, l3);
    size_t base = (size_t)row * GK + c;
    __nv_bfloat162* o0 = (__nv_bfloat162*)(out + base);
    __nv_bfloat162* o1 = (__nv_bfloat162*)(out + base + 1024);
    __nv_bfloat162* o2 = (__nv_bfloat162*)(out + base + 2048);
    o0[0] = hA; o0[1] = hB;
    if (WMODE) { o1[0] = hA; o1[1] = hB; o2[0] = lA; o2[1] = lB; }
    else       { o1[0] = lA; o1[1] = lB; o2[0] = hA; o2[1] = hB; }
}

// ---------------------------------------------------------------------------
// HMMA GEMM: C[M,N] = A[M,GK] @ B[N,GK]^T + bias   (128x128 CTA tile)
// 8 warps (2m x 4n), warp tile 64x32, mma.sync m16n8k16 bf16.
// cp.async 3-stage pipeline, SW128-swizzled smem, ldmatrix operand loads.
// head_out=1 scatters to [b][h][t][d].
// ---------------------------------------------------------------------------
__global__ __launch_bounds__(256)
void hmma_gemm_kernel(const __nv_bfloat16* __restrict__ A,
                      const __nv_bfloat16* __restrict__ B,
                      const float* __restrict__ bias,
                      float* __restrict__ out, int head_out)
{
    extern __shared__ char smem[];
    const uint32_t sb = smem_to_u32(smem);
    const int tid  = threadIdx.x;
    const int wid  = tid >> 5, lane = tid & 31;
    const int warp_m = wid >> 2;       // 0..1  (64 rows each)
    const int warp_n = wid & 3;        // 0..3  (32 cols each)
    const int bm = blockIdx.y * 128, bn = blockIdx.x * 128;

    // Global->smem mapping: 4 A-chunks + 4 B-chunks (16B each) per thread
    const __nv_bfloat16* Ag[4];
    const __nv_bfloat16* Bg[4];
    uint32_t sOffA[4], sOffB[4];
#pragma unroll
    for (int i = 0; i < 4; i++) {
        int id = tid + i * 256;            // 0..1023
        int grow = id >> 3, gch = id & 7;  // row 0..127, 16B-chunk 0..7
        Ag[i] = A + (size_t)(bm + grow) * GK + gch * 8;
        Bg[i] = B + (size_t)(bn + grow) * GK + gch * 8;
        sOffA[i] = SMEM_SWIZZLE_128B((uint32_t)(grow * 128 + gch * 16));
        sOffB[i] = sOffA[i] + 16384;
    }

    // Prologue: stages 0,1
#pragma unroll
    for (int s = 0; s < 2; s++) {
        uint32_t base = sb + s * STAGE_BYTES;
        int k0 = s * BKC;
#pragma unroll
        for (int i = 0; i < 4; i++) {
            cp16(base + sOffA[i], Ag[i] + k0);
            cp16(base + sOffB[i], Bg[i] + k0);
        }
        cp_commit();
    }

    // Fragment address precompute (per-lane)
    uint32_t arbase[4], axor[4];
    const int ahi = (lane >> 4) & 1;       // which 16B chunk half for A
#pragma unroll
    for (int mi = 0; mi < 4; mi++) {
        int row = warp_m * 64 + mi * 16 + (lane & 15);
        arbase[mi] = (uint32_t)row * 128;
        axor[mi]   = (uint32_t)(row & 7) * 16;
    }
    uint32_t brbase[4], bxor[4];
    const int lq = lane & 15;
    const int bhi = (lq >> 3) & 1;
#pragma unroll
    for (int ni = 0; ni < 4; ni++) {
        int row = warp_n * 32 + ni * 8 + (lq & 7);
        brbase[ni] = (uint32_t)row * 128 + 16384;
        bxor[ni]   = (uint32_t)(row & 7) * 16;
    }

    float acc[4][4][4];
#pragma unroll
    for (int mi = 0; mi < 4; mi++)
#pragma unroll
        for (int ni = 0; ni < 4; ni++)
#pragma unroll
            for (int e = 0; e < 4; e++) acc[mi][ni][e] = 0.f;

    for (int c = 0; c < NCHUNK; c++) {
        if (c < NCHUNK - 1) asm volatile("cp.async.wait_group 1;" ::: "memory");
        else                asm volatile("cp.async.wait_group 0;" ::: "memory");
        __syncthreads();

        // Issue stage c+2 (overlaps with compute of stage c)
        if (c + 2 < NCHUNK) {
            uint32_t base = sb + ((c + 2) % STAGES) * STAGE_BYTES;
            int k0 = (c + 2) * BKC;
#pragma unroll
            for (int i = 0; i < 4; i++) {
                cp16(base + sOffA[i], Ag[i] + k0);
                cp16(base + sOffB[i], Bg[i] + k0);
            }
            cp_commit();
        }

        const uint32_t stage = sb + (c % STAGES) * STAGE_BYTES;
#pragma unroll
        for (int ks = 0; ks < 4; ks++) {
            uint32_t af[4][4], bf[4][2];
#pragma unroll
            for (int mi = 0; mi < 4; mi++)
                ldsm_x4(af[mi], stage + arbase[mi] +
                        ((uint32_t)((ks * 2 + ahi) * 16) ^ axor[mi]));
#pragma unroll
            for (int ni = 0; ni < 4; ni++)
                ldsm_x2(bf[ni], stage + brbase[ni] +
                        ((uint32_t)((ks * 2 + bhi) * 16) ^ bxor[ni]));
#pragma unroll
            for (int mi = 0; mi < 4; mi++)
#pragma unroll
                for (int ni = 0; ni < 4; ni++)
                    mma_bf16(acc[mi][ni], af[mi], bf[ni]);
        }
    }

    // Epilogue: direct register -> gmem (float2 per fragment row), + bias
    const int qrow = lane >> 2;            // 0..7
    const int qcol = (lane & 3) * 2;       // 0,2,4,6
#pragma unroll
    for (int mi = 0; mi < 4; mi++) {
        int m_lo = bm + warp_m * 64 + mi * 16 + qrow;
        int m_hi = m_lo + 8;
#pragma unroll
        for (int ni = 0; ni < 4; ni++) {
            int n = bn + warp_n * 32 + ni * 8 + qcol;
            float2 bv = *(const float2*)(bias + n);
            float2 lo, hi;
            lo.x = acc[mi][ni][0] + bv.x; lo.y = acc[mi][ni][1] + bv.y;
            hi.x = acc[mi][ni][2] + bv.x; hi.y = acc[mi][ni][3] + bv.y;
            if (head_out) {
                int h = n >> 6, d0 = n & (HDIM - 1);
                int b0 = m_lo >> 11, t0 = m_lo & (TT - 1);
                int b1 = m_hi >> 11, t1 = m_hi & (TT - 1);
                *(float2*)(out + ((size_t)((b0*HH + h)*TT + t0) << 6) + d0) = lo;
                *(float2*)(out + ((size_t)((b1*HH + h)*TT + t1) << 6) + d0) = hi;
            } else {
                *(float2*)(out + (size_t)m_lo * DD + n) = lo;
                *(float2*)(out + (size_t)m_hi * DD + n) = hi;
            }
        }
    }
}

// ---------------------------------------------------------------------------
// Flash attention (causal), fp32 (unchanged from passing R1 kernel)
// ---------------------------------------------------------------------------
__global__ __launch_bounds__(256, 2)
void flash_kernel(const float* __restrict__ Q, const float* __restrict__ K,
                  const float* __restrict__ V, float* __restrict__ Oout)
{
    __shared__ float Qt[64][64];   // [d][q]
    __shared__ float KP[64][64];   // Kt[d][k]  then  P[q][k]
    __shared__ float Vs[64][64];   // [k][d]

    const int tid = threadIdx.x;
    const int tr  = tid >> 4;
    const int tc  = tid & 15;
    const int bh  = blockIdx.y;
    const int qt  = blockIdx.x;
    const int q0  = qt * 64;

    const float* Qb = Q + (size_t)bh * TT * HDIM;
    const float* Kb = K + (size_t)bh * TT * HDIM;
    const float* Vb = V + (size_t)bh * TT * HDIM;

#pragma unroll
    for (int it = 0; it < 4; it++) {
        int idx = tid + it * 256;
        int r   = idx & 63;
        int d4  = (idx >> 6) << 2;
        float4 v = *(const float4*)(Qb + (size_t)(q0 + r) * HDIM + d4);
        Qt[d4+0][r] = v.x * 0.125f;
        Qt[d4+1][r] = v.y * 0.125f;
        Qt[d4+2][r] = v.z * 0.125f;
        Qt[d4+3][r] = v.w * 0.125f;
    }

    float o[4][4] = {};
    float mi[4], li[4];
#pragma unroll
    for (int i = 0; i < 4; i++) { mi[i] = -1e30f; li[i] = 0.f; }

    for (int j = 0; j <= qt; j++) {
        const int k0 = j * 64;
        __syncthreads();

#pragma unroll
        for (int it = 0; it < 4; it++) {
            int idx = tid + it * 256;
            int r   = idx & 63;
            int d4  = (idx >> 6) << 2;
            float4 kv = *(const float4*)(Kb + (size_t)(k0 + r) * HDIM + d4);
            KP[d4+0][r] = kv.x; KP[d4+1][r] = kv.y; KP[d4+2][r] = kv.z; KP[d4+3][r] = kv.w;
            float4 vv = *(const float4*)(Vb + (size_t)(k0 + r) * HDIM + d4);
            *(float4*)&Vs[r][d4] = vv;
        }
        __syncthreads();

        float s[4][4] = {};
#pragma unroll 16
        for (int d = 0; d < 64; d++) {
            float qv[4], kv[4];
            *(float4*)qv = *(const float4*)&Qt[d][tr*4];
            *(float4*)kv = *(const float4*)&KP[d][tc*4];
#pragma unroll
            for (int i = 0; i < 4; i++)
#pragma unroll
                for (int jj = 0; jj < 4; jj++) s[i][jj] += qv[i] * kv[jj];
        }

        if (j == qt) {
#pragma unroll
            for (int i = 0; i < 4; i++) {
                int qg = tr*4 + i;
#pragma unroll
                for (int jj = 0; jj < 4; jj++)
                    if (tc*4 + jj > qg) s[i][jj] = -1e30f;
            }
        }

        float p[4][4];
#pragma unroll
        for (int i = 0; i < 4; i++) {
            float mx = fmaxf(fmaxf(s[i][0], s[i][1]), fmaxf(s[i][2], s[i][3]));
#pragma unroll
            for (int off = 8; off > 0; off >>= 1)
                mx = fmaxf(mx, __shfl_xor_sync(0xffffffffu, mx, off, 16));
            float mn = fmaxf(mi[i], mx);
            float cc = __expf(mi[i] - mn);
            float sum = 0.f;
#pragma unroll
            for (int jj = 0; jj < 4; jj++) { p[i][jj] = __expf(s[i][jj] - mn); sum += p[i][jj]; }
#pragma unroll
            for (int off = 8; off > 0; off >>= 1)
                sum += __shfl_xor_sync(0xffffffffu, sum, off, 16);
            li[i] = li[i] * cc + sum;
            mi[i] = mn;
#pragma unroll
            for (int jj = 0; jj < 4; jj++) o[i][jj] *= cc;
        }

        __syncthreads();
#pragma unroll
        for (int i = 0; i < 4; i++)
            *(float4*)&KP[tr*4 + i][tc*4] = *(const float4*)&p[i][0];
        __syncthreads();

#pragma unroll 8
        for (int k4 = 0; k4 < 64; k4 += 4) {
            float pv[4][4], vv[4][4];
#pragma unroll
            for (int i = 0; i < 4; i++)
                *(float4*)pv[i] = *(const float4*)&KP[tr*4 + i][k4];
#pragma unroll
            for (int kk = 0; kk < 4; kk++)
                *(float4*)vv[kk] = *(const float4*)&Vs[k4 + kk][tc*4];
#pragma unroll
            for (int i = 0; i < 4; i++)
#pragma unroll
                for (int jj = 0; jj < 4; jj++)
#pragma unroll
                    for (int kk = 0; kk < 4; kk++)
                        o[i][jj] += pv[i][kk] * vv[kk][jj];
        }
    }

    const int b = bh >> 4, h = bh & 15;
#pragma unroll
    for (int i = 0; i < 4; i++) {
        int t = q0 + tr*4 + i;
        float inv = 1.f / li[i];
        float4 vv;
        vv.x = o[i][0]*inv; vv.y = o[i][1]*inv; vv.z = o[i][2]*inv; vv.w = o[i][3]*inv;
        *(float4*)(Oout + (size_t)(b*TT + t) * DD + h*HDIM + tc*4) = vv;
    }
}

// ---------------------------------------------------------------------------
extern "C" void kernel_launch(void* const* d_in, const int* in_sizes, int n_in,
                              void* d_out, int out_size)
{
    const float* q  = (const float*)d_in[0];
    const float* k  = (const float*)d_in[1];
    const float* v  = (const float*)d_in[2];
    const float* wq = (const float*)d_in[3];
    const float* bq = (const float*)d_in[4];
    const float* wk = (const float*)d_in[5];
    const float* bk = (const float*)d_in[6];
    const float* wv = (const float*)d_in[7];
    const float* bv = (const float*)d_in[8];
    const float* wo = (const float*)d_in[9];
    const float* bo = (const float*)d_in[10];
    float* out = (float*)d_out;

    float *gq, *gk, *gv, *gatt;
    __nv_bfloat16 *gxc, *gwc;
    cudaGetSymbolAddress((void**)&gq,   g_q);
    cudaGetSymbolAddress((void**)&gk,   g_k);
    cudaGetSymbolAddress((void**)&gv,   g_v);
    cudaGetSymbolAddress((void**)&gatt, g_att);
    cudaGetSymbolAddress((void**)&gxc,  g_xc);
    cudaGetSymbolAddress((void**)&gwc,  g_wc);

    cudaFuncSetAttribute(hmma_gemm_kernel,
                         cudaFuncAttributeMaxDynamicSharedMemorySize, GEMM_SMEM_SZ);

    dim3 gg(DD / 128, MM / 128);          // (8, 64)
    const int xblocks = MM;               // 8192 blocks of 256 -> 256 elems each
    const int wblocks = DD;               // 1024

    // Q projection
    convert_split_kernel<0><<<xblocks, 256>>>(q, gxc, MM);
    convert_split_kernel<1><<<wblocks, 256>>>(wq, gwc, DD);
    hmma_gemm_kernel<<<gg, 256, GEMM_SMEM_SZ>>>(gxc, gwc, bq, gq, 1);
    // K projection
    convert_split_kernel<0><<<xblocks, 256>>>(k, gxc, MM);
    convert_split_kernel<1><<<wblocks, 256>>>(wk, gwc, DD);
    hmma_gemm_kernel<<<gg, 256, GEMM_SMEM_SZ>>>(gxc, gwc, bk, gk, 1);
    // V projection
    convert_split_kernel<0><<<xblocks, 256>>>(v, gxc, MM);
    convert_split_kernel<1><<<wblocks, 256>>>(wv, gwc, DD);
    hmma_gemm_kernel<<<gg, 256, GEMM_SMEM_SZ>>>(gxc, gwc, bv, gv, 1);

    // Attention
    flash_kernel<<<dim3(TT / 64, BB * HH), 256>>>(gq, gk, gv, gatt);

    // Output projection
    convert_split_kernel<0><<<xblocks, 256>>>(gatt, gxc, MM);
    convert_split_kernel<1><<<wblocks, 256>>>(wo, gwc, DD);
    hmma_gemm_kernel<<<gg, 256, GEMM_SMEM_SZ>>>(gxc, gwc, bo, out, 0);
}

// round 12
// speedup vs baseline: 2.9526x; 1.8714x over previous
#include <cuda_runtime.h>
#include <cuda_bf16.h>
#include <cstdint>
#include <cstddef>

// Problem constants
#define BB   4
#define TT   2048
#define DD   1024
#define HH   16
#define HDIM 64
#define MM   (BB*TT)   // 8192
#define GK   3072      // split-bf16 concatenated K ( [h|l|h] x [h|h|l] )
#define BKC  64        // bf16 K per GEMM pipeline stage
#define NCHUNK (GK/BKC) // 48
#define STAGES 3
#define STAGE_BYTES 32768
#define GEMM_SMEM_SZ (STAGES*STAGE_BYTES)   // 96KB

// Flash smem layout (dynamic, 96KB):
//  [0,16K)   Qh plane  128 rows x 128B (SW128)
//  [16K,32K) Ql plane
//  stage s at 32K + s*32K:  Kh(8K) Kl(8K) Vh(8K) Vl(8K)
#define FL_QH   0u
#define FL_QL   16384u
#define FL_STG  32768u
#define FL_SMEM 98304

// Scratch (device globals; no allocation allowed)
__device__ __nv_bfloat16 g_qc[(size_t)BB*HH*TT*128];  // [b][h][t][hi(64)|lo(64)]
__device__ __nv_bfloat16 g_kc[(size_t)BB*HH*TT*128];
__device__ __nv_bfloat16 g_vc[(size_t)BB*HH*TT*128];
__device__ __nv_bfloat16 g_xc[(size_t)MM*GK];         // activations [hi|lo|hi]
__device__ __nv_bfloat16 g_wc[(size_t)DD*GK];         // weights [hi|hi|lo]

// ---------------------------------------------------------------------------
// Portable PTX helpers (no sm_103a-only instructions!)
// ---------------------------------------------------------------------------
__device__ __forceinline__ uint32_t smem_to_u32(const void* p) {
    uint32_t a;
    asm("{ .reg .u64 t; cvta.to.shared.u64 t, %1; cvt.u32.u64 %0, t; }" : "=r"(a) : "l"(p));
    return a;
}
__device__ __forceinline__ void cp16(uint32_t saddr, const void* g) {
    asm volatile("cp.async.cg.shared.global [%0], [%1], 16;" :: "r"(saddr), "l"(g));
}
__device__ __forceinline__ void cp_commit() {
    asm volatile("cp.async.commit_group;" ::: "memory");
}
__device__ __forceinline__ void ldsm_x4(uint32_t* r, uint32_t addr) {
    asm volatile("ldmatrix.sync.aligned.m8n8.x4.shared.b16 {%0,%1,%2,%3}, [%4];"
        : "=r"(r[0]), "=r"(r[1]), "=r"(r[2]), "=r"(r[3]) : "r"(addr));
}
__device__ __forceinline__ void ldsm_x2(uint32_t* r, uint32_t addr) {
    asm volatile("ldmatrix.sync.aligned.m8n8.x2.shared.b16 {%0,%1}, [%2];"
        : "=r"(r[0]), "=r"(r[1]) : "r"(addr));
}
__device__ __forceinline__ void ldsm_x2_trans(uint32_t* r, uint32_t addr) {
    asm volatile("ldmatrix.sync.aligned.m8n8.x2.trans.shared.b16 {%0,%1}, [%2];"
        : "=r"(r[0]), "=r"(r[1]) : "r"(addr));
}
__device__ __forceinline__ void mma_bf16(float* c, const uint32_t* a, const uint32_t* b) {
    asm volatile("mma.sync.aligned.m16n8k16.row.col.f32.bf16.bf16.f32 "
        "{%0,%1,%2,%3}, {%4,%5,%6,%7}, {%8,%9}, {%0,%1,%2,%3};"
        : "+f"(c[0]), "+f"(c[1]), "+f"(c[2]), "+f"(c[3])
        : "r"(a[0]), "r"(a[1]), "r"(a[2]), "r"(a[3]), "r"(b[0]), "r"(b[1]));
}
// pack {lo,hi} f32 -> bf16x2 (lo in bits[15:0])
__device__ __forceinline__ uint32_t packbf2(float lo, float hi) {
    uint32_t r;
    asm("cvt.rn.bf16x2.f32 %0, %1, %2;" : "=r"(r) : "f"(hi), "f"(lo));
    return r;
}
__device__ __forceinline__ uint32_t packh2(__nv_bfloat16 a, __nv_bfloat16 b) {
    __nv_bfloat162 t = __halves2bfloat162(a, b);
    return *reinterpret_cast<uint32_t*>(&t);
}
#define SMEM_SWIZZLE_128B(off) ((off) ^ (((off) >> 3) & 0x70))

// ---------------------------------------------------------------------------
// Split conversion: fp32 [rows,1024] -> bf16 [rows,3072]
// WMODE=0 (activations): [hi | lo | hi];  WMODE=1 (weights): [hi | hi | lo]
// ---------------------------------------------------------------------------
template<int WMODE>
__global__ void convert_split_kernel(const float* __restrict__ in,
                                     __nv_bfloat16* __restrict__ out, int rows)
{
    int i = blockIdx.x * 256 + threadIdx.x;
    int row = i >> 8;
    int c = (i & 255) << 2;
    if (row >= rows) return;
    float4 x = *(const float4*)(in + (size_t)row * 1024 + c);
    __nv_bfloat16 h0 = __float2bfloat16(x.x);
    __nv_bfloat16 h1 = __float2bfloat16(x.y);
    __nv_bfloat16 h2 = __float2bfloat16(x.z);
    __nv_bfloat16 h3 = __float2bfloat16(x.w);
    __nv_bfloat16 l0 = __float2bfloat16(x.x - __bfloat162float(h0));
    __nv_bfloat16 l1 = __float2bfloat16(x.y - __bfloat162float(h1));
    __nv_bfloat16 l2 = __float2bfloat16(x.z - __bfloat162float(h2));
    __nv_bfloat16 l3 = __float2bfloat16(x.w - __bfloat162float(h3));
    __nv_bfloat162 hA = __halves2bfloat162(h0, h1), hB = __halves2bfloat162(h2, h3);
    __nv_bfloat162 lA = __halves2bfloat162(l0, l1), lB = __halves2bfloat162(l2, l3);
    size_t base = (size_t)row * GK + c;
    __nv_bfloat162* o0 = (__nv_bfloat162*)(out + base);
    __nv_bfloat162* o1 = (__nv_bfloat162*)(out + base + 1024);
    __nv_bfloat162* o2 = (__nv_bfloat162*)(out + base + 2048);
    o0[0] = hA; o0[1] = hB;
    if (WMODE) { o1[0] = hA; o1[1] = hB; o2[0] = lA; o2[1] = lB; }
    else       { o1[0] = lA; o1[1] = lB; o2[0] = hA; o2[1] = hB; }
}

// ---------------------------------------------------------------------------
// HMMA GEMM: C[M,N] = A[M,GK] @ B[N,GK]^T + bias   (128x128 CTA tile)
// OUT_MODE 0: fp32 [m][1024].  OUT_MODE 1: split bf16 head layout
//   [b][h][t][hi(64)|lo(64)], value scaled by `scale` before split.
// ---------------------------------------------------------------------------
template<int OUT_MODE>
__global__ __launch_bounds__(256)
void hmma_gemm_kernel(const __nv_bfloat16* __restrict__ A,
                      const __nv_bfloat16* __restrict__ B,
                      const float* __restrict__ bias,
                      void* __restrict__ outv, float scale)
{
    extern __shared__ char smem[];
    const uint32_t sb = smem_to_u32(smem);
    const int tid  = threadIdx.x;
    const int wid  = tid >> 5, lane = tid & 31;
    const int warp_m = wid >> 2;
    const int warp_n = wid & 3;
    const int bm = blockIdx.y * 128, bn = blockIdx.x * 128;

    const __nv_bfloat16* Ag[4];
    const __nv_bfloat16* Bg[4];
    uint32_t sOffA[4], sOffB[4];
#pragma unroll
    for (int i = 0; i < 4; i++) {
        int id = tid + i * 256;
        int grow = id >> 3, gch = id & 7;
        Ag[i] = A + (size_t)(bm + grow) * GK + gch * 8;
        Bg[i] = B + (size_t)(bn + grow) * GK + gch * 8;
        sOffA[i] = SMEM_SWIZZLE_128B((uint32_t)(grow * 128 + gch * 16));
        sOffB[i] = sOffA[i] + 16384;
    }

#pragma unroll
    for (int s = 0; s < 2; s++) {
        uint32_t base = sb + s * STAGE_BYTES;
        int k0 = s * BKC;
#pragma unroll
        for (int i = 0; i < 4; i++) {
            cp16(base + sOffA[i], Ag[i] + k0);
            cp16(base + sOffB[i], Bg[i] + k0);
        }
        cp_commit();
    }

    uint32_t arbase[4], axor[4];
    const int ahi = (lane >> 4) & 1;
#pragma unroll
    for (int mi = 0; mi < 4; mi++) {
        int row = warp_m * 64 + mi * 16 + (lane & 15);
        arbase[mi] = (uint32_t)row * 128;
        axor[mi]   = (uint32_t)(row & 7) * 16;
    }
    uint32_t brbase[4], bxor[4];
    const int lq = lane & 15;
    const int bhi = (lq >> 3) & 1;
#pragma unroll
    for (int ni = 0; ni < 4; ni++) {
        int row = warp_n * 32 + ni * 8 + (lq & 7);
        brbase[ni] = (uint32_t)row * 128 + 16384;
        bxor[ni]   = (uint32_t)(row & 7) * 16;
    }

    float acc[4][4][4];
#pragma unroll
    for (int mi = 0; mi < 4; mi++)
#pragma unroll
        for (int ni = 0; ni < 4; ni++)
#pragma unroll
            for (int e = 0; e < 4; e++) acc[mi][ni][e] = 0.f;

    for (int c = 0; c < NCHUNK; c++) {
        if (c < NCHUNK - 1) asm volatile("cp.async.wait_group 1;" ::: "memory");
        else                asm volatile("cp.async.wait_group 0;" ::: "memory");
        __syncthreads();

        if (c + 2 < NCHUNK) {
            uint32_t base = sb + ((c + 2) % STAGES) * STAGE_BYTES;
            int k0 = (c + 2) * BKC;
#pragma unroll
            for (int i = 0; i < 4; i++) {
                cp16(base + sOffA[i], Ag[i] + k0);
                cp16(base + sOffB[i], Bg[i] + k0);
            }
            cp_commit();
        }

        const uint32_t stage = sb + (c % STAGES) * STAGE_BYTES;
#pragma unroll
        for (int ks = 0; ks < 4; ks++) {
            uint32_t af[4][4], bf[4][2];
#pragma unroll
            for (int mi = 0; mi < 4; mi++)
                ldsm_x4(af[mi], stage + arbase[mi] +
                        ((uint32_t)((ks * 2 + ahi) * 16) ^ axor[mi]));
#pragma unroll
            for (int ni = 0; ni < 4; ni++)
                ldsm_x2(bf[ni], stage + brbase[ni] +
                        ((uint32_t)((ks * 2 + bhi) * 16) ^ bxor[ni]));
#pragma unroll
            for (int mi = 0; mi < 4; mi++)
#pragma unroll
                for (int ni = 0; ni < 4; ni++)
                    mma_bf16(acc[mi][ni], af[mi], bf[ni]);
        }
    }

    const int qrow = lane >> 2;
    const int qcol = (lane & 3) * 2;
#pragma unroll
    for (int mi = 0; mi < 4; mi++) {
        int m_lo = bm + warp_m * 64 + mi * 16 + qrow;
        int m_hi = m_lo + 8;
#pragma unroll
        for (int ni = 0; ni < 4; ni++) {
            int n = bn + warp_n * 32 + ni * 8 + qcol;
            float2 bv = *(const float2*)(bias + n);
            float x0 = acc[mi][ni][0] + bv.x, y0 = acc[mi][ni][1] + bv.y;
            float x1 = acc[mi][ni][2] + bv.x, y1 = acc[mi][ni][3] + bv.y;
            if (OUT_MODE == 1) {
                x0 *= scale; y0 *= scale; x1 *= scale; y1 *= scale;
                __nv_bfloat16* out = (__nv_bfloat16*)outv;
                int hh = n >> 6, d0 = n & (HDIM - 1);
                int b0 = m_lo >> 11, t0 = m_lo & (TT - 1);
                int b1 = m_hi >> 11, t1 = m_hi & (TT - 1);
                size_t base0 = ((size_t)((b0*HH + hh)*TT + t0)) << 7;
                size_t base1 = ((size_t)((b1*HH + hh)*TT + t1)) << 7;
                __nv_bfloat16 hx0 = __float2bfloat16(x0), hy0 = __float2bfloat16(y0);
                __nv_bfloat16 hx1 = __float2bfloat16(x1), hy1 = __float2bfloat16(y1);
                *(uint32_t*)(out + base0 + d0)      = packh2(hx0, hy0);
                *(uint32_t*)(out + base0 + 64 + d0) = packbf2(x0 - __bfloat162float(hx0),
                                                              y0 - __bfloat162float(hy0));
                *(uint32_t*)(out + base1 + d0)      = packh2(hx1, hy1);
                *(uint32_t*)(out + base1 + 64 + d0) = packbf2(x1 - __bfloat162float(hx1),
                                                              y1 - __bfloat162float(hy1));
            } else {
                float* out = (float*)outv;
                float2 lo; lo.x = x0; lo.y = y0;
                float2 hi; hi.x = x1; hi.y = y1;
                *(float2*)(out + (size_t)m_lo * DD + n) = lo;
                *(float2*)(out + (size_t)m_hi * DD + n) = hi;
            }
        }
    }
}

// ---------------------------------------------------------------------------
// Flash attention (causal) via mma.sync bf16 with split precision.
// CTA: 128 q rows (8 warps x 16), 64 kv per iteration, double-buffered cp.async.
// S = qh*kh + ql*kh + qh*kl ; O += ph*Vh + pl*Vh + ph*Vl.
// Output written directly as split activations into g_xc [hi|lo|hi].
// ---------------------------------------------------------------------------
__device__ __forceinline__ void fl_load_kv(uint32_t stage, const __nv_bfloat16* Kb,
                                           const __nv_bfloat16* Vb, int k0, int tid)
{
#pragma unroll
    for (int i = 0; i < 4; i++) {
        int id = tid + i * 256;
        int row = id >> 4, ch = id & 15;
        uint32_t o = (ch < 8) ? SMEM_SWIZZLE_128B((uint32_t)(row*128 + ch*16))
                              : 8192u + SMEM_SWIZZLE_128B((uint32_t)(row*128 + (ch-8)*16));
        cp16(stage + o, Kb + ((size_t)(k0 + row) << 7) + ch * 8);
    }
#pragma unroll
    for (int i = 0; i < 4; i++) {
        int id = tid + i * 256;
        int row = id >> 4, ch = id & 15;
        uint32_t o = (ch < 8) ? SMEM_SWIZZLE_128B((uint32_t)(row*128 + ch*16))
                              : 8192u + SMEM_SWIZZLE_128B((uint32_t)(row*128 + (ch-8)*16));
        cp16(stage + 16384u + o, Vb + ((size_t)(k0 + row) << 7) + ch * 8);
    }
}

__global__ __launch_bounds__(256)
void flash_hmma_kernel(const __nv_bfloat16* __restrict__ Qg,
                       const __nv_bfloat16* __restrict__ Kg,
                       const __nv_bfloat16* __restrict__ Vg,
                       __nv_bfloat16* __restrict__ Xout)
{
    extern __shared__ char smem[];
    const uint32_t sb = smem_to_u32(smem);
    const int tid = threadIdx.x, wid = tid >> 5, lane = tid & 31;
    const int qt = blockIdx.x, bh = blockIdx.y;
    const int q0 = qt * 128;
    const int qbase = q0 + wid * 16;
    const int ntiles = 2 * qt + 2;

    const __nv_bfloat16* Qb = Qg + (((size_t)bh * TT + q0) << 7);
    const __nv_bfloat16* Kb = Kg + ((size_t)bh * TT << 7);
    const __nv_bfloat16* Vb = Vg + ((size_t)bh * TT << 7);

    // Q tile: 128 rows x 256B -> Qh/Ql planes
#pragma unroll
    for (int i = 0; i < 8; i++) {
        int id = tid + i * 256;
        int row = id >> 4, ch = id & 15;
        uint32_t o = (ch < 8) ? FL_QH + SMEM_SWIZZLE_128B((uint32_t)(row*128 + ch*16))
                              : FL_QL + SMEM_SWIZZLE_128B((uint32_t)(row*128 + (ch-8)*16));
        cp16(sb + o, Qb + ((size_t)row << 7) + ch * 8);
    }
    cp_commit();
    fl_load_kv(sb + FL_STG, Kb, Vb, 0, tid);
    cp_commit();

    // per-lane fragment addressing
    const int lq = lane & 15;
    const int bhi = (lq >> 3) & 1;
    const int ahi = (lane >> 4) & 1;
    const int arow = wid * 16 + (lane & 15);
    const uint32_t arb = (uint32_t)arow * 128;
    const uint32_t ax  = (uint32_t)(arow & 7) * 16;
    uint32_t brb[8], bx[8];
#pragma unroll
    for (int nt = 0; nt < 8; nt++) {
        int r = nt * 8 + (lq & 7);
        brb[nt] = (uint32_t)r * 128;
        bx[nt]  = (uint32_t)(r & 7) * 16;
    }
    uint32_t vrb[4], vx[4];
#pragma unroll
    for (int kc = 0; kc < 4; kc++) {
        int r = kc * 16 + lq;
        vrb[kc] = (uint32_t)r * 128;
        vx[kc]  = (uint32_t)(r & 7) * 16;
    }

    float oacc[8][4];
#pragma unroll
    for (int nt = 0; nt < 8; nt++)
#pragma unroll
        for (int e = 0; e < 4; e++) oacc[nt][e] = 0.f;
    float m0 = -1e30f, m1 = -1e30f, l0 = 0.f, l1 = 0.f;

    for (int j = 0; j < ntiles; j++) {
        const int k0 = j * 64;
        if (j + 1 < ntiles) {
            fl_load_kv(sb + FL_STG + ((j + 1) & 1) * 32768u, Kb, Vb, (j + 1) * 64, tid);
            cp_commit();
            asm volatile("cp.async.wait_group 1;" ::: "memory");
        } else {
            asm volatile("cp.async.wait_group 0;" ::: "memory");
        }
        __syncthreads();
        const uint32_t stage = sb + FL_STG + (j & 1) * 32768u;

        if (k0 <= qbase + 15) {
            float sacc[8][4];
#pragma unroll
            for (int nt = 0; nt < 8; nt++)
#pragma unroll
                for (int e = 0; e < 4; e++) sacc[nt][e] = 0.f;

            // S = qh*kh + ql*kh + qh*kl
#pragma unroll
            for (int pass = 0; pass < 3; pass++) {
                const uint32_t qpl = sb + ((pass == 1) ? FL_QL : FL_QH);
                const uint32_t kpl = stage + ((pass == 2) ? 8192u : 0u);
#pragma unroll
                for (int ks = 0; ks < 4; ks++) {
                    uint32_t Af[4];
                    ldsm_x4(Af, qpl + arb + (((uint32_t)((ks*2 + ahi)*16)) ^ ax));
#pragma unroll
                    for (int nt = 0; nt < 8; nt++) {
                        uint32_t Bf[2];
                        ldsm_x2(Bf, kpl + brb[nt] + (((uint32_t)((ks*2 + bhi)*16)) ^ bx[nt]));
                        mma_bf16(sacc[nt], Af, Bf);
                    }
                }
            }

            // causal mask (only near-diagonal tiles)
            const int qg0 = qbase + (lane >> 2);
            const int qg1 = qg0 + 8;
            if (k0 + 63 > qbase) {
#pragma unroll
                for (int nt = 0; nt < 8; nt++) {
                    int kgb = k0 + nt * 8 + (lane & 3) * 2;
                    if (kgb     > qg0) sacc[nt][0] = -1e30f;
                    if (kgb + 1 > qg0) sacc[nt][1] = -1e30f;
                    if (kgb     > qg1) sacc[nt][2] = -1e30f;
                    if (kgb + 1 > qg1) sacc[nt][3] = -1e30f;
                }
            }

            // online softmax
            float mx0 = -1e30f, mx1 = -1e30f;
#pragma unroll
            for (int nt = 0; nt < 8; nt++) {
                mx0 = fmaxf(mx0, fmaxf(sacc[nt][0], sacc[nt][1]));
                mx1 = fmaxf(mx1, fmaxf(sacc[nt][2], sacc[nt][3]));
            }
            mx0 = fmaxf(mx0, __shfl_xor_sync(0xffffffffu, mx0, 1));
            mx0 = fmaxf(mx0, __shfl_xor_sync(0xffffffffu, mx0, 2));
            mx1 = fmaxf(mx1, __shfl_xor_sync(0xffffffffu, mx1, 1));
            mx1 = fmaxf(mx1, __shfl_xor_sync(0xffffffffu, mx1, 2));
            const float nm0 = fmaxf(m0, mx0), nm1 = fmaxf(m1, mx1);
            const float sc0 = __expf(m0 - nm0), sc1 = __expf(m1 - nm1);
            float sum0 = 0.f, sum1 = 0.f;
#pragma unroll
            for (int nt = 0; nt < 8; nt++) {
                sacc[nt][0] = __expf(sacc[nt][0] - nm0); sum0 += sacc[nt][0];
                sacc[nt][1] = __expf(sacc[nt][1] - nm0); sum0 += sacc[nt][1];
                sacc[nt][2] = __expf(sacc[nt][2] - nm1); sum1 += sacc[nt][2];
                sacc[nt][3] = __expf(sacc[nt][3] - nm1); sum1 += sacc[nt][3];
            }
            sum0 += __shfl_xor_sync(0xffffffffu, sum0, 1);
            sum0 += __shfl_xor_sync(0xffffffffu, sum0, 2);
            sum1 += __shfl_xor_sync(0xffffffffu, sum1, 1);
            sum1 += __shfl_xor_sync(0xffffffffu, sum1, 2);
            l0 = l0 * sc0 + sum0;  l1 = l1 * sc1 + sum1;
            m0 = nm0;  m1 = nm1;
#pragma unroll
            for (int nt = 0; nt < 8; nt++) {
                oacc[nt][0] *= sc0; oacc[nt][1] *= sc0;
                oacc[nt][2] *= sc1; oacc[nt][3] *= sc1;
            }

            // P -> split bf16 fragments (C-layout == A-layout pairs)
            uint32_t phg[8], phg8[8], plg[8], plg8[8];
#pragma unroll
            for (int nt = 0; nt < 8; nt++) {
                float p0 = sacc[nt][0], p1 = sacc[nt][1];
                float p2 = sacc[nt][2], p3 = sacc[nt][3];
                __nv_bfloat16 h0 = __float2bfloat16(p0), h1 = __float2bfloat16(p1);
                __nv_bfloat16 h2 = __float2bfloat16(p2), h3 = __float2bfloat16(p3);
                phg[nt]  = packh2(h0, h1);
                phg8[nt] = packh2(h2, h3);
                plg[nt]  = packbf2(p0 - __bfloat162float(h0), p1 - __bfloat162float(h1));
                plg8[nt] = packbf2(p2 - __bfloat162float(h2), p3 - __bfloat162float(h3));
            }

            // O += ph*Vh + pl*Vh + ph*Vl
#pragma unroll
            for (int pass = 0; pass < 3; pass++) {
                const uint32_t vpl = stage + 16384u + ((pass == 2) ? 8192u : 0u);
#pragma unroll
                for (int kc = 0; kc < 4; kc++) {
                    uint32_t Af[4];
                    if (pass == 1) {
                        Af[0] = plg[2*kc];   Af[1] = plg8[2*kc];
                        Af[2] = plg[2*kc+1]; Af[3] = plg8[2*kc+1];
                    } else {
                        Af[0] = phg[2*kc];   Af[1] = phg8[2*kc];
                        Af[2] = phg[2*kc+1]; Af[3] = phg8[2*kc+1];
                    }
#pragma unroll
                    for (int nt = 0; nt < 8; nt++) {
                        uint32_t Bf[2];
                        ldsm_x2_trans(Bf, vpl + vrb[kc] + (((uint32_t)(nt*16)) ^ vx[kc]));
                        mma_bf16(oacc[nt], Af, Bf);
                    }
                }
            }
        }
        __syncthreads();
    }

    // epilogue: normalize, split to bf16, write g_xc [hi|lo|hi]
    const int b = bh >> 4, h = bh & 15;
    const int t0 = qbase + (lane >> 2);
    const int t1 = t0 + 8;
    const size_t r0 = (size_t)(b * TT + t0) * GK;
    const size_t r1 = (size_t)(b * TT + t1) * GK;
    const float i0 = 1.f / l0, i1 = 1.f / l1;
    const int cbase = h * 64 + (lane & 3) * 2;
#pragma unroll
    for (int nt = 0; nt < 8; nt++) {
        int c = cbase + nt * 8;
        float v0 = oacc[nt][0] * i0, v1 = oacc[nt][1] * i0;
        float w0 = oacc[nt][2] * i1, w1 = oacc[nt][3] * i1;
        __nv_bfloat16 a0 = __float2bfloat16(v0), a1 = __float2bfloat16(v1);
        __nv_bfloat16 b0 = __float2bfloat16(w0), b1 = __float2bfloat16(w1);
        uint32_t hp0 = packh2(a0, a1);
        uint32_t lp0 = packbf2(v0 - __bfloat162float(a0), v1 - __bfloat162float(a1));
        uint32_t hp1 = packh2(b0, b1);
        uint32_t lp1 = packbf2(w0 - __bfloat162float(b0), w1 - __bfloat162float(b1));
        *(uint32_t*)(Xout + r0 + c)        = hp0;
        *(uint32_t*)(Xout + r0 + 1024 + c) = lp0;
        *(uint32_t*)(Xout + r0 + 2048 + c) = hp0;
        *(uint32_t*)(Xout + r1 + c)        = hp1;
        *(uint32_t*)(Xout + r1 + 1024 + c) = lp1;
        *(uint32_t*)(Xout + r1 + 2048 + c) = hp1;
    }
}

// ---------------------------------------------------------------------------
extern "C" void kernel_launch(void* const* d_in, const int* in_sizes, int n_in,
                              void* d_out, int out_size)
{
    const float* q  = (const float*)d_in[0];
    const float* k  = (const float*)d_in[1];
    const float* v  = (const float*)d_in[2];
    const float* wq = (const float*)d_in[3];
    const float* bq = (const float*)d_in[4];
    const float* wk = (const float*)d_in[5];
    const float* bk = (const float*)d_in[6];
    const float* wv = (const float*)d_in[7];
    const float* bv = (const float*)d_in[8];
    const float* wo = (const float*)d_in[9];
    const float* bo = (const float*)d_in[10];
    float* out = (float*)d_out;

    __nv_bfloat16 *gqc, *gkc, *gvc, *gxc, *gwc;
    cudaGetSymbolAddress((void**)&gqc, g_qc);
    cudaGetSymbolAddress((void**)&gkc, g_kc);
    cudaGetSymbolAddress((void**)&gvc, g_vc);
    cudaGetSymbolAddress((void**)&gxc, g_xc);
    cudaGetSymbolAddress((void**)&gwc, g_wc);

    cudaFuncSetAttribute(hmma_gemm_kernel<0>,
                         cudaFuncAttributeMaxDynamicSharedMemorySize, GEMM_SMEM_SZ);
    cudaFuncSetAttribute(hmma_gemm_kernel<1>,
                         cudaFuncAttributeMaxDynamicSharedMemorySize, GEMM_SMEM_SZ);
    cudaFuncSetAttribute(flash_hmma_kernel,
                         cudaFuncAttributeMaxDynamicSharedMemorySize, FL_SMEM);

    dim3 gg(DD / 128, MM / 128);          // (8, 64)

    // Q projection (pre-scaled by 1/sqrt(hd) = 0.125)
    convert_split_kernel<0><<<MM, 256>>>(q, gxc, MM);
    convert_split_kernel<1><<<DD, 256>>>(wq, gwc, DD);
    hmma_gemm_kernel<1><<<gg, 256, GEMM_SMEM_SZ>>>(gxc, gwc, bq, gqc, 0.125f);
    // K projection
    convert_split_kernel<0><<<MM, 256>>>(k, gxc, MM);
    convert_split_kernel<1><<<DD, 256>>>(wk, gwc, DD);
    hmma_gemm_kernel<1><<<gg, 256, GEMM_SMEM_SZ>>>(gxc, gwc, bk, gkc, 1.0f);
    // V projection
    convert_split_kernel<0><<<MM, 256>>>(v, gxc, MM);
    convert_split_kernel<1><<<DD, 256>>>(wv, gwc, DD);
    hmma_gemm_kernel<1><<<gg, 256, GEMM_SMEM_SZ>>>(gxc, gwc, bv, gvc, 1.0f);

    // Attention (writes split activations directly into gxc)
    flash_hmma_kernel<<<dim3(TT / 128, BB * HH), 256, FL_SMEM>>>(gqc, gkc, gvc, gxc);

    // Output projection
    convert_split_kernel<1><<<DD, 256>>>(wo, gwc, DD);
    hmma_gemm_kernel<0><<<gg, 256, GEMM_SMEM_SZ>>>(gxc, gwc, bo, out, 1.0f);
}

// round 13
// speedup vs baseline: 3.2100x; 1.0872x over previous
#include <cuda_runtime.h>
#include <cuda_bf16.h>
#include <cstdint>
#include <cstddef>

// Problem constants
#define BB   4
#define TT   2048
#define DD   1024
#define HH   16
#define HDIM 64
#define MM   (BB*TT)   // 8192
#define GK   3072      // split-bf16 concatenated K ( [h|l|h] x [h|h|l] )
#define BKC  64        // bf16 K per GEMM pipeline stage
#define NCHUNK (GK/BKC) // 48
#define STAGES 3
#define STAGE_BYTES 32768
#define GEMM_SMEM_SZ (STAGES*STAGE_BYTES)   // 96KB

// Flash smem layout (dynamic, 96KB)
#define FL_QH   0u
#define FL_QL   16384u
#define FL_STG  32768u
#define FL_SMEM 98304

// Scratch (device globals; no allocation allowed)
__device__ __nv_bfloat16 g_qc[(size_t)BB*HH*TT*128];  // [b][h][t][hi(64)|lo(64)]
__device__ __nv_bfloat16 g_kc[(size_t)BB*HH*TT*128];
__device__ __nv_bfloat16 g_vc[(size_t)BB*HH*TT*128];
__device__ __nv_bfloat16 g_x0[(size_t)MM*GK];         // act buffers [hi|lo|hi]
__device__ __nv_bfloat16 g_x1[(size_t)MM*GK];
__device__ __nv_bfloat16 g_x2[(size_t)MM*GK];
__device__ __nv_bfloat16 g_w0[(size_t)DD*GK];         // weights [hi|hi|lo]
__device__ __nv_bfloat16 g_w1[(size_t)DD*GK];
__device__ __nv_bfloat16 g_w2[(size_t)DD*GK];
__device__ __nv_bfloat16 g_w3[(size_t)DD*GK];

// ---------------------------------------------------------------------------
// Portable PTX helpers
// ---------------------------------------------------------------------------
__device__ __forceinline__ uint32_t smem_to_u32(const void* p) {
    uint32_t a;
    asm("{ .reg .u64 t; cvta.to.shared.u64 t, %1; cvt.u32.u64 %0, t; }" : "=r"(a) : "l"(p));
    return a;
}
__device__ __forceinline__ void cp16(uint32_t saddr, const void* g) {
    asm volatile("cp.async.cg.shared.global [%0], [%1], 16;" :: "r"(saddr), "l"(g));
}
__device__ __forceinline__ void cp_commit() {
    asm volatile("cp.async.commit_group;" ::: "memory");
}
__device__ __forceinline__ void ldsm_x4(uint32_t* r, uint32_t addr) {
    asm volatile("ldmatrix.sync.aligned.m8n8.x4.shared.b16 {%0,%1,%2,%3}, [%4];"
        : "=r"(r[0]), "=r"(r[1]), "=r"(r[2]), "=r"(r[3]) : "r"(addr));
}
__device__ __forceinline__ void ldsm_x2(uint32_t* r, uint32_t addr) {
    asm volatile("ldmatrix.sync.aligned.m8n8.x2.shared.b16 {%0,%1}, [%2];"
        : "=r"(r[0]), "=r"(r[1]) : "r"(addr));
}
__device__ __forceinline__ void ldsm_x2_trans(uint32_t* r, uint32_t addr) {
    asm volatile("ldmatrix.sync.aligned.m8n8.x2.trans.shared.b16 {%0,%1}, [%2];"
        : "=r"(r[0]), "=r"(r[1]) : "r"(addr));
}
__device__ __forceinline__ void mma_bf16(float* c, const uint32_t* a, const uint32_t* b) {
    asm volatile("mma.sync.aligned.m16n8k16.row.col.f32.bf16.bf16.f32 "
        "{%0,%1,%2,%3}, {%4,%5,%6,%7}, {%8,%9}, {%0,%1,%2,%3};"
        : "+f"(c[0]), "+f"(c[1]), "+f"(c[2]), "+f"(c[3])
        : "r"(a[0]), "r"(a[1]), "r"(a[2]), "r"(a[3]), "r"(b[0]), "r"(b[1]));
}
__device__ __forceinline__ uint32_t packbf2(float lo, float hi) {
    uint32_t r;
    asm("cvt.rn.bf16x2.f32 %0, %1, %2;" : "=r"(r) : "f"(hi), "f"(lo));
    return r;
}
__device__ __forceinline__ uint32_t packh2(__nv_bfloat16 a, __nv_bfloat16 b) {
    __nv_bfloat162 t = __halves2bfloat162(a, b);
    return *reinterpret_cast<uint32_t*>(&t);
}
#define SMEM_SWIZZLE_128B(off) ((off) ^ (((off) >> 3) & 0x70))

// ---------------------------------------------------------------------------
// Split conversions. Act: [hi|lo|hi]; Weight: [hi|hi|lo].
// ---------------------------------------------------------------------------
template<int WMODE>
__device__ __forceinline__ void conv_row(const float* __restrict__ in,
                                         __nv_bfloat16* __restrict__ out,
                                         int row, int tid)
{
    int c = tid << 2;
    float4 x = *(const float4*)(in + (size_t)row * 1024 + c);
    __nv_bfloat16 h0 = __float2bfloat16(x.x);
    __nv_bfloat16 h1 = __float2bfloat16(x.y);
    __nv_bfloat16 h2 = __float2bfloat16(x.z);
    __nv_bfloat16 h3 = __float2bfloat16(x.w);
    __nv_bfloat16 l0 = __float2bfloat16(x.x - __bfloat162float(h0));
    __nv_bfloat16 l1 = __float2bfloat16(x.y - __bfloat162float(h1));
    __nv_bfloat16 l2 = __float2bfloat16(x.z - __bfloat162float(h2));
    __nv_bfloat16 l3 = __float2bfloat16(x.w - __bfloat162float(h3));
    __nv_bfloat162 hA = __halves2bfloat162(h0, h1), hB = __halves2bfloat162(h2, h3);
    __nv_bfloat162 lA = __halves2bfloat162(l0, l1), lB = __halves2bfloat162(l2, l3);
    size_t base = (size_t)row * GK + c;
    __nv_bfloat162* o0 = (__nv_bfloat162*)(out + base);
    __nv_bfloat162* o1 = (__nv_bfloat162*)(out + base + 1024);
    __nv_bfloat162* o2 = (__nv_bfloat162*)(out + base + 2048);
    o0[0] = hA; o0[1] = hB;
    if (WMODE) { o1[0] = hA; o1[1] = hB; o2[0] = lA; o2[1] = lB; }
    else       { o1[0] = lA; o1[1] = lB; o2[0] = hA; o2[1] = hB; }
}

__global__ void convert_act3_kernel(const float* __restrict__ q,
                                    const float* __restrict__ k,
                                    const float* __restrict__ v,
                                    __nv_bfloat16* __restrict__ o0,
                                    __nv_bfloat16* __restrict__ o1,
                                    __nv_bfloat16* __restrict__ o2)
{
    const float* in = (blockIdx.y == 0) ? q : (blockIdx.y == 1) ? k : v;
    __nv_bfloat16* out = (blockIdx.y == 0) ? o0 : (blockIdx.y == 1) ? o1 : o2;
    conv_row<0>(in, out, blockIdx.x, threadIdx.x);
}

__global__ void convert_w4_kernel(const float* __restrict__ w0,
                                  const float* __restrict__ w1,
                                  const float* __restrict__ w2,
                                  const float* __restrict__ w3,
                                  __nv_bfloat16* __restrict__ o0,
                                  __nv_bfloat16* __restrict__ o1,
                                  __nv_bfloat16* __restrict__ o2,
                                  __nv_bfloat16* __restrict__ o3)
{
    const float* in = (blockIdx.y == 0) ? w0 : (blockIdx.y == 1) ? w1
                    : (blockIdx.y == 2) ? w2 : w3;
    __nv_bfloat16* out = (blockIdx.y == 0) ? o0 : (blockIdx.y == 1) ? o1
                       : (blockIdx.y == 2) ? o2 : o3;
    conv_row<1>(in, out, blockIdx.x, threadIdx.x);
}

// ---------------------------------------------------------------------------
// HMMA GEMM core (128x128 CTA tile). OUT_MODE 0: fp32 [m][1024].
// OUT_MODE 1: split bf16 head layout [b][h][t][hi|lo], scaled.
// ---------------------------------------------------------------------------
template<int OUT_MODE>
__device__ __forceinline__ void gemm_body(const __nv_bfloat16* __restrict__ A,
                                          const __nv_bfloat16* __restrict__ B,
                                          const float* __restrict__ bias,
                                          void* __restrict__ outv, float scale,
                                          char* smem)
{
    const uint32_t sb = smem_to_u32(smem);
    const int tid  = threadIdx.x;
    const int wid  = tid >> 5, lane = tid & 31;
    const int warp_m = wid >> 2;
    const int warp_n = wid & 3;
    const int bm = blockIdx.y * 128, bn = blockIdx.x * 128;

    const __nv_bfloat16* Ag[4];
    const __nv_bfloat16* Bg[4];
    uint32_t sOffA[4], sOffB[4];
#pragma unroll
    for (int i = 0; i < 4; i++) {
        int id = tid + i * 256;
        int grow = id >> 3, gch = id & 7;
        Ag[i] = A + (size_t)(bm + grow) * GK + gch * 8;
        Bg[i] = B + (size_t)(bn + grow) * GK + gch * 8;
        sOffA[i] = SMEM_SWIZZLE_128B((uint32_t)(grow * 128 + gch * 16));
        sOffB[i] = sOffA[i] + 16384;
    }

#pragma unroll
    for (int s = 0; s < 2; s++) {
        uint32_t base = sb + s * STAGE_BYTES;
        int k0 = s * BKC;
#pragma unroll
        for (int i = 0; i < 4; i++) {
            cp16(base + sOffA[i], Ag[i] + k0);
            cp16(base + sOffB[i], Bg[i] + k0);
        }
        cp_commit();
    }

    uint32_t arbase[4], axor[4];
    const int ahi = (lane >> 4) & 1;
#pragma unroll
    for (int mi = 0; mi < 4; mi++) {
        int row = warp_m * 64 + mi * 16 + (lane & 15);
        arbase[mi] = (uint32_t)row * 128;
        axor[mi]   = (uint32_t)(row & 7) * 16;
    }
    uint32_t brbase[4], bxor[4];
    const int lq = lane & 15;
    const int bhi = (lq >> 3) & 1;
#pragma unroll
    for (int ni = 0; ni < 4; ni++) {
        int row = warp_n * 32 + ni * 8 + (lq & 7);
        brbase[ni] = (uint32_t)row * 128 + 16384;
        bxor[ni]   = (uint32_t)(row & 7) * 16;
    }

    float acc[4][4][4];
#pragma unroll
    for (int mi = 0; mi < 4; mi++)
#pragma unroll
        for (int ni = 0; ni < 4; ni++)
#pragma unroll
            for (int e = 0; e < 4; e++) acc[mi][ni][e] = 0.f;

    for (int c = 0; c < NCHUNK; c++) {
        if (c < NCHUNK - 1) asm volatile("cp.async.wait_group 1;" ::: "memory");
        else                asm volatile("cp.async.wait_group 0;" ::: "memory");
        __syncthreads();

        if (c + 2 < NCHUNK) {
            uint32_t base = sb + ((c + 2) % STAGES) * STAGE_BYTES;
            int k0 = (c + 2) * BKC;
#pragma unroll
            for (int i = 0; i < 4; i++) {
                cp16(base + sOffA[i], Ag[i] + k0);
                cp16(base + sOffB[i], Bg[i] + k0);
            }
            cp_commit();
        }

        const uint32_t stage = sb + (c % STAGES) * STAGE_BYTES;
#pragma unroll
        for (int ks = 0; ks < 4; ks++) {
            uint32_t af[4][4], bf[4][2];
#pragma unroll
            for (int mi = 0; mi < 4; mi++)
                ldsm_x4(af[mi], stage + arbase[mi] +
                        ((uint32_t)((ks * 2 + ahi) * 16) ^ axor[mi]));
#pragma unroll
            for (int ni = 0; ni < 4; ni++)
                ldsm_x2(bf[ni], stage + brbase[ni] +
                        ((uint32_t)((ks * 2 + bhi) * 16) ^ bxor[ni]));
#pragma unroll
            for (int mi = 0; mi < 4; mi++)
#pragma unroll
                for (int ni = 0; ni < 4; ni++)
                    mma_bf16(acc[mi][ni], af[mi], bf[ni]);
        }
    }

    const int qrow = lane >> 2;
    const int qcol = (lane & 3) * 2;
#pragma unroll
    for (int mi = 0; mi < 4; mi++) {
        int m_lo = bm + warp_m * 64 + mi * 16 + qrow;
        int m_hi = m_lo + 8;
#pragma unroll
        for (int ni = 0; ni < 4; ni++) {
            int n = bn + warp_n * 32 + ni * 8 + qcol;
            float2 bv = *(const float2*)(bias + n);
            float x0 = acc[mi][ni][0] + bv.x, y0 = acc[mi][ni][1] + bv.y;
            float x1 = acc[mi][ni][2] + bv.x, y1 = acc[mi][ni][3] + bv.y;
            if (OUT_MODE == 1) {
                x0 *= scale; y0 *= scale; x1 *= scale; y1 *= scale;
                __nv_bfloat16* out = (__nv_bfloat16*)outv;
                int hh = n >> 6, d0 = n & (HDIM - 1);
                int b0 = m_lo >> 11, t0 = m_lo & (TT - 1);
                int b1 = m_hi >> 11, t1 = m_hi & (TT - 1);
                size_t base0 = ((size_t)((b0*HH + hh)*TT + t0)) << 7;
                size_t base1 = ((size_t)((b1*HH + hh)*TT + t1)) << 7;
                __nv_bfloat16 hx0 = __float2bfloat16(x0), hy0 = __float2bfloat16(y0);
                __nv_bfloat16 hx1 = __float2bfloat16(x1), hy1 = __float2bfloat16(y1);
                *(uint32_t*)(out + base0 + d0)      = packh2(hx0, hy0);
                *(uint32_t*)(out + base0 + 64 + d0) = packbf2(x0 - __bfloat162float(hx0),
                                                              y0 - __bfloat162float(hy0));
                *(uint32_t*)(out + base1 + d0)      = packh2(hx1, hy1);
                *(uint32_t*)(out + base1 + 64 + d0) = packbf2(x1 - __bfloat162float(hx1),
                                                              y1 - __bfloat162float(hy1));
            } else {
                float* out = (float*)outv;
                float2 lo; lo.x = x0; lo.y = y0;
                float2 hi; hi.x = x1; hi.y = y1;
                *(float2*)(out + (size_t)m_lo * DD + n) = lo;
                *(float2*)(out + (size_t)m_hi * DD + n) = hi;
            }
        }
    }
}

// Batched QKV GEMM: grid.z picks {A,B,bias,out,scale}
__global__ __launch_bounds__(256)
void hmma_gemm3_kernel(const __nv_bfloat16* A0, const __nv_bfloat16* A1,
                       const __nv_bfloat16* A2,
                       const __nv_bfloat16* B0, const __nv_bfloat16* B1,
                       const __nv_bfloat16* B2,
                       const float* b0, const float* b1, const float* b2,
                       __nv_bfloat16* o0, __nv_bfloat16* o1, __nv_bfloat16* o2,
                       float s0)
{
    extern __shared__ char smem[];
    const int z = blockIdx.z;
    const __nv_bfloat16* A = (z == 0) ? A0 : (z == 1) ? A1 : A2;
    const __nv_bfloat16* B = (z == 0) ? B0 : (z == 1) ? B1 : B2;
    const float* bias      = (z == 0) ? b0 : (z == 1) ? b1 : b2;
    __nv_bfloat16* out     = (z == 0) ? o0 : (z == 1) ? o1 : o2;
    float scale            = (z == 0) ? s0 : 1.0f;
    gemm_body<1>(A, B, bias, out, scale, smem);
}

__global__ __launch_bounds__(256)
void hmma_gemm_out_kernel(const __nv_bfloat16* __restrict__ A,
                          const __nv_bfloat16* __restrict__ B,
                          const float* __restrict__ bias,
                          float* __restrict__ out)
{
    extern __shared__ char smem[];
    gemm_body<0>(A, B, bias, out, 1.0f, smem);
}

// ---------------------------------------------------------------------------
// Flash attention (causal), mma.sync bf16 split precision.
// Fragment-reuse: per ks load {Qh,Ql} x4 + per nt {Kh,Kl} x2, 3 mma combos.
// ---------------------------------------------------------------------------
__device__ __forceinline__ void fl_load_kv(uint32_t stage, const __nv_bfloat16* Kb,
                                           const __nv_bfloat16* Vb, int k0, int tid)
{
#pragma unroll
    for (int i = 0; i < 4; i++) {
        int id = tid + i * 256;
        int row = id >> 4, ch = id & 15;
        uint32_t o = (ch < 8) ? SMEM_SWIZZLE_128B((uint32_t)(row*128 + ch*16))
                              : 8192u + SMEM_SWIZZLE_128B((uint32_t)(row*128 + (ch-8)*16));
        cp16(stage + o, Kb + ((size_t)(k0 + row) << 7) + ch * 8);
    }
#pragma unroll
    for (int i = 0; i < 4; i++) {
        int id = tid + i * 256;
        int row = id >> 4, ch = id & 15;
        uint32_t o = (ch < 8) ? SMEM_SWIZZLE_128B((uint32_t)(row*128 + ch*16))
                              : 8192u + SMEM_SWIZZLE_128B((uint32_t)(row*128 + (ch-8)*16));
        cp16(stage + 16384u + o, Vb + ((size_t)(k0 + row) << 7) + ch * 8);
    }
}

__global__ __launch_bounds__(256)
void flash_hmma_kernel(const __nv_bfloat16* __restrict__ Qg,
                       const __nv_bfloat16* __restrict__ Kg,
                       const __nv_bfloat16* __restrict__ Vg,
                       __nv_bfloat16* __restrict__ Xout)
{
    extern __shared__ char smem[];
    const uint32_t sb = smem_to_u32(smem);
    const int tid = threadIdx.x, wid = tid >> 5, lane = tid & 31;
    const int qt = blockIdx.x, bh = blockIdx.y;
    const int q0 = qt * 128;
    const int qbase = q0 + wid * 16;
    const int ntiles = 2 * qt + 2;

    const __nv_bfloat16* Qb = Qg + (((size_t)bh * TT + q0) << 7);
    const __nv_bfloat16* Kb = Kg + ((size_t)bh * TT << 7);
    const __nv_bfloat16* Vb = Vg + ((size_t)bh * TT << 7);

#pragma unroll
    for (int i = 0; i < 8; i++) {
        int id = tid + i * 256;
        int row = id >> 4, ch = id & 15;
        uint32_t o = (ch < 8) ? FL_QH + SMEM_SWIZZLE_128B((uint32_t)(row*128 + ch*16))
                              : FL_QL + SMEM_SWIZZLE_128B((uint32_t)(row*128 + (ch-8)*16));
        cp16(sb + o, Qb + ((size_t)row << 7) + ch * 8);
    }
    cp_commit();
    fl_load_kv(sb + FL_STG, Kb, Vb, 0, tid);
    cp_commit();

    const int lq = lane & 15;
    const int bhi = (lq >> 3) & 1;
    const int ahi = (lane >> 4) & 1;
    const int arow = wid * 16 + (lane & 15);
    const uint32_t arb = (uint32_t)arow * 128;
    const uint32_t ax  = (uint32_t)(arow & 7) * 16;
    uint32_t brb[8], bx[8];
#pragma unroll
    for (int nt = 0; nt < 8; nt++) {
        int r = nt * 8 + (lq & 7);
        brb[nt] = (uint32_t)r * 128;
        bx[nt]  = (uint32_t)(r & 7) * 16;
    }
    uint32_t vrb[4], vx[4];
#pragma unroll
    for (int kc = 0; kc < 4; kc++) {
        int r = kc * 16 + lq;
        vrb[kc] = (uint32_t)r * 128;
        vx[kc]  = (uint32_t)(r & 7) * 16;
    }

    float oacc[8][4];
#pragma unroll
    for (int nt = 0; nt < 8; nt++)
#pragma unroll
        for (int e = 0; e < 4; e++) oacc[nt][e] = 0.f;
    float m0 = -1e30f, m1 = -1e30f, l0 = 0.f, l1 = 0.f;

    for (int j = 0; j < ntiles; j++) {
        const int k0 = j * 64;
        if (j + 1 < ntiles) {
            fl_load_kv(sb + FL_STG + ((j + 1) & 1) * 32768u, Kb, Vb, (j + 1) * 64, tid);
            cp_commit();
            asm volatile("cp.async.wait_group 1;" ::: "memory");
        } else {
            asm volatile("cp.async.wait_group 0;" ::: "memory");
        }
        __syncthreads();
        const uint32_t stage = sb + FL_STG + (j & 1) * 32768u;

        if (k0 <= qbase + 15) {
            float sacc[8][4];
#pragma unroll
            for (int nt = 0; nt < 8; nt++)
#pragma unroll
                for (int e = 0; e < 4; e++) sacc[nt][e] = 0.f;

            // S = qh*kh + ql*kh + qh*kl  (shared fragment loads)
#pragma unroll
            for (int ks = 0; ks < 4; ks++) {
                const uint32_t koff = (((uint32_t)((ks*2 + ahi)*16)) ^ ax);
                uint32_t Ah[4], Al[4];
                ldsm_x4(Ah, sb + FL_QH + arb + koff);
                ldsm_x4(Al, sb + FL_QL + arb + koff);
#pragma unroll
                for (int nt = 0; nt < 8; nt++) {
                    const uint32_t boff = brb[nt] + (((uint32_t)((ks*2 + bhi)*16)) ^ bx[nt]);
                    uint32_t Bh[2], Bl[2];
                    ldsm_x2(Bh, stage + boff);
                    ldsm_x2(Bl, stage + 8192u + boff);
                    mma_bf16(sacc[nt], Ah, Bh);
                    mma_bf16(sacc[nt], Al, Bh);
                    mma_bf16(sacc[nt], Ah, Bl);
                }
            }

            // causal mask
            const int qg0 = qbase + (lane >> 2);
            const int qg1 = qg0 + 8;
            if (k0 + 63 > qbase) {
#pragma unroll
                for (int nt = 0; nt < 8; nt++) {
                    int kgb = k0 + nt * 8 + (lane & 3) * 2;
                    if (kgb     > qg0) sacc[nt][0] = -1e30f;
                    if (kgb + 1 > qg0) sacc[nt][1] = -1e30f;
                    if (kgb     > qg1) sacc[nt][2] = -1e30f;
                    if (kgb + 1 > qg1) sacc[nt][3] = -1e30f;
                }
            }

            // online softmax
            float mx0 = -1e30f, mx1 = -1e30f;
#pragma unroll
            for (int nt = 0; nt < 8; nt++) {
                mx0 = fmaxf(mx0, fmaxf(sacc[nt][0], sacc[nt][1]));
                mx1 = fmaxf(mx1, fmaxf(sacc[nt][2], sacc[nt][3]));
            }
            mx0 = fmaxf(mx0, __shfl_xor_sync(0xffffffffu, mx0, 1));
            mx0 = fmaxf(mx0, __shfl_xor_sync(0xffffffffu, mx0, 2));
            mx1 = fmaxf(mx1, __shfl_xor_sync(0xffffffffu, mx1, 1));
            mx1 = fmaxf(mx1, __shfl_xor_sync(0xffffffffu, mx1, 2));
            const float nm0 = fmaxf(m0, mx0), nm1 = fmaxf(m1, mx1);
            const float sc0 = __expf(m0 - nm0), sc1 = __expf(m1 - nm1);
            float sum0 = 0.f, sum1 = 0.f;
#pragma unroll
            for (int nt = 0; nt < 8; nt++) {
                sacc[nt][0] = __expf(sacc[nt][0] - nm0); sum0 += sacc[nt][0];
                sacc[nt][1] = __expf(sacc[nt][1] - nm0); sum0 += sacc[nt][1];
                sacc[nt][2] = __expf(sacc[nt][2] - nm1); sum1 += sacc[nt][2];
                sacc[nt][3] = __expf(sacc[nt][3] - nm1); sum1 += sacc[nt][3];
            }
            sum0 += __shfl_xor_sync(0xffffffffu, sum0, 1);
            sum0 += __shfl_xor_sync(0xffffffffu, sum0, 2);
            sum1 += __shfl_xor_sync(0xffffffffu, sum1, 1);
            sum1 += __shfl_xor_sync(0xffffffffu, sum1, 2);
            l0 = l0 * sc0 + sum0;  l1 = l1 * sc1 + sum1;
            m0 = nm0;  m1 = nm1;
#pragma unroll
            for (int nt = 0; nt < 8; nt++) {
                oacc[nt][0] *= sc0; oacc[nt][1] *= sc0;
                oacc[nt][2] *= sc1; oacc[nt][3] *= sc1;
            }

            // P -> split bf16 fragments
            uint32_t phg[8], phg8[8], plg[8], plg8[8];
#pragma unroll
            for (int nt = 0; nt < 8; nt++) {
                float p0 = sacc[nt][0], p1 = sacc[nt][1];
                float p2 = sacc[nt][2], p3 = sacc[nt][3];
                __nv_bfloat16 h0 = __float2bfloat16(p0), h1 = __float2bfloat16(p1);
                __nv_bfloat16 h2 = __float2bfloat16(p2), h3 = __float2bfloat16(p3);
                phg[nt]  = packh2(h0, h1);
                phg8[nt] = packh2(h2, h3);
                plg[nt]  = packbf2(p0 - __bfloat162float(h0), p1 - __bfloat162float(h1));
                plg8[nt] = packbf2(p2 - __bfloat162float(h2), p3 - __bfloat162float(h3));
            }

            // O += ph*Vh + pl*Vh + ph*Vl  (shared V fragment loads)
#pragma unroll
            for (int kc = 0; kc < 4; kc++) {
                uint32_t Afh[4], Afl[4];
                Afh[0] = phg[2*kc];   Afh[1] = phg8[2*kc];
                Afh[2] = phg[2*kc+1]; Afh[3] = phg8[2*kc+1];
                Afl[0] = plg[2*kc];   Afl[1] = plg8[2*kc];
                Afl[2] = plg[2*kc+1]; Afl[3] = plg8[2*kc+1];
#pragma unroll
                for (int nt = 0; nt < 8; nt++) {
                    const uint32_t voff = vrb[kc] + (((uint32_t)(nt*16)) ^ vx[kc]);
                    uint32_t Vh[2], Vl[2];
                    ldsm_x2_trans(Vh, stage + 16384u + voff);
                    ldsm_x2_trans(Vl, stage + 24576u + voff);
                    mma_bf16(oacc[nt], Afh, Vh);
                    mma_bf16(oacc[nt], Afl, Vh);
                    mma_bf16(oacc[nt], Afh, Vl);
                }
            }
        }
        __syncthreads();
    }

    // epilogue: normalize, split, write [hi|lo|hi] activations
    const int b = bh >> 4, h = bh & 15;
    const int t0 = qbase + (lane >> 2);
    const int t1 = t0 + 8;
    const size_t r0 = (size_t)(b * TT + t0) * GK;
    const size_t r1 = (size_t)(b * TT + t1) * GK;
    const float i0 = 1.f / l0, i1 = 1.f / l1;
    const int cbase = h * 64 + (lane & 3) * 2;
#pragma unroll
    for (int nt = 0; nt < 8; nt++) {
        int c = cbase + nt * 8;
        float v0 = oacc[nt][0] * i0, v1 = oacc[nt][1] * i0;
        float w0 = oacc[nt][2] * i1, w1 = oacc[nt][3] * i1;
        __nv_bfloat16 a0 = __float2bfloat16(v0), a1 = __float2bfloat16(v1);
        __nv_bfloat16 b0 = __float2bfloat16(w0), b1 = __float2bfloat16(w1);
        uint32_t hp0 = packh2(a0, a1);
        uint32_t lp0 = packbf2(v0 - __bfloat162float(a0), v1 - __bfloat162float(a1));
        uint32_t hp1 = packh2(b0, b1);
        uint32_t lp1 = packbf2(w0 - __bfloat162float(b0), w1 - __bfloat162float(b1));
        *(uint32_t*)(Xout + r0 + c)        = hp0;
        *(uint32_t*)(Xout + r0 + 1024 + c) = lp0;
        *(uint32_t*)(Xout + r0 + 2048 + c) = hp0;
        *(uint32_t*)(Xout + r1 + c)        = hp1;
        *(uint32_t*)(Xout + r1 + 1024 + c) = lp1;
        *(uint32_t*)(Xout + r1 + 2048 + c) = hp1;
    }
}

// ---------------------------------------------------------------------------
extern "C" void kernel_launch(void* const* d_in, const int* in_sizes, int n_in,
                              void* d_out, int out_size)
{
    const float* q  = (const float*)d_in[0];
    const float* k  = (const float*)d_in[1];
    const float* v  = (const float*)d_in[2];
    const float* wq = (const float*)d_in[3];
    const float* bq = (const float*)d_in[4];
    const float* wk = (const float*)d_in[5];
    const float* bk = (const float*)d_in[6];
    const float* wv = (const float*)d_in[7];
    const float* bv = (const float*)d_in[8];
    const float* wo = (const float*)d_in[9];
    const float* bo = (const float*)d_in[10];
    float* out = (float*)d_out;

    __nv_bfloat16 *gqc, *gkc, *gvc, *gx0, *gx1, *gx2, *gw0, *gw1, *gw2, *gw3;
    cudaGetSymbolAddress((void**)&gqc, g_qc);
    cudaGetSymbolAddress((void**)&gkc, g_kc);
    cudaGetSymbolAddress((void**)&gvc, g_vc);
    cudaGetSymbolAddress((void**)&gx0, g_x0);
    cudaGetSymbolAddress((void**)&gx1, g_x1);
    cudaGetSymbolAddress((void**)&gx2, g_x2);
    cudaGetSymbolAddress((void**)&gw0, g_w0);
    cudaGetSymbolAddress((void**)&gw1, g_w1);
    cudaGetSymbolAddress((void**)&gw2, g_w2);
    cudaGetSymbolAddress((void**)&gw3, g_w3);

    cudaFuncSetAttribute(hmma_gemm3_kernel,
                         cudaFuncAttributeMaxDynamicSharedMemorySize, GEMM_SMEM_SZ);
    cudaFuncSetAttribute(hmma_gemm_out_kernel,
                         cudaFuncAttributeMaxDynamicSharedMemorySize, GEMM_SMEM_SZ);
    cudaFuncSetAttribute(flash_hmma_kernel,
                         cudaFuncAttributeMaxDynamicSharedMemorySize, FL_SMEM);

    // Converts: activations (q,k,v) and all 4 weights
    convert_act3_kernel<<<dim3(MM, 3), 256>>>(q, k, v, gx0, gx1, gx2);
    convert_w4_kernel<<<dim3(DD, 4), 256>>>(wq, wk, wv, wo, gw0, gw1, gw2, gw3);

    // Batched QKV projections (Q pre-scaled by 0.125)
    hmma_gemm3_kernel<<<dim3(DD/128, MM/128, 3), 256, GEMM_SMEM_SZ>>>(
        gx0, gx1, gx2, gw0, gw1, gw2, bq, bk, bv, gqc, gkc, gvc, 0.125f);

    // Attention (writes split activations into gx0)
    flash_hmma_kernel<<<dim3(TT/128, BB*HH), 256, FL_SMEM>>>(gqc, gkc, gvc, gx0);

    // Output projection
    hmma_gemm_out_kernel<<<dim3(DD/128, MM/128), 256, GEMM_SMEM_SZ>>>(gx0, gw3, bo, out);
}

// round 14
// speedup vs baseline: 3.3556x; 1.0453x over previous
#include <cuda_runtime.h>
#include <cuda_bf16.h>
#include <cstdint>
#include <cstddef>

// Problem constants
#define BB   4
#define TT   2048
#define DD   1024
#define HH   16
#define HDIM 64
#define MM   (BB*TT)   // 8192
#define GK   3072      // split-bf16 concatenated K ( [h|l|h] x [h|h|l] )
#define BKC  64        // bf16 K per GEMM pipeline stage
#define NCHUNK (GK/BKC) // 48
#define STAGES 3
#define STAGE_BYTES 32768
#define GEMM_SMEM_SZ (STAGES*STAGE_BYTES)   // 96KB

// Flash smem layout (dynamic, 96KB)
#define FL_QH   0u
#define FL_QL   16384u
#define FL_STG  32768u
#define FL_SMEM 98304

// Q projection scale: (1/sqrt(64)) * log2(e)  -> scores in log2 domain
#define QSCALE 0.1803368801111204f

// Scratch (device globals; no allocation allowed)
__device__ __nv_bfloat16 g_qc[(size_t)BB*HH*TT*128];  // [b][h][t][hi(64)|lo(64)]
__device__ __nv_bfloat16 g_kc[(size_t)BB*HH*TT*128];
__device__ __nv_bfloat16 g_vc[(size_t)BB*HH*TT*128];
__device__ __nv_bfloat16 g_x0[(size_t)MM*GK];         // act buffers [hi|lo|hi]
__device__ __nv_bfloat16 g_x1[(size_t)MM*GK];
__device__ __nv_bfloat16 g_x2[(size_t)MM*GK];
__device__ __nv_bfloat16 g_w0[(size_t)DD*GK];         // weights [hi|hi|lo]
__device__ __nv_bfloat16 g_w1[(size_t)DD*GK];
__device__ __nv_bfloat16 g_w2[(size_t)DD*GK];
__device__ __nv_bfloat16 g_w3[(size_t)DD*GK];

// ---------------------------------------------------------------------------
// Portable PTX helpers
// ---------------------------------------------------------------------------
__device__ __forceinline__ uint32_t smem_to_u32(const void* p) {
    uint32_t a;
    asm("{ .reg .u64 t; cvta.to.shared.u64 t, %1; cvt.u32.u64 %0, t; }" : "=r"(a) : "l"(p));
    return a;
}
__device__ __forceinline__ void cp16(uint32_t saddr, const void* g) {
    asm volatile("cp.async.cg.shared.global [%0], [%1], 16;" :: "r"(saddr), "l"(g));
}
__device__ __forceinline__ void cp_commit() {
    asm volatile("cp.async.commit_group;" ::: "memory");
}
__device__ __forceinline__ void ldsm_x4(uint32_t* r, uint32_t addr) {
    asm volatile("ldmatrix.sync.aligned.m8n8.x4.shared.b16 {%0,%1,%2,%3}, [%4];"
        : "=r"(r[0]), "=r"(r[1]), "=r"(r[2]), "=r"(r[3]) : "r"(addr));
}
__device__ __forceinline__ void ldsm_x4_trans(uint32_t* r, uint32_t addr) {
    asm volatile("ldmatrix.sync.aligned.m8n8.x4.trans.shared.b16 {%0,%1,%2,%3}, [%4];"
        : "=r"(r[0]), "=r"(r[1]), "=r"(r[2]), "=r"(r[3]) : "r"(addr));
}
__device__ __forceinline__ void mma_bf16(float* c, const uint32_t* a, const uint32_t* b) {
    asm volatile("mma.sync.aligned.m16n8k16.row.col.f32.bf16.bf16.f32 "
        "{%0,%1,%2,%3}, {%4,%5,%6,%7}, {%8,%9}, {%0,%1,%2,%3};"
        : "+f"(c[0]), "+f"(c[1]), "+f"(c[2]), "+f"(c[3])
        : "r"(a[0]), "r"(a[1]), "r"(a[2]), "r"(a[3]), "r"(b[0]), "r"(b[1]));
}
__device__ __forceinline__ uint32_t packbf2(float lo, float hi) {
    uint32_t r;
    asm("cvt.rn.bf16x2.f32 %0, %1, %2;" : "=r"(r) : "f"(hi), "f"(lo));
    return r;
}
__device__ __forceinline__ uint32_t packh2(__nv_bfloat16 a, __nv_bfloat16 b) {
    __nv_bfloat162 t = __halves2bfloat162(a, b);
    return *reinterpret_cast<uint32_t*>(&t);
}
#define SMEM_SWIZZLE_128B(off) ((off) ^ (((off) >> 3) & 0x70))

// ---------------------------------------------------------------------------
// Split conversions. Act: [hi|lo|hi]; Weight: [hi|hi|lo].
// ---------------------------------------------------------------------------
template<int WMODE>
__device__ __forceinline__ void conv_row(const float* __restrict__ in,
                                         __nv_bfloat16* __restrict__ out,
                                         int row, int tid)
{
    int c = tid << 2;
    float4 x = *(const float4*)(in + (size_t)row * 1024 + c);
    __nv_bfloat16 h0 = __float2bfloat16(x.x);
    __nv_bfloat16 h1 = __float2bfloat16(x.y);
    __nv_bfloat16 h2 = __float2bfloat16(x.z);
    __nv_bfloat16 h3 = __float2bfloat16(x.w);
    __nv_bfloat16 l0 = __float2bfloat16(x.x - __bfloat162float(h0));
    __nv_bfloat16 l1 = __float2bfloat16(x.y - __bfloat162float(h1));
    __nv_bfloat16 l2 = __float2bfloat16(x.z - __bfloat162float(h2));
    __nv_bfloat16 l3 = __float2bfloat16(x.w - __bfloat162float(h3));
    __nv_bfloat162 hA = __halves2bfloat162(h0, h1), hB = __halves2bfloat162(h2, h3);
    __nv_bfloat162 lA = __halves2bfloat162(l0, l1), lB = __halves2bfloat162(l2, l3);
    size_t base = (size_t)row * GK + c;
    __nv_bfloat162* o0 = (__nv_bfloat162*)(out + base);
    __nv_bfloat162* o1 = (__nv_bfloat162*)(out + base + 1024);
    __nv_bfloat162* o2 = (__nv_bfloat162*)(out + base + 2048);
    o0[0] = hA; o0[1] = hB;
    if (WMODE) { o1[0] = hA; o1[1] = hB; o2[0] = lA; o2[1] = lB; }
    else       { o1[0] = lA; o1[1] = lB; o2[0] = hA; o2[1] = hB; }
}

__global__ void convert_act3_kernel(const float* __restrict__ q,
                                    const float* __restrict__ k,
                                    const float* __restrict__ v,
                                    __nv_bfloat16* __restrict__ o0,
                                    __nv_bfloat16* __restrict__ o1,
                                    __nv_bfloat16* __restrict__ o2)
{
    const float* in = (blockIdx.y == 0) ? q : (blockIdx.y == 1) ? k : v;
    __nv_bfloat16* out = (blockIdx.y == 0) ? o0 : (blockIdx.y == 1) ? o1 : o2;
    conv_row<0>(in, out, blockIdx.x, threadIdx.x);
}

__global__ void convert_w4_kernel(const float* __restrict__ w0,
                                  const float* __restrict__ w1,
                                  const float* __restrict__ w2,
                                  const float* __restrict__ w3,
                                  __nv_bfloat16* __restrict__ o0,
                                  __nv_bfloat16* __restrict__ o1,
                                  __nv_bfloat16* __restrict__ o2,
                                  __nv_bfloat16* __restrict__ o3)
{
    const float* in = (blockIdx.y == 0) ? w0 : (blockIdx.y == 1) ? w1
                    : (blockIdx.y == 2) ? w2 : w3;
    __nv_bfloat16* out = (blockIdx.y == 0) ? o0 : (blockIdx.y == 1) ? o1
                       : (blockIdx.y == 2) ? o2 : o3;
    conv_row<1>(in, out, blockIdx.x, threadIdx.x);
}

// ---------------------------------------------------------------------------
// HMMA GEMM core (128x128 CTA tile). B loads paired via ldmatrix.x4.
// OUT_MODE 0: fp32 [m][1024].  OUT_MODE 1: split bf16 head layout, scaled.
// ---------------------------------------------------------------------------
template<int OUT_MODE>
__device__ __forceinline__ void gemm_body(const __nv_bfloat16* __restrict__ A,
                                          const __nv_bfloat16* __restrict__ B,
                                          const float* __restrict__ bias,
                                          void* __restrict__ outv, float scale,
                                          char* smem)
{
    const uint32_t sb = smem_to_u32(smem);
    const int tid  = threadIdx.x;
    const int wid  = tid >> 5, lane = tid & 31;
    const int warp_m = wid >> 2;
    const int warp_n = wid & 3;
    const int bm = blockIdx.y * 128, bn = blockIdx.x * 128;

    const __nv_bfloat16* Ag[4];
    const __nv_bfloat16* Bg[4];
    uint32_t sOffA[4], sOffB[4];
#pragma unroll
    for (int i = 0; i < 4; i++) {
        int id = tid + i * 256;
        int grow = id >> 3, gch = id & 7;
        Ag[i] = A + (size_t)(bm + grow) * GK + gch * 8;
        Bg[i] = B + (size_t)(bn + grow) * GK + gch * 8;
        sOffA[i] = SMEM_SWIZZLE_128B((uint32_t)(grow * 128 + gch * 16));
        sOffB[i] = sOffA[i] + 16384;
    }

#pragma unroll
    for (int s = 0; s < 2; s++) {
        uint32_t base = sb + s * STAGE_BYTES;
        int k0 = s * BKC;
#pragma unroll
        for (int i = 0; i < 4; i++) {
            cp16(base + sOffA[i], Ag[i] + k0);
            cp16(base + sOffB[i], Bg[i] + k0);
        }
        cp_commit();
    }

    uint32_t arbase[4], axor[4];
    const int ahi = (lane >> 4) & 1;
#pragma unroll
    for (int mi = 0; mi < 4; mi++) {
        int row = warp_m * 64 + mi * 16 + (lane & 15);
        arbase[mi] = (uint32_t)row * 128;
        axor[mi]   = (uint32_t)(row & 7) * 16;
    }
    // Paired B addressing: x4 loads two n8 tiles (lanes 16-31 -> second tile)
    const int bsel = (lane >> 3) & 1;                      // k-half select
    const int bRowP = warp_n * 32 + (((lane >> 4) & 1) << 3) + (lane & 7);
    uint32_t bpbase[2];
#pragma unroll
    for (int p = 0; p < 2; p++)
        bpbase[p] = (uint32_t)(bRowP + p * 16) * 128 + 16384;
    const uint32_t bpxor = (uint32_t)(lane & 7) * 16;

    float acc[4][4][4];
#pragma unroll
    for (int mi = 0; mi < 4; mi++)
#pragma unroll
        for (int ni = 0; ni < 4; ni++)
#pragma unroll
            for (int e = 0; e < 4; e++) acc[mi][ni][e] = 0.f;

    for (int c = 0; c < NCHUNK; c++) {
        if (c < NCHUNK - 1) asm volatile("cp.async.wait_group 1;" ::: "memory");
        else                asm volatile("cp.async.wait_group 0;" ::: "memory");
        __syncthreads();

        if (c + 2 < NCHUNK) {
            uint32_t base = sb + ((c + 2) % STAGES) * STAGE_BYTES;
            int k0 = (c + 2) * BKC;
#pragma unroll
            for (int i = 0; i < 4; i++) {
                cp16(base + sOffA[i], Ag[i] + k0);
                cp16(base + sOffB[i], Bg[i] + k0);
            }
            cp_commit();
        }

        const uint32_t stage = sb + (c % STAGES) * STAGE_BYTES;
#pragma unroll
        for (int ks = 0; ks < 4; ks++) {
            uint32_t af[4][4], bf[2][4];
#pragma unroll
            for (int mi = 0; mi < 4; mi++)
                ldsm_x4(af[mi], stage + arbase[mi] +
                        ((uint32_t)((ks * 2 + ahi) * 16) ^ axor[mi]));
#pragma unroll
            for (int p = 0; p < 2; p++)
                ldsm_x4(bf[p], stage + bpbase[p] +
                        ((uint32_t)((ks * 2 + bsel) * 16) ^ bpxor));
#pragma unroll
            for (int mi = 0; mi < 4; mi++)
#pragma unroll
                for (int ni = 0; ni < 4; ni++)
                    mma_bf16(acc[mi][ni], af[mi], &bf[ni >> 1][(ni & 1) * 2]);
        }
    }

    const int qrow = lane >> 2;
    const int qcol = (lane & 3) * 2;
#pragma unroll
    for (int mi = 0; mi < 4; mi++) {
        int m_lo = bm + warp_m * 64 + mi * 16 + qrow;
        int m_hi = m_lo + 8;
#pragma unroll
        for (int ni = 0; ni < 4; ni++) {
            int n = bn + warp_n * 32 + ni * 8 + qcol;
            float2 bv = *(const float2*)(bias + n);
            float x0 = acc[mi][ni][0] + bv.x, y0 = acc[mi][ni][1] + bv.y;
            float x1 = acc[mi][ni][2] + bv.x, y1 = acc[mi][ni][3] + bv.y;
            if (OUT_MODE == 1) {
                x0 *= scale; y0 *= scale; x1 *= scale; y1 *= scale;
                __nv_bfloat16* out = (__nv_bfloat16*)outv;
                int hh = n >> 6, d0 = n & (HDIM - 1);
                int b0 = m_lo >> 11, t0 = m_lo & (TT - 1);
                int b1 = m_hi >> 11, t1 = m_hi & (TT - 1);
                size_t base0 = ((size_t)((b0*HH + hh)*TT + t0)) << 7;
                size_t base1 = ((size_t)((b1*HH + hh)*TT + t1)) << 7;
                __nv_bfloat16 hx0 = __float2bfloat16(x0), hy0 = __float2bfloat16(y0);
                __nv_bfloat16 hx1 = __float2bfloat16(x1), hy1 = __float2bfloat16(y1);
                *(uint32_t*)(out + base0 + d0)      = packh2(hx0, hy0);
                *(uint32_t*)(out + base0 + 64 + d0) = packbf2(x0 - __bfloat162float(hx0),
                                                              y0 - __bfloat162float(hy0));
                *(uint32_t*)(out + base1 + d0)      = packh2(hx1, hy1);
                *(uint32_t*)(out + base1 + 64 + d0) = packbf2(x1 - __bfloat162float(hx1),
                                                              y1 - __bfloat162float(hy1));
            } else {
                float* out = (float*)outv;
                float2 lo; lo.x = x0; lo.y = y0;
                float2 hi; hi.x = x1; hi.y = y1;
                *(float2*)(out + (size_t)m_lo * DD + n) = lo;
                *(float2*)(out + (size_t)m_hi * DD + n) = hi;
            }
        }
    }
}

__global__ __launch_bounds__(256)
void hmma_gemm3_kernel(const __nv_bfloat16* A0, const __nv_bfloat16* A1,
                       const __nv_bfloat16* A2,
                       const __nv_bfloat16* B0, const __nv_bfloat16* B1,
                       const __nv_bfloat16* B2,
                       const float* b0, const float* b1, const float* b2,
                       __nv_bfloat16* o0, __nv_bfloat16* o1, __nv_bfloat16* o2,
                       float s0)
{
    extern __shared__ char smem[];
    const int z = blockIdx.z;
    const __nv_bfloat16* A = (z == 0) ? A0 : (z == 1) ? A1 : A2;
    const __nv_bfloat16* B = (z == 0) ? B0 : (z == 1) ? B1 : B2;
    const float* bias      = (z == 0) ? b0 : (z == 1) ? b1 : b2;
    __nv_bfloat16* out     = (z == 0) ? o0 : (z == 1) ? o1 : o2;
    float scale            = (z == 0) ? s0 : 1.0f;
    gemm_body<1>(A, B, bias, out, scale, smem);
}

__global__ __launch_bounds__(256)
void hmma_gemm_out_kernel(const __nv_bfloat16* __restrict__ A,
                          const __nv_bfloat16* __restrict__ B,
                          const float* __restrict__ bias,
                          float* __restrict__ out)
{
    extern __shared__ char smem[];
    gemm_body<0>(A, B, bias, out, 1.0f, smem);
}

// ---------------------------------------------------------------------------
// Flash attention (causal), mma.sync bf16 split precision, log2-domain scores.
// K and V B-fragments loaded pairwise via ldmatrix.x4 / x4.trans.
// ---------------------------------------------------------------------------
__device__ __forceinline__ void fl_load_kv(uint32_t stage, const __nv_bfloat16* Kb,
                                           const __nv_bfloat16* Vb, int k0, int tid)
{
#pragma unroll
    for (int i = 0; i < 4; i++) {
        int id = tid + i * 256;
        int row = id >> 4, ch = id & 15;
        uint32_t o = (ch < 8) ? SMEM_SWIZZLE_128B((uint32_t)(row*128 + ch*16))
                              : 8192u + SMEM_SWIZZLE_128B((uint32_t)(row*128 + (ch-8)*16));
        cp16(stage + o, Kb + ((size_t)(k0 + row) << 7) + ch * 8);
    }
#pragma unroll
    for (int i = 0; i < 4; i++) {
        int id = tid + i * 256;
        int row = id >> 4, ch = id & 15;
        uint32_t o = (ch < 8) ? SMEM_SWIZZLE_128B((uint32_t)(row*128 + ch*16))
                              : 8192u + SMEM_SWIZZLE_128B((uint32_t)(row*128 + (ch-8)*16));
        cp16(stage + 16384u + o, Vb + ((size_t)(k0 + row) << 7) + ch * 8);
    }
}

__global__ __launch_bounds__(256)
void flash_hmma_kernel(const __nv_bfloat16* __restrict__ Qg,
                       const __nv_bfloat16* __restrict__ Kg,
                       const __nv_bfloat16* __restrict__ Vg,
                       __nv_bfloat16* __restrict__ Xout)
{
    extern __shared__ char smem[];
    const uint32_t sb = smem_to_u32(smem);
    const int tid = threadIdx.x, wid = tid >> 5, lane = tid & 31;
    const int qt = blockIdx.x, bh = blockIdx.y;
    const int q0 = qt * 128;
    const int qbase = q0 + wid * 16;
    const int ntiles = 2 * qt + 2;

    const __nv_bfloat16* Qb = Qg + (((size_t)bh * TT + q0) << 7);
    const __nv_bfloat16* Kb = Kg + ((size_t)bh * TT << 7);
    const __nv_bfloat16* Vb = Vg + ((size_t)bh * TT << 7);

#pragma unroll
    for (int i = 0; i < 8; i++) {
        int id = tid + i * 256;
        int row = id >> 4, ch = id & 15;
        uint32_t o = (ch < 8) ? FL_QH + SMEM_SWIZZLE_128B((uint32_t)(row*128 + ch*16))
                              : FL_QL + SMEM_SWIZZLE_128B((uint32_t)(row*128 + (ch-8)*16));
        cp16(sb + o, Qb + ((size_t)row << 7) + ch * 8);
    }
    cp_commit();
    fl_load_kv(sb + FL_STG, Kb, Vb, 0, tid);
    cp_commit();

    // A (Q) fragment addressing
    const int ahi = (lane >> 4) & 1;
    const int arow = wid * 16 + (lane & 15);
    const uint32_t arb = (uint32_t)arow * 128;
    const uint32_t ax  = (uint32_t)(arow & 7) * 16;
    // Paired K addressing: x4, pair p covers nt=2p,2p+1
    const int bsel = (lane >> 3) & 1;
    const int bRowP = (((lane >> 4) & 1) << 3) + (lane & 7);
    uint32_t bpb[4];
#pragma unroll
    for (int p = 0; p < 4; p++) bpb[p] = (uint32_t)(bRowP + p * 16) * 128;
    const uint32_t bpx = (uint32_t)(lane & 7) * 16;
    // Paired V addressing: x4.trans, pair p covers nt=2p,2p+1 (col select via lane>>4)
    const int vhi = (lane >> 4) & 1;
    uint32_t vpb[4];
#pragma unroll
    for (int kc = 0; kc < 4; kc++)
        vpb[kc] = (uint32_t)(kc * 16 + (lane & 15)) * 128;
    const uint32_t vpx = (uint32_t)(lane & 7) * 16;

    float oacc[8][4];
#pragma unroll
    for (int nt = 0; nt < 8; nt++)
#pragma unroll
        for (int e = 0; e < 4; e++) oacc[nt][e] = 0.f;
    float m0 = -1e30f, m1 = -1e30f, l0 = 0.f, l1 = 0.f;

    for (int j = 0; j < ntiles; j++) {
        const int k0 = j * 64;
        if (j + 1 < ntiles) {
            fl_load_kv(sb + FL_STG + ((j + 1) & 1) * 32768u, Kb, Vb, (j + 1) * 64, tid);
            cp_commit();
            asm volatile("cp.async.wait_group 1;" ::: "memory");
        } else {
            asm volatile("cp.async.wait_group 0;" ::: "memory");
        }
        __syncthreads();
        const uint32_t stage = sb + FL_STG + (j & 1) * 32768u;

        if (k0 <= qbase + 15) {
            float sacc[8][4];
#pragma unroll
            for (int nt = 0; nt < 8; nt++)
#pragma unroll
                for (int e = 0; e < 4; e++) sacc[nt][e] = 0.f;

            // S = qh*kh + ql*kh + qh*kl  (paired K loads)
#pragma unroll
            for (int ks = 0; ks < 4; ks++) {
                const uint32_t koff = (((uint32_t)((ks*2 + ahi)*16)) ^ ax);
                const uint32_t bko  = (((uint32_t)((ks*2 + bsel)*16)) ^ bpx);
                uint32_t Ah[4], Al[4];
                ldsm_x4(Ah, sb + FL_QH + arb + koff);
                ldsm_x4(Al, sb + FL_QL + arb + koff);
#pragma unroll
                for (int p = 0; p < 4; p++) {
                    uint32_t Bh[4], Bl[4];
                    ldsm_x4(Bh, stage + bpb[p] + bko);
                    ldsm_x4(Bl, stage + 8192u + bpb[p] + bko);
                    mma_bf16(sacc[2*p],   Ah, Bh);
                    mma_bf16(sacc[2*p],   Al, Bh);
                    mma_bf16(sacc[2*p],   Ah, Bl);
                    mma_bf16(sacc[2*p+1], Ah, Bh + 2);
                    mma_bf16(sacc[2*p+1], Al, Bh + 2);
                    mma_bf16(sacc[2*p+1], Ah, Bl + 2);
                }
            }

            // causal mask
            const int qg0 = qbase + (lane >> 2);
            const int qg1 = qg0 + 8;
            if (k0 + 63 > qbase) {
#pragma unroll
                for (int nt = 0; nt < 8; nt++) {
                    int kgb = k0 + nt * 8 + (lane & 3) * 2;
                    if (kgb     > qg0) sacc[nt][0] = -1e30f;
                    if (kgb + 1 > qg0) sacc[nt][1] = -1e30f;
                    if (kgb     > qg1) sacc[nt][2] = -1e30f;
                    if (kgb + 1 > qg1) sacc[nt][3] = -1e30f;
                }
            }

            // online softmax (log2 domain)
            float mx0 = -1e30f, mx1 = -1e30f;
#pragma unroll
            for (int nt = 0; nt < 8; nt++) {
                mx0 = fmaxf(mx0, fmaxf(sacc[nt][0], sacc[nt][1]));
                mx1 = fmaxf(mx1, fmaxf(sacc[nt][2], sacc[nt][3]));
            }
            mx0 = fmaxf(mx0, __shfl_xor_sync(0xffffffffu, mx0, 1));
            mx0 = fmaxf(mx0, __shfl_xor_sync(0xffffffffu, mx0, 2));
            mx1 = fmaxf(mx1, __shfl_xor_sync(0xffffffffu, mx1, 1));
            mx1 = fmaxf(mx1, __shfl_xor_sync(0xffffffffu, mx1, 2));
            const float nm0 = fmaxf(m0, mx0), nm1 = fmaxf(m1, mx1);
            const float sc0 = exp2f(m0 - nm0), sc1 = exp2f(m1 - nm1);
            float sum0 = 0.f, sum1 = 0.f;
#pragma unroll
            for (int nt = 0; nt < 8; nt++) {
                sacc[nt][0] = exp2f(sacc[nt][0] - nm0); sum0 += sacc[nt][0];
                sacc[nt][1] = exp2f(sacc[nt][1] - nm0); sum0 += sacc[nt][1];
                sacc[nt][2] = exp2f(sacc[nt][2] - nm1); sum1 += sacc[nt][2];
                sacc[nt][3] = exp2f(sacc[nt][3] - nm1); sum1 += sacc[nt][3];
            }
            sum0 += __shfl_xor_sync(0xffffffffu, sum0, 1);
            sum0 += __shfl_xor_sync(0xffffffffu, sum0, 2);
            sum1 += __shfl_xor_sync(0xffffffffu, sum1, 1);
            sum1 += __shfl_xor_sync(0xffffffffu, sum1, 2);
            l0 = l0 * sc0 + sum0;  l1 = l1 * sc1 + sum1;
            m0 = nm0;  m1 = nm1;
#pragma unroll
            for (int nt = 0; nt < 8; nt++) {
                oacc[nt][0] *= sc0; oacc[nt][1] *= sc0;
                oacc[nt][2] *= sc1; oacc[nt][3] *= sc1;
            }

            // P -> split bf16 fragments
            uint32_t phg[8], phg8[8], plg[8], plg8[8];
#pragma unroll
            for (int nt = 0; nt < 8; nt++) {
                float p0 = sacc[nt][0], p1 = sacc[nt][1];
                float p2 = sacc[nt][2], p3 = sacc[nt][3];
                __nv_bfloat16 h0 = __float2bfloat16(p0), h1 = __float2bfloat16(p1);
                __nv_bfloat16 h2 = __float2bfloat16(p2), h3 = __float2bfloat16(p3);
                phg[nt]  = packh2(h0, h1);
                phg8[nt] = packh2(h2, h3);
                plg[nt]  = packbf2(p0 - __bfloat162float(h0), p1 - __bfloat162float(h1));
                plg8[nt] = packbf2(p2 - __bfloat162float(h2), p3 - __bfloat162float(h3));
            }

            // O += ph*Vh + pl*Vh + ph*Vl  (paired V loads)
#pragma unroll
            for (int kc = 0; kc < 4; kc++) {
                uint32_t Afh[4], Afl[4];
                Afh[0] = phg[2*kc];   Afh[1] = phg8[2*kc];
                Afh[2] = phg[2*kc+1]; Afh[3] = phg8[2*kc+1];
                Afl[0] = plg[2*kc];   Afl[1] = plg8[2*kc];
                Afl[2] = plg[2*kc+1]; Afl[3] = plg8[2*kc+1];
#pragma unroll
                for (int p = 0; p < 4; p++) {
                    const uint32_t voff = vpb[kc] + (((uint32_t)((2*p + vhi)*16)) ^ vpx);
                    uint32_t Vh[4], Vl[4];
                    ldsm_x4_trans(Vh, stage + 16384u + voff);
                    ldsm_x4_trans(Vl, stage + 24576u + voff);
                    mma_bf16(oacc[2*p],   Afh, Vh);
                    mma_bf16(oacc[2*p],   Afl, Vh);
                    mma_bf16(oacc[2*p],   Afh, Vl);
                    mma_bf16(oacc[2*p+1], Afh, Vh + 2);
                    mma_bf16(oacc[2*p+1], Afl, Vh + 2);
                    mma_bf16(oacc[2*p+1], Afh, Vl + 2);
                }
            }
        }
        __syncthreads();
    }

    // epilogue: normalize, split, write [hi|lo|hi] activations
    const int b = bh >> 4, h = bh & 15;
    const int t0 = qbase + (lane >> 2);
    const int t1 = t0 + 8;
    const size_t r0 = (size_t)(b * TT + t0) * GK;
    const size_t r1 = (size_t)(b * TT + t1) * GK;
    const float i0 = 1.f / l0, i1 = 1.f / l1;
    const int cbase = h * 64 + (lane & 3) * 2;
#pragma unroll
    for (int nt = 0; nt < 8; nt++) {
        int c = cbase + nt * 8;
        float v0 = oacc[nt][0] * i0, v1 = oacc[nt][1] * i0;
        float w0 = oacc[nt][2] * i1, w1 = oacc[nt][3] * i1;
        __nv_bfloat16 a0 = __float2bfloat16(v0), a1 = __float2bfloat16(v1);
        __nv_bfloat16 b0 = __float2bfloat16(w0), b1 = __float2bfloat16(w1);
        uint32_t hp0 = packh2(a0, a1);
        uint32_t lp0 = packbf2(v0 - __bfloat162float(a0), v1 - __bfloat162float(a1));
        uint32_t hp1 = packh2(b0, b1);
        uint32_t lp1 = packbf2(w0 - __bfloat162float(b0), w1 - __bfloat162float(b1));
        *(uint32_t*)(Xout + r0 + c)        = hp0;
        *(uint32_t*)(Xout + r0 + 1024 + c) = lp0;
        *(uint32_t*)(Xout + r0 + 2048 + c) = hp0;
        *(uint32_t*)(Xout + r1 + c)        = hp1;
        *(uint32_t*)(Xout + r1 + 1024 + c) = lp1;
        *(uint32_t*)(Xout + r1 + 2048 + c) = hp1;
    }
}

// ---------------------------------------------------------------------------
extern "C" void kernel_launch(void* const* d_in, const int* in_sizes, int n_in,
                              void* d_out, int out_size)
{
    const float* q  = (const float*)d_in[0];
    const float* k  = (const float*)d_in[1];
    const float* v  = (const float*)d_in[2];
    const float* wq = (const float*)d_in[3];
    const float* bq = (const float*)d_in[4];
    const float* wk = (const float*)d_in[5];
    const float* bk = (const float*)d_in[6];
    const float* wv = (const float*)d_in[7];
    const float* bv = (const float*)d_in[8];
    const float* wo = (const float*)d_in[9];
    const float* bo = (const float*)d_in[10];
    float* out = (float*)d_out;

    __nv_bfloat16 *gqc, *gkc, *gvc, *gx0, *gx1, *gx2, *gw0, *gw1, *gw2, *gw3;
    cudaGetSymbolAddress((void**)&gqc, g_qc);
    cudaGetSymbolAddress((void**)&gkc, g_kc);
    cudaGetSymbolAddress((void**)&gvc, g_vc);
    cudaGetSymbolAddress((void**)&gx0, g_x0);
    cudaGetSymbolAddress((void**)&gx1, g_x1);
    cudaGetSymbolAddress((void**)&gx2, g_x2);
    cudaGetSymbolAddress((void**)&gw0, g_w0);
    cudaGetSymbolAddress((void**)&gw1, g_w1);
    cudaGetSymbolAddress((void**)&gw2, g_w2);
    cudaGetSymbolAddress((void**)&gw3, g_w3);

    cudaFuncSetAttribute(hmma_gemm3_kernel,
                         cudaFuncAttributeMaxDynamicSharedMemorySize, GEMM_SMEM_SZ);
    cudaFuncSetAttribute(hmma_gemm_out_kernel,
                         cudaFuncAttributeMaxDynamicSharedMemorySize, GEMM_SMEM_SZ);
    cudaFuncSetAttribute(flash_hmma_kernel,
                         cudaFuncAttributeMaxDynamicSharedMemorySize, FL_SMEM);

    // Converts: activations (q,k,v) and all 4 weights
    convert_act3_kernel<<<dim3(MM, 3), 256>>>(q, k, v, gx0, gx1, gx2);
    convert_w4_kernel<<<dim3(DD, 4), 256>>>(wq, wk, wv, wo, gw0, gw1, gw2, gw3);

    // Batched QKV projections (Q pre-scaled by 0.125*log2e for exp2 softmax)
    hmma_gemm3_kernel<<<dim3(DD/128, MM/128, 3), 256, GEMM_SMEM_SZ>>>(
        gx0, gx1, gx2, gw0, gw1, gw2, bq, bk, bv, gqc, gkc, gvc, QSCALE);

    // Attention (writes split activations into gx0)
    flash_hmma_kernel<<<dim3(TT/128, BB*HH), 256, FL_SMEM>>>(gqc, gkc, gvc, gx0);

    // Output projection
    hmma_gemm_out_kernel<<<dim3(DD/128, MM/128), 256, GEMM_SMEM_SZ>>>(gx0, gw3, bo, out);
}

// round 15
// speedup vs baseline: 3.8801x; 1.1563x over previous
#include <cuda_runtime.h>
#include <cuda_bf16.h>
#include <cuda_fp16.h>
#include <cstdint>
#include <cstddef>

// Problem constants
#define BB   4
#define TT   2048
#define DD   1024
#define HH   16
#define HDIM 64
#define MM   (BB*TT)   // 8192
#define GK   3072      // split-bf16 concatenated K ( [h|l|h] x [h|h|l] )
#define BKC  64        // bf16 K per GEMM pipeline stage
#define NCHUNK (GK/BKC) // 48
#define STAGES 3
#define STAGE_BYTES 32768
#define GEMM_SMEM_SZ (STAGES*STAGE_BYTES)   // 96KB

// Flash smem layout (dynamic, 96KB)
#define FL_QH   0u
#define FL_QL   16384u
#define FL_STG  32768u
#define FL_SMEM 98304

// Q projection scale: (1/sqrt(64)) * log2(e)  -> scores in log2 domain
#define QSCALE 0.1803368801111204f

// Scratch (device globals; no allocation allowed)
__device__ __nv_bfloat16 g_qc[(size_t)BB*HH*TT*128];  // [b][h][t][hi(64)|lo(64)] bf16
__device__ __nv_bfloat16 g_kc[(size_t)BB*HH*TT*128];  // bf16 split
__device__ __nv_bfloat16 g_vc[(size_t)BB*HH*TT*128];  // fp16 split (bytes reinterpreted)
__device__ __nv_bfloat16 g_x0[(size_t)MM*GK];         // act buffers [hi|lo|hi]
__device__ __nv_bfloat16 g_x1[(size_t)MM*GK];
__device__ __nv_bfloat16 g_x2[(size_t)MM*GK];
__device__ __nv_bfloat16 g_w0[(size_t)DD*GK];         // weights [hi|hi|lo]
__device__ __nv_bfloat16 g_w1[(size_t)DD*GK];
__device__ __nv_bfloat16 g_w2[(size_t)DD*GK];
__device__ __nv_bfloat16 g_w3[(size_t)DD*GK];

// ---------------------------------------------------------------------------
// Portable PTX helpers
// ---------------------------------------------------------------------------
__device__ __forceinline__ uint32_t smem_to_u32(const void* p) {
    uint32_t a;
    asm("{ .reg .u64 t; cvta.to.shared.u64 t, %1; cvt.u32.u64 %0, t; }" : "=r"(a) : "l"(p));
    return a;
}
__device__ __forceinline__ void cp16(uint32_t saddr, const void* g) {
    asm volatile("cp.async.cg.shared.global [%0], [%1], 16;" :: "r"(saddr), "l"(g));
}
__device__ __forceinline__ void cp_commit() {
    asm volatile("cp.async.commit_group;" ::: "memory");
}
__device__ __forceinline__ void ldsm_x4(uint32_t* r, uint32_t addr) {
    asm volatile("ldmatrix.sync.aligned.m8n8.x4.shared.b16 {%0,%1,%2,%3}, [%4];"
        : "=r"(r[0]), "=r"(r[1]), "=r"(r[2]), "=r"(r[3]) : "r"(addr));
}
__device__ __forceinline__ void ldsm_x4_trans(uint32_t* r, uint32_t addr) {
    asm volatile("ldmatrix.sync.aligned.m8n8.x4.trans.shared.b16 {%0,%1,%2,%3}, [%4];"
        : "=r"(r[0]), "=r"(r[1]), "=r"(r[2]), "=r"(r[3]) : "r"(addr));
}
__device__ __forceinline__ void mma_bf16(float* c, const uint32_t* a, const uint32_t* b) {
    asm volatile("mma.sync.aligned.m16n8k16.row.col.f32.bf16.bf16.f32 "
        "{%0,%1,%2,%3}, {%4,%5,%6,%7}, {%8,%9}, {%0,%1,%2,%3};"
        : "+f"(c[0]), "+f"(c[1]), "+f"(c[2]), "+f"(c[3])
        : "r"(a[0]), "r"(a[1]), "r"(a[2]), "r"(a[3]), "r"(b[0]), "r"(b[1]));
}
__device__ __forceinline__ void mma_f16(float* c, const uint32_t* a, const uint32_t* b) {
    asm volatile("mma.sync.aligned.m16n8k16.row.col.f32.f16.f16.f32 "
        "{%0,%1,%2,%3}, {%4,%5,%6,%7}, {%8,%9}, {%0,%1,%2,%3};"
        : "+f"(c[0]), "+f"(c[1]), "+f"(c[2]), "+f"(c[3])
        : "r"(a[0]), "r"(a[1]), "r"(a[2]), "r"(a[3]), "r"(b[0]), "r"(b[1]));
}
// pack {lo,hi} f32 -> bf16x2 / f16x2 (lo in bits[15:0])
__device__ __forceinline__ uint32_t packbf2(float lo, float hi) {
    uint32_t r;
    asm("cvt.rn.bf16x2.f32 %0, %1, %2;" : "=r"(r) : "f"(hi), "f"(lo));
    return r;
}
__device__ __forceinline__ uint32_t packf16_2(float lo, float hi) {
    uint32_t r;
    asm("cvt.rn.f16x2.f32 %0, %1, %2;" : "=r"(r) : "f"(hi), "f"(lo));
    return r;
}
__device__ __forceinline__ uint32_t packh2(__nv_bfloat16 a, __nv_bfloat16 b) {
    __nv_bfloat162 t = __halves2bfloat162(a, b);
    return *reinterpret_cast<uint32_t*>(&t);
}
#define SMEM_SWIZZLE_128B(off) ((off) ^ (((off) >> 3) & 0x70))

// ---------------------------------------------------------------------------
// Split conversions. Act: [hi|lo|hi]; Weight: [hi|hi|lo].
// ---------------------------------------------------------------------------
template<int WMODE>
__device__ __forceinline__ void conv_row(const float* __restrict__ in,
                                         __nv_bfloat16* __restrict__ out,
                                         int row, int tid)
{
    int c = tid << 2;
    float4 x = *(const float4*)(in + (size_t)row * 1024 + c);
    __nv_bfloat16 h0 = __float2bfloat16(x.x);
    __nv_bfloat16 h1 = __float2bfloat16(x.y);
    __nv_bfloat16 h2 = __float2bfloat16(x.z);
    __nv_bfloat16 h3 = __float2bfloat16(x.w);
    __nv_bfloat16 l0 = __float2bfloat16(x.x - __bfloat162float(h0));
    __nv_bfloat16 l1 = __float2bfloat16(x.y - __bfloat162float(h1));
    __nv_bfloat16 l2 = __float2bfloat16(x.z - __bfloat162float(h2));
    __nv_bfloat16 l3 = __float2bfloat16(x.w - __bfloat162float(h3));
    __nv_bfloat162 hA = __halves2bfloat162(h0, h1), hB = __halves2bfloat162(h2, h3);
    __nv_bfloat162 lA = __halves2bfloat162(l0, l1), lB = __halves2bfloat162(l2, l3);
    size_t base = (size_t)row * GK + c;
    __nv_bfloat162* o0 = (__nv_bfloat162*)(out + base);
    __nv_bfloat162* o1 = (__nv_bfloat162*)(out + base + 1024);
    __nv_bfloat162* o2 = (__nv_bfloat162*)(out + base + 2048);
    o0[0] = hA; o0[1] = hB;
    if (WMODE) { o1[0] = hA; o1[1] = hB; o2[0] = lA; o2[1] = lB; }
    else       { o1[0] = lA; o1[1] = lB; o2[0] = hA; o2[1] = hB; }
}

__global__ void convert_act3_kernel(const float* __restrict__ q,
                                    const float* __restrict__ k,
                                    const float* __restrict__ v,
                                    __nv_bfloat16* __restrict__ o0,
                                    __nv_bfloat16* __restrict__ o1,
                                    __nv_bfloat16* __restrict__ o2)
{
    const float* in = (blockIdx.y == 0) ? q : (blockIdx.y == 1) ? k : v;
    __nv_bfloat16* out = (blockIdx.y == 0) ? o0 : (blockIdx.y == 1) ? o1 : o2;
    conv_row<0>(in, out, blockIdx.x, threadIdx.x);
}

__global__ void convert_w4_kernel(const float* __restrict__ w0,
                                  const float* __restrict__ w1,
                                  const float* __restrict__ w2,
                                  const float* __restrict__ w3,
                                  __nv_bfloat16* __restrict__ o0,
                                  __nv_bfloat16* __restrict__ o1,
                                  __nv_bfloat16* __restrict__ o2,
                                  __nv_bfloat16* __restrict__ o3)
{
    const float* in = (blockIdx.y == 0) ? w0 : (blockIdx.y == 1) ? w1
                    : (blockIdx.y == 2) ? w2 : w3;
    __nv_bfloat16* out = (blockIdx.y == 0) ? o0 : (blockIdx.y == 1) ? o1
                       : (blockIdx.y == 2) ? o2 : o3;
    conv_row<1>(in, out, blockIdx.x, threadIdx.x);
}

// ---------------------------------------------------------------------------
// HMMA GEMM core (128x128 CTA tile). B loads paired via ldmatrix.x4.
// OUT_MODE 0: fp32 [m][1024].
// OUT_MODE 1: split bf16 head layout [b][h][t][hi|lo], scaled.
// OUT_MODE 2: split fp16 head layout (for V).
// ---------------------------------------------------------------------------
template<int OUT_MODE>
__device__ __forceinline__ void gemm_body(const __nv_bfloat16* __restrict__ A,
                                          const __nv_bfloat16* __restrict__ B,
                                          const float* __restrict__ bias,
                                          void* __restrict__ outv, float scale,
                                          char* smem)
{
    const uint32_t sb = smem_to_u32(smem);
    const int tid  = threadIdx.x;
    const int wid  = tid >> 5, lane = tid & 31;
    const int warp_m = wid >> 2;
    const int warp_n = wid & 3;
    const int bm = blockIdx.y * 128, bn = blockIdx.x * 128;

    const __nv_bfloat16* Ag[4];
    const __nv_bfloat16* Bg[4];
    uint32_t sOffA[4], sOffB[4];
#pragma unroll
    for (int i = 0; i < 4; i++) {
        int id = tid + i * 256;
        int grow = id >> 3, gch = id & 7;
        Ag[i] = A + (size_t)(bm + grow) * GK + gch * 8;
        Bg[i] = B + (size_t)(bn + grow) * GK + gch * 8;
        sOffA[i] = SMEM_SWIZZLE_128B((uint32_t)(grow * 128 + gch * 16));
        sOffB[i] = sOffA[i] + 16384;
    }

#pragma unroll
    for (int s = 0; s < 2; s++) {
        uint32_t base = sb + s * STAGE_BYTES;
        int k0 = s * BKC;
#pragma unroll
        for (int i = 0; i < 4; i++) {
            cp16(base + sOffA[i], Ag[i] + k0);
            cp16(base + sOffB[i], Bg[i] + k0);
        }
        cp_commit();
    }

    uint32_t arbase[4], axor[4];
    const int ahi = (lane >> 4) & 1;
#pragma unroll
    for (int mi = 0; mi < 4; mi++) {
        int row = warp_m * 64 + mi * 16 + (lane & 15);
        arbase[mi] = (uint32_t)row * 128;
        axor[mi]   = (uint32_t)(row & 7) * 16;
    }
    const int bsel = (lane >> 3) & 1;
    const int bRowP = warp_n * 32 + (((lane >> 4) & 1) << 3) + (lane & 7);
    uint32_t bpbase[2];
#pragma unroll
    for (int p = 0; p < 2; p++)
        bpbase[p] = (uint32_t)(bRowP + p * 16) * 128 + 16384;
    const uint32_t bpxor = (uint32_t)(lane & 7) * 16;

    float acc[4][4][4];
#pragma unroll
    for (int mi = 0; mi < 4; mi++)
#pragma unroll
        for (int ni = 0; ni < 4; ni++)
#pragma unroll
            for (int e = 0; e < 4; e++) acc[mi][ni][e] = 0.f;

    for (int c = 0; c < NCHUNK; c++) {
        if (c < NCHUNK - 1) asm volatile("cp.async.wait_group 1;" ::: "memory");
        else                asm volatile("cp.async.wait_group 0;" ::: "memory");
        __syncthreads();

        if (c + 2 < NCHUNK) {
            uint32_t base = sb + ((c + 2) % STAGES) * STAGE_BYTES;
            int k0 = (c + 2) * BKC;
#pragma unroll
            for (int i = 0; i < 4; i++) {
                cp16(base + sOffA[i], Ag[i] + k0);
                cp16(base + sOffB[i], Bg[i] + k0);
            }
            cp_commit();
        }

        const uint32_t stage = sb + (c % STAGES) * STAGE_BYTES;
#pragma unroll
        for (int ks = 0; ks < 4; ks++) {
            uint32_t af[4][4], bf[2][4];
#pragma unroll
            for (int mi = 0; mi < 4; mi++)
                ldsm_x4(af[mi], stage + arbase[mi] +
                        ((uint32_t)((ks * 2 + ahi) * 16) ^ axor[mi]));
#pragma unroll
            for (int p = 0; p < 2; p++)
                ldsm_x4(bf[p], stage + bpbase[p] +
                        ((uint32_t)((ks * 2 + bsel) * 16) ^ bpxor));
#pragma unroll
            for (int mi = 0; mi < 4; mi++)
#pragma unroll
                for (int ni = 0; ni < 4; ni++)
                    mma_bf16(acc[mi][ni], af[mi], &bf[ni >> 1][(ni & 1) * 2]);
        }
    }

    const int qrow = lane >> 2;
    const int qcol = (lane & 3) * 2;
#pragma unroll
    for (int mi = 0; mi < 4; mi++) {
        int m_lo = bm + warp_m * 64 + mi * 16 + qrow;
        int m_hi = m_lo + 8;
#pragma unroll
        for (int ni = 0; ni < 4; ni++) {
            int n = bn + warp_n * 32 + ni * 8 + qcol;
            float2 bv = *(const float2*)(bias + n);
            float x0 = acc[mi][ni][0] + bv.x, y0 = acc[mi][ni][1] + bv.y;
            float x1 = acc[mi][ni][2] + bv.x, y1 = acc[mi][ni][3] + bv.y;
            if (OUT_MODE >= 1) {
                x0 *= scale; y0 *= scale; x1 *= scale; y1 *= scale;
                char* out = (char*)outv;
                int hh = n >> 6, d0 = n & (HDIM - 1);
                int b0 = m_lo >> 11, t0 = m_lo & (TT - 1);
                int b1 = m_hi >> 11, t1 = m_hi & (TT - 1);
                size_t base0 = (((size_t)((b0*HH + hh)*TT + t0)) << 8);  // bytes: 128 elems * 2
                size_t base1 = (((size_t)((b1*HH + hh)*TT + t1)) << 8);
                if (OUT_MODE == 1) {
                    __nv_bfloat16 hx0 = __float2bfloat16(x0), hy0 = __float2bfloat16(y0);
                    __nv_bfloat16 hx1 = __float2bfloat16(x1), hy1 = __float2bfloat16(y1);
                    *(uint32_t*)(out + base0 + d0*2)       = packh2(hx0, hy0);
                    *(uint32_t*)(out + base0 + 128 + d0*2) = packbf2(x0 - __bfloat162float(hx0),
                                                                     y0 - __bfloat162float(hy0));
                    *(uint32_t*)(out + base1 + d0*2)       = packh2(hx1, hy1);
                    *(uint32_t*)(out + base1 + 128 + d0*2) = packbf2(x1 - __bfloat162float(hx1),
                                                                     y1 - __bfloat162float(hy1));
                } else {
                    __half hx0 = __float2half_rn(x0), hy0 = __float2half_rn(y0);
                    __half hx1 = __float2half_rn(x1), hy1 = __float2half_rn(y1);
                    __half2 hp0 = __halves2half2(hx0, hy0);
                    __half2 hp1 = __halves2half2(hx1, hy1);
                    *(uint32_t*)(out + base0 + d0*2)       = *reinterpret_cast<uint32_t*>(&hp0);
                    *(uint32_t*)(out + base0 + 128 + d0*2) = packf16_2(x0 - __half2float(hx0),
                                                                       y0 - __half2float(hy0));
                    *(uint32_t*)(out + base1 + d0*2)       = *reinterpret_cast<uint32_t*>(&hp1);
                    *(uint32_t*)(out + base1 + 128 + d0*2) = packf16_2(x1 - __half2float(hx1),
                                                                       y1 - __half2float(hy1));
                }
            } else {
                float* out = (float*)outv;
                float2 lo; lo.x = x0; lo.y = y0;
                float2 hi; hi.x = x1; hi.y = y1;
                *(float2*)(out + (size_t)m_lo * DD + n) = lo;
                *(float2*)(out + (size_t)m_hi * DD + n) = hi;
            }
        }
    }
}

__global__ __launch_bounds__(256)
void hmma_gemm3_kernel(const __nv_bfloat16* A0, const __nv_bfloat16* A1,
                       const __nv_bfloat16* A2,
                       const __nv_bfloat16* B0, const __nv_bfloat16* B1,
                       const __nv_bfloat16* B2,
                       const float* b0, const float* b1, const float* b2,
                       __nv_bfloat16* o0, __nv_bfloat16* o1, __nv_bfloat16* o2,
                       float s0)
{
    extern __shared__ char smem[];
    const int z = blockIdx.z;
    if (z == 2) {
        gemm_body<2>(A2, B2, b2, o2, 1.0f, smem);          // V: fp16 split
    } else if (z == 1) {
        gemm_body<1>(A1, B1, b1, o1, 1.0f, smem);          // K: bf16 split
    } else {
        gemm_body<1>(A0, B0, b0, o0, s0, smem);            // Q: bf16 split, scaled
    }
}

__global__ __launch_bounds__(256)
void hmma_gemm_out_kernel(const __nv_bfloat16* __restrict__ A,
                          const __nv_bfloat16* __restrict__ B,
                          const float* __restrict__ bias,
                          float* __restrict__ out)
{
    extern __shared__ char smem[];
    gemm_body<0>(A, B, bias, out, 1.0f, smem);
}

// ---------------------------------------------------------------------------
// Flash attention (causal), heavy-first scheduling (qt reversed on grid.y).
// S: bf16 3-term split. PV: P fp16 single x V fp16 split (2 MMAs).
// ---------------------------------------------------------------------------
__device__ __forceinline__ void fl_load_kv(uint32_t stage, const __nv_bfloat16* Kb,
                                           const __nv_bfloat16* Vb, int k0, int tid)
{
#pragma unroll
    for (int i = 0; i < 4; i++) {
        int id = tid + i * 256;
        int row = id >> 4, ch = id & 15;
        uint32_t o = (ch < 8) ? SMEM_SWIZZLE_128B((uint32_t)(row*128 + ch*16))
                              : 8192u + SMEM_SWIZZLE_128B((uint32_t)(row*128 + (ch-8)*16));
        cp16(stage + o, Kb + ((size_t)(k0 + row) << 7) + ch * 8);
    }
#pragma unroll
    for (int i = 0; i < 4; i++) {
        int id = tid + i * 256;
        int row = id >> 4, ch = id & 15;
        uint32_t o = (ch < 8) ? SMEM_SWIZZLE_128B((uint32_t)(row*128 + ch*16))
                              : 8192u + SMEM_SWIZZLE_128B((uint32_t)(row*128 + (ch-8)*16));
        cp16(stage + 16384u + o, Vb + ((size_t)(k0 + row) << 7) + ch * 8);
    }
}

__global__ __launch_bounds__(256)
void flash_hmma_kernel(const __nv_bfloat16* __restrict__ Qg,
                       const __nv_bfloat16* __restrict__ Kg,
                       const __nv_bfloat16* __restrict__ Vg,
                       __nv_bfloat16* __restrict__ Xout)
{
    extern __shared__ char smem[];
    const uint32_t sb = smem_to_u32(smem);
    const int tid = threadIdx.x, wid = tid >> 5, lane = tid & 31;
    const int bh = blockIdx.x;
    const int qt = gridDim.y - 1 - blockIdx.y;     // heavy tiles launch first
    const int q0 = qt * 128;
    const int qbase = q0 + wid * 16;
    const int ntiles = 2 * qt + 2;

    const __nv_bfloat16* Qb = Qg + (((size_t)bh * TT + q0) << 7);
    const __nv_bfloat16* Kb = Kg + ((size_t)bh * TT << 7);
    const __nv_bfloat16* Vb = Vg + ((size_t)bh * TT << 7);

#pragma unroll
    for (int i = 0; i < 8; i++) {
        int id = tid + i * 256;
        int row = id >> 4, ch = id & 15;
        uint32_t o = (ch < 8) ? FL_QH + SMEM_SWIZZLE_128B((uint32_t)(row*128 + ch*16))
                              : FL_QL + SMEM_SWIZZLE_128B((uint32_t)(row*128 + (ch-8)*16));
        cp16(sb + o, Qb + ((size_t)row << 7) + ch * 8);
    }
    cp_commit();
    fl_load_kv(sb + FL_STG, Kb, Vb, 0, tid);
    cp_commit();

    // A (Q) fragment addressing
    const int ahi = (lane >> 4) & 1;
    const int arow = wid * 16 + (lane & 15);
    const uint32_t arb = (uint32_t)arow * 128;
    const uint32_t ax  = (uint32_t)(arow & 7) * 16;
    // Paired K addressing: x4, pair p covers nt=2p,2p+1
    const int bsel = (lane >> 3) & 1;
    const int bRowP = (((lane >> 4) & 1) << 3) + (lane & 7);
    uint32_t bpb[4];
#pragma unroll
    for (int p = 0; p < 4; p++) bpb[p] = (uint32_t)(bRowP + p * 16) * 128;
    const uint32_t bpx = (uint32_t)(lane & 7) * 16;
    // Paired V addressing: x4.trans
    const int vhi = (lane >> 4) & 1;
    uint32_t vpb[4];
#pragma unroll
    for (int kc = 0; kc < 4; kc++)
        vpb[kc] = (uint32_t)(kc * 16 + (lane & 15)) * 128;
    const uint32_t vpx = (uint32_t)(lane & 7) * 16;

    float oacc[8][4];
#pragma unroll
    for (int nt = 0; nt < 8; nt++)
#pragma unroll
        for (int e = 0; e < 4; e++) oacc[nt][e] = 0.f;
    float m0 = -1e30f, m1 = -1e30f, l0 = 0.f, l1 = 0.f;

    for (int j = 0; j < ntiles; j++) {
        const int k0 = j * 64;
        if (j + 1 < ntiles) {
            fl_load_kv(sb + FL_STG + ((j + 1) & 1) * 32768u, Kb, Vb, (j + 1) * 64, tid);
            cp_commit();
            asm volatile("cp.async.wait_group 1;" ::: "memory");
        } else {
            asm volatile("cp.async.wait_group 0;" ::: "memory");
        }
        __syncthreads();
        const uint32_t stage = sb + FL_STG + (j & 1) * 32768u;

        if (k0 <= qbase + 15) {
            float sacc[8][4];
#pragma unroll
            for (int nt = 0; nt < 8; nt++)
#pragma unroll
                for (int e = 0; e < 4; e++) sacc[nt][e] = 0.f;

            // S = qh*kh + ql*kh + qh*kl  (paired K loads)
#pragma unroll
            for (int ks = 0; ks < 4; ks++) {
                const uint32_t koff = (((uint32_t)((ks*2 + ahi)*16)) ^ ax);
                const uint32_t bko  = (((uint32_t)((ks*2 + bsel)*16)) ^ bpx);
                uint32_t Ah[4], Al[4];
                ldsm_x4(Ah, sb + FL_QH + arb + koff);
                ldsm_x4(Al, sb + FL_QL + arb + koff);
#pragma unroll
                for (int p = 0; p < 4; p++) {
                    uint32_t Bh[4], Bl[4];
                    ldsm_x4(Bh, stage + bpb[p] + bko);
                    ldsm_x4(Bl, stage + 8192u + bpb[p] + bko);
                    mma_bf16(sacc[2*p],   Ah, Bh);
                    mma_bf16(sacc[2*p],   Al, Bh);
                    mma_bf16(sacc[2*p],   Ah, Bl);
                    mma_bf16(sacc[2*p+1], Ah, Bh + 2);
                    mma_bf16(sacc[2*p+1], Al, Bh + 2);
                    mma_bf16(sacc[2*p+1], Ah, Bl + 2);
                }
            }

            // causal mask
            const int qg0 = qbase + (lane >> 2);
            const int qg1 = qg0 + 8;
            if (k0 + 63 > qbase) {
#pragma unroll
                for (int nt = 0; nt < 8; nt++) {
                    int kgb = k0 + nt * 8 + (lane & 3) * 2;
                    if (kgb     > qg0) sacc[nt][0] = -1e30f;
                    if (kgb + 1 > qg0) sacc[nt][1] = -1e30f;
                    if (kgb     > qg1) sacc[nt][2] = -1e30f;
                    if (kgb + 1 > qg1) sacc[nt][3] = -1e30f;
                }
            }

            // online softmax (log2 domain)
            float mx0 = -1e30f, mx1 = -1e30f;
#pragma unroll
            for (int nt = 0; nt < 8; nt++) {
                mx0 = fmaxf(mx0, fmaxf(sacc[nt][0], sacc[nt][1]));
                mx1 = fmaxf(mx1, fmaxf(sacc[nt][2], sacc[nt][3]));
            }
            mx0 = fmaxf(mx0, __shfl_xor_sync(0xffffffffu, mx0, 1));
            mx0 = fmaxf(mx0, __shfl_xor_sync(0xffffffffu, mx0, 2));
            mx1 = fmaxf(mx1, __shfl_xor_sync(0xffffffffu, mx1, 1));
            mx1 = fmaxf(mx1, __shfl_xor_sync(0xffffffffu, mx1, 2));
            const float nm0 = fmaxf(m0, mx0), nm1 = fmaxf(m1, mx1);
            const float sc0 = exp2f(m0 - nm0), sc1 = exp2f(m1 - nm1);
            float sum0 = 0.f, sum1 = 0.f;
#pragma unroll
            for (int nt = 0; nt < 8; nt++) {
                sacc[nt][0] = exp2f(sacc[nt][0] - nm0); sum0 += sacc[nt][0];
                sacc[nt][1] = exp2f(sacc[nt][1] - nm0); sum0 += sacc[nt][1];
                sacc[nt][2] = exp2f(sacc[nt][2] - nm1); sum1 += sacc[nt][2];
                sacc[nt][3] = exp2f(sacc[nt][3] - nm1); sum1 += sacc[nt][3];
            }
            sum0 += __shfl_xor_sync(0xffffffffu, sum0, 1);
            sum0 += __shfl_xor_sync(0xffffffffu, sum0, 2);
            sum1 += __shfl_xor_sync(0xffffffffu, sum1, 1);
            sum1 += __shfl_xor_sync(0xffffffffu, sum1, 2);
            l0 = l0 * sc0 + sum0;  l1 = l1 * sc1 + sum1;
            m0 = nm0;  m1 = nm1;
#pragma unroll
            for (int nt = 0; nt < 8; nt++) {
                oacc[nt][0] *= sc0; oacc[nt][1] *= sc0;
                oacc[nt][2] *= sc1; oacc[nt][3] *= sc1;
            }

            // P -> single fp16 fragments
            uint32_t phg[8], phg8[8];
#pragma unroll
            for (int nt = 0; nt < 8; nt++) {
                phg[nt]  = packf16_2(sacc[nt][0], sacc[nt][1]);
                phg8[nt] = packf16_2(sacc[nt][2], sacc[nt][3]);
            }

            // O += P*Vh + P*Vl  (V fp16 split; paired V loads)
#pragma unroll
            for (int kc = 0; kc < 4; kc++) {
                uint32_t Af[4];
                Af[0] = phg[2*kc];   Af[1] = phg8[2*kc];
                Af[2] = phg[2*kc+1]; Af[3] = phg8[2*kc+1];
#pragma unroll
                for (int p = 0; p < 4; p++) {
                    const uint32_t voff = vpb[kc] + (((uint32_t)((2*p + vhi)*16)) ^ vpx);
                    uint32_t Vh[4], Vl[4];
                    ldsm_x4_trans(Vh, stage + 16384u + voff);
                    ldsm_x4_trans(Vl, stage + 24576u + voff);
                    mma_f16(oacc[2*p],   Af, Vh);
                    mma_f16(oacc[2*p],   Af, Vl);
                    mma_f16(oacc[2*p+1], Af, Vh + 2);
                    mma_f16(oacc[2*p+1], Af, Vl + 2);
                }
            }
        }
        __syncthreads();
    }

    // epilogue: normalize, split, write [hi|lo|hi] activations
    const int b = bh >> 4, h = bh & 15;
    const int t0 = qbase + (lane >> 2);
    const int t1 = t0 + 8;
    const size_t r0 = (size_t)(b * TT + t0) * GK;
    const size_t r1 = (size_t)(b * TT + t1) * GK;
    const float i0 = 1.f / l0, i1 = 1.f / l1;
    const int cbase = h * 64 + (lane & 3) * 2;
#pragma unroll
    for (int nt = 0; nt < 8; nt++) {
        int c = cbase + nt * 8;
        float v0 = oacc[nt][0] * i0, v1 = oacc[nt][1] * i0;
        float w0 = oacc[nt][2] * i1, w1 = oacc[nt][3] * i1;
        __nv_bfloat16 a0 = __float2bfloat16(v0), a1 = __float2bfloat16(v1);
        __nv_bfloat16 b0 = __float2bfloat16(w0), b1 = __float2bfloat16(w1);
        uint32_t hp0 = packh2(a0, a1);
        uint32_t lp0 = packbf2(v0 - __bfloat162float(a0), v1 - __bfloat162float(a1));
        uint32_t hp1 = packh2(b0, b1);
        uint32_t lp1 = packbf2(w0 - __bfloat162float(b0), w1 - __bfloat162float(b1));
        *(uint32_t*)(Xout + r0 + c)        = hp0;
        *(uint32_t*)(Xout + r0 + 1024 + c) = lp0;
        *(uint32_t*)(Xout + r0 + 2048 + c) = hp0;
        *(uint32_t*)(Xout + r1 + c)        = hp1;
        *(uint32_t*)(Xout + r1 + 1024 + c) = lp1;
        *(uint32_t*)(Xout + r1 + 2048 + c) = hp1;
    }
}

// ---------------------------------------------------------------------------
extern "C" void kernel_launch(void* const* d_in, const int* in_sizes, int n_in,
                              void* d_out, int out_size)
{
    const float* q  = (const float*)d_in[0];
    const float* k  = (const float*)d_in[1];
    const float* v  = (const float*)d_in[2];
    const float* wq = (const float*)d_in[3];
    const float* bq = (const float*)d_in[4];
    const float* wk = (const float*)d_in[5];
    const float* bk = (const float*)d_in[6];
    const float* wv = (const float*)d_in[7];
    const float* bv = (const float*)d_in[8];
    const float* wo = (const float*)d_in[9];
    const float* bo = (const float*)d_in[10];
    float* out = (float*)d_out;

    __nv_bfloat16 *gqc, *gkc, *gvc, *gx0, *gx1, *gx2, *gw0, *gw1, *gw2, *gw3;
    cudaGetSymbolAddress((void**)&gqc, g_qc);
    cudaGetSymbolAddress((void**)&gkc, g_kc);
    cudaGetSymbolAddress((void**)&gvc, g_vc);
    cudaGetSymbolAddress((void**)&gx0, g_x0);
    cudaGetSymbolAddress((void**)&gx1, g_x1);
    cudaGetSymbolAddress((void**)&gx2, g_x2);
    cudaGetSymbolAddress((void**)&gw0, g_w0);
    cudaGetSymbolAddress((void**)&gw1, g_w1);
    cudaGetSymbolAddress((void**)&gw2, g_w2);
    cudaGetSymbolAddress((void**)&gw3, g_w3);

    cudaFuncSetAttribute(hmma_gemm3_kernel,
                         cudaFuncAttributeMaxDynamicSharedMemorySize, GEMM_SMEM_SZ);
    cudaFuncSetAttribute(hmma_gemm_out_kernel,
                         cudaFuncAttributeMaxDynamicSharedMemorySize, GEMM_SMEM_SZ);
    cudaFuncSetAttribute(flash_hmma_kernel,
                         cudaFuncAttributeMaxDynamicSharedMemorySize, FL_SMEM);

    // Converts: activations (q,k,v) and all 4 weights
    convert_act3_kernel<<<dim3(MM, 3), 256>>>(q, k, v, gx0, gx1, gx2);
    convert_w4_kernel<<<dim3(DD, 4), 256>>>(wq, wk, wv, wo, gw0, gw1, gw2, gw3);

    // Batched QKV projections (Q pre-scaled; V emitted as fp16 split)
    hmma_gemm3_kernel<<<dim3(DD/128, MM/128, 3), 256, GEMM_SMEM_SZ>>>(
        gx0, gx1, gx2, gw0, gw1, gw2, bq, bk, bv, gqc, gkc, gvc, QSCALE);

    // Attention (heavy q-tiles first; writes split activations into gx0)
    flash_hmma_kernel<<<dim3(BB*HH, TT/128), 256, FL_SMEM>>>(gqc, gkc, gvc, gx0);

    // Output projection
    hmma_gemm_out_kernel<<<dim3(DD/128, MM/128), 256, GEMM_SMEM_SZ>>>(gx0, gw3, bo, out);
}

// round 16
// speedup vs baseline: 4.6801x; 1.2062x over previous
#include <cuda_runtime.h>
#include <cuda_bf16.h>
#include <cuda_fp16.h>
#include <cstdint>
#include <cstddef>

// Problem constants
#define BB   4
#define TT   2048
#define DD   1024
#define HH   16
#define HDIM 64
#define MM   (BB*TT)   // 8192
#define GK2  2048      // fp16 split activations [xh|xl]; weights single fp16 (1024)
#define BKC  64        // halves per pipeline chunk (128B rows, SW128)
#define NCH2 32        // GK2/BKC
#define STAGES 3
#define STAGE_BYTES 32768
#define GEMM_SMEM_SZ (STAGES*STAGE_BYTES)   // 96KB

// Flash smem layout (dynamic, 96KB)
#define FL_QH   0u
#define FL_QL   16384u
#define FL_STG  32768u
#define FL_SMEM 98304

// Q projection scale: (1/sqrt(64)) * log2(e)  -> scores in log2 domain
#define QSCALE 0.1803368801111204f

// Scratch (device globals; no allocation allowed)
__device__ __nv_bfloat16 g_qc[(size_t)BB*HH*TT*128];  // [b][h][t][hi|lo] bf16 split
__device__ __nv_bfloat16 g_kc[(size_t)BB*HH*TT*128];  // bf16 split
__device__ __nv_bfloat16 g_vc[(size_t)BB*HH*TT*128];  // fp16 split (reinterpreted)
__device__ __half g_x0[(size_t)MM*GK2];               // act [xh|xl] fp16
__device__ __half g_x1[(size_t)MM*GK2];
__device__ __half g_x2[(size_t)MM*GK2];
__device__ __half g_w0[(size_t)DD*1024];              // weights single fp16
__device__ __half g_w1[(size_t)DD*1024];
__device__ __half g_w2[(size_t)DD*1024];
__device__ __half g_w3[(size_t)DD*1024];

// ---------------------------------------------------------------------------
// Portable PTX helpers
// ---------------------------------------------------------------------------
__device__ __forceinline__ uint32_t smem_to_u32(const void* p) {
    uint32_t a;
    asm("{ .reg .u64 t; cvta.to.shared.u64 t, %1; cvt.u32.u64 %0, t; }" : "=r"(a) : "l"(p));
    return a;
}
__device__ __forceinline__ void cp16(uint32_t saddr, const void* g) {
    asm volatile("cp.async.cg.shared.global [%0], [%1], 16;" :: "r"(saddr), "l"(g));
}
__device__ __forceinline__ void cp_commit() {
    asm volatile("cp.async.commit_group;" ::: "memory");
}
__device__ __forceinline__ void ldsm_x4(uint32_t* r, uint32_t addr) {
    asm volatile("ldmatrix.sync.aligned.m8n8.x4.shared.b16 {%0,%1,%2,%3}, [%4];"
        : "=r"(r[0]), "=r"(r[1]), "=r"(r[2]), "=r"(r[3]) : "r"(addr));
}
__device__ __forceinline__ void ldsm_x4_trans(uint32_t* r, uint32_t addr) {
    asm volatile("ldmatrix.sync.aligned.m8n8.x4.trans.shared.b16 {%0,%1,%2,%3}, [%4];"
        : "=r"(r[0]), "=r"(r[1]), "=r"(r[2]), "=r"(r[3]) : "r"(addr));
}
__device__ __forceinline__ void mma_bf16(float* c, const uint32_t* a, const uint32_t* b) {
    asm volatile("mma.sync.aligned.m16n8k16.row.col.f32.bf16.bf16.f32 "
        "{%0,%1,%2,%3}, {%4,%5,%6,%7}, {%8,%9}, {%0,%1,%2,%3};"
        : "+f"(c[0]), "+f"(c[1]), "+f"(c[2]), "+f"(c[3])
        : "r"(a[0]), "r"(a[1]), "r"(a[2]), "r"(a[3]), "r"(b[0]), "r"(b[1]));
}
__device__ __forceinline__ void mma_f16(float* c, const uint32_t* a, const uint32_t* b) {
    asm volatile("mma.sync.aligned.m16n8k16.row.col.f32.f16.f16.f32 "
        "{%0,%1,%2,%3}, {%4,%5,%6,%7}, {%8,%9}, {%0,%1,%2,%3};"
        : "+f"(c[0]), "+f"(c[1]), "+f"(c[2]), "+f"(c[3])
        : "r"(a[0]), "r"(a[1]), "r"(a[2]), "r"(a[3]), "r"(b[0]), "r"(b[1]));
}
// pack {lo,hi} f32 -> bf16x2 / f16x2 (lo in bits[15:0])
__device__ __forceinline__ uint32_t packbf2(float lo, float hi) {
    uint32_t r;
    asm("cvt.rn.bf16x2.f32 %0, %1, %2;" : "=r"(r) : "f"(hi), "f"(lo));
    return r;
}
__device__ __forceinline__ uint32_t packf16_2(float lo, float hi) {
    uint32_t r;
    asm("cvt.rn.f16x2.f32 %0, %1, %2;" : "=r"(r) : "f"(hi), "f"(lo));
    return r;
}
__device__ __forceinline__ uint32_t packh2(__nv_bfloat16 a, __nv_bfloat16 b) {
    __nv_bfloat162 t = __halves2bfloat162(a, b);
    return *reinterpret_cast<uint32_t*>(&t);
}
__device__ __forceinline__ uint32_t packhh(__half a, __half b) {
    __half2 t = __halves2half2(a, b);
    return *reinterpret_cast<uint32_t*>(&t);
}
#define SMEM_SWIZZLE_128B(off) ((off) ^ (((off) >> 3) & 0x70))

// ---------------------------------------------------------------------------
// Conversions. Act: fp32[1024] -> fp16 split [xh(1024)|xl(1024)].
// Weight: fp32[1024] -> fp16 [wh(1024)].
// ---------------------------------------------------------------------------
__global__ void convert_act3_kernel(const float* __restrict__ q,
                                    const float* __restrict__ k,
                                    const float* __restrict__ v,
                                    __half* __restrict__ o0,
                                    __half* __restrict__ o1,
                                    __half* __restrict__ o2)
{
    const float* in = (blockIdx.y == 0) ? q : (blockIdx.y == 1) ? k : v;
    __half* out = (blockIdx.y == 0) ? o0 : (blockIdx.y == 1) ? o1 : o2;
    int row = blockIdx.x;
    int c = threadIdx.x << 2;
    float4 x = *(const float4*)(in + (size_t)row * 1024 + c);
    __half h0 = __float2half_rn(x.x), h1 = __float2half_rn(x.y);
    __half h2 = __float2half_rn(x.z), h3 = __float2half_rn(x.w);
    uint32_t l01 = packf16_2(x.x - __half2float(h0), x.y - __half2float(h1));
    uint32_t l23 = packf16_2(x.z - __half2float(h2), x.w - __half2float(h3));
    size_t base = (size_t)row * GK2 + c;
    *(uint32_t*)(out + base)            = packhh(h0, h1);
    *(uint32_t*)(out + base + 2)        = packhh(h2, h3);
    *(uint32_t*)(out + base + 1024)     = l01;
    *(uint32_t*)(out + base + 1026)     = l23;
}

__global__ void convert_w4_kernel(const float* __restrict__ w0,
                                  const float* __restrict__ w1,
                                  const float* __restrict__ w2,
                                  const float* __restrict__ w3,
                                  __half* __restrict__ o0,
                                  __half* __restrict__ o1,
                                  __half* __restrict__ o2,
                                  __half* __restrict__ o3)
{
    const float* in = (blockIdx.y == 0) ? w0 : (blockIdx.y == 1) ? w1
                    : (blockIdx.y == 2) ? w2 : w3;
    __half* out = (blockIdx.y == 0) ? o0 : (blockIdx.y == 1) ? o1
                : (blockIdx.y == 2) ? o2 : o3;
    int row = blockIdx.x;
    int c = threadIdx.x << 2;
    float4 x = *(const float4*)(in + (size_t)row * 1024 + c);
    size_t base = (size_t)row * 1024 + c;
    *(uint32_t*)(out + base)     = packf16_2(x.x, x.y);
    *(uint32_t*)(out + base + 2) = packf16_2(x.z, x.w);
}

// ---------------------------------------------------------------------------
// HMMA GEMM core (128x128 CTA tile), fp16. A: [M,GK2]=[xh|xl] (stride 2048);
// B: [N,1024] single fp16, chunk index (c & 15) reuses wh for both A halves.
// OUT_MODE 0: fp32 [m][1024].  1: split bf16 head layout, scaled.
// 2: split fp16 head layout (V).
// ---------------------------------------------------------------------------
template<int OUT_MODE>
__device__ __forceinline__ void gemm_body(const __half* __restrict__ A,
                                          const __half* __restrict__ B,
                                          const float* __restrict__ bias,
                                          void* __restrict__ outv, float scale,
                                          char* smem)
{
    const uint32_t sb = smem_to_u32(smem);
    const int tid  = threadIdx.x;
    const int wid  = tid >> 5, lane = tid & 31;
    const int warp_m = wid >> 2;
    const int warp_n = wid & 3;
    const int bm = blockIdx.y * 128, bn = blockIdx.x * 128;

    const __half* Ag[4];
    const __half* Bg[4];
    uint32_t sOffA[4], sOffB[4];
#pragma unroll
    for (int i = 0; i < 4; i++) {
        int id = tid + i * 256;
        int grow = id >> 3, gch = id & 7;
        Ag[i] = A + (size_t)(bm + grow) * GK2 + gch * 8;
        Bg[i] = B + (size_t)(bn + grow) * 1024 + gch * 8;
        sOffA[i] = SMEM_SWIZZLE_128B((uint32_t)(grow * 128 + gch * 16));
        sOffB[i] = sOffA[i] + 16384;
    }

#pragma unroll
    for (int s = 0; s < 2; s++) {
        uint32_t base = sb + s * STAGE_BYTES;
        int k0a = s * BKC;
        int k0b = (s & 15) * BKC;
#pragma unroll
        for (int i = 0; i < 4; i++) {
            cp16(base + sOffA[i], Ag[i] + k0a);
            cp16(base + sOffB[i], Bg[i] + k0b);
        }
        cp_commit();
    }

    uint32_t arbase[4], axor[4];
    const int ahi = (lane >> 4) & 1;
#pragma unroll
    for (int mi = 0; mi < 4; mi++) {
        int row = warp_m * 64 + mi * 16 + (lane & 15);
        arbase[mi] = (uint32_t)row * 128;
        axor[mi]   = (uint32_t)(row & 7) * 16;
    }
    const int bsel = (lane >> 3) & 1;
    const int bRowP = warp_n * 32 + (((lane >> 4) & 1) << 3) + (lane & 7);
    uint32_t bpbase[2];
#pragma unroll
    for (int p = 0; p < 2; p++)
        bpbase[p] = (uint32_t)(bRowP + p * 16) * 128 + 16384;
    const uint32_t bpxor = (uint32_t)(lane & 7) * 16;

    float acc[4][4][4];
#pragma unroll
    for (int mi = 0; mi < 4; mi++)
#pragma unroll
        for (int ni = 0; ni < 4; ni++)
#pragma unroll
            for (int e = 0; e < 4; e++) acc[mi][ni][e] = 0.f;

    for (int c = 0; c < NCH2; c++) {
        if (c < NCH2 - 1) asm volatile("cp.async.wait_group 1;" ::: "memory");
        else              asm volatile("cp.async.wait_group 0;" ::: "memory");
        __syncthreads();

        if (c + 2 < NCH2) {
            uint32_t base = sb + ((c + 2) % STAGES) * STAGE_BYTES;
            int k0a = (c + 2) * BKC;
            int k0b = ((c + 2) & 15) * BKC;
#pragma unroll
            for (int i = 0; i < 4; i++) {
                cp16(base + sOffA[i], Ag[i] + k0a);
                cp16(base + sOffB[i], Bg[i] + k0b);
            }
            cp_commit();
        }

        const uint32_t stage = sb + (c % STAGES) * STAGE_BYTES;
#pragma unroll
        for (int ks = 0; ks < 4; ks++) {
            uint32_t af[4][4], bf[2][4];
#pragma unroll
            for (int mi = 0; mi < 4; mi++)
                ldsm_x4(af[mi], stage + arbase[mi] +
                        ((uint32_t)((ks * 2 + ahi) * 16) ^ axor[mi]));
#pragma unroll
            for (int p = 0; p < 2; p++)
                ldsm_x4(bf[p], stage + bpbase[p] +
                        ((uint32_t)((ks * 2 + bsel) * 16) ^ bpxor));
#pragma unroll
            for (int mi = 0; mi < 4; mi++)
#pragma unroll
                for (int ni = 0; ni < 4; ni++)
                    mma_f16(acc[mi][ni], af[mi], &bf[ni >> 1][(ni & 1) * 2]);
        }
    }

    const int qrow = lane >> 2;
    const int qcol = (lane & 3) * 2;
#pragma unroll
    for (int mi = 0; mi < 4; mi++) {
        int m_lo = bm + warp_m * 64 + mi * 16 + qrow;
        int m_hi = m_lo + 8;
#pragma unroll
        for (int ni = 0; ni < 4; ni++) {
            int n = bn + warp_n * 32 + ni * 8 + qcol;
            float2 bv = *(const float2*)(bias + n);
            float x0 = acc[mi][ni][0] + bv.x, y0 = acc[mi][ni][1] + bv.y;
            float x1 = acc[mi][ni][2] + bv.x, y1 = acc[mi][ni][3] + bv.y;
            if (OUT_MODE >= 1) {
                x0 *= scale; y0 *= scale; x1 *= scale; y1 *= scale;
                char* out = (char*)outv;
                int hh = n >> 6, d0 = n & (HDIM - 1);
                int b0 = m_lo >> 11, t0 = m_lo & (TT - 1);
                int b1 = m_hi >> 11, t1 = m_hi & (TT - 1);
                size_t base0 = (((size_t)((b0*HH + hh)*TT + t0)) << 8);  // 128 elems * 2B
                size_t base1 = (((size_t)((b1*HH + hh)*TT + t1)) << 8);
                if (OUT_MODE == 1) {
                    __nv_bfloat16 hx0 = __float2bfloat16(x0), hy0 = __float2bfloat16(y0);
                    __nv_bfloat16 hx1 = __float2bfloat16(x1), hy1 = __float2bfloat16(y1);
                    *(uint32_t*)(out + base0 + d0*2)       = packh2(hx0, hy0);
                    *(uint32_t*)(out + base0 + 128 + d0*2) = packbf2(x0 - __bfloat162float(hx0),
                                                                     y0 - __bfloat162float(hy0));
                    *(uint32_t*)(out + base1 + d0*2)       = packh2(hx1, hy1);
                    *(uint32_t*)(out + base1 + 128 + d0*2) = packbf2(x1 - __bfloat162float(hx1),
                                                                     y1 - __bfloat162float(hy1));
                } else {
                    __half hx0 = __float2half_rn(x0), hy0 = __float2half_rn(y0);
                    __half hx1 = __float2half_rn(x1), hy1 = __float2half_rn(y1);
                    *(uint32_t*)(out + base0 + d0*2)       = packhh(hx0, hy0);
                    *(uint32_t*)(out + base0 + 128 + d0*2) = packf16_2(x0 - __half2float(hx0),
                                                                       y0 - __half2float(hy0));
                    *(uint32_t*)(out + base1 + d0*2)       = packhh(hx1, hy1);
                    *(uint32_t*)(out + base1 + 128 + d0*2) = packf16_2(x1 - __half2float(hx1),
                                                                       y1 - __half2float(hy1));
                }
            } else {
                float* out = (float*)outv;
                float2 lo; lo.x = x0; lo.y = y0;
                float2 hi; hi.x = x1; hi.y = y1;
                *(float2*)(out + (size_t)m_lo * DD + n) = lo;
                *(float2*)(out + (size_t)m_hi * DD + n) = hi;
            }
        }
    }
}

__global__ __launch_bounds__(256)
void hmma_gemm3_kernel(const __half* A0, const __half* A1, const __half* A2,
                       const __half* B0, const __half* B1, const __half* B2,
                       const float* b0, const float* b1, const float* b2,
                       __nv_bfloat16* o0, __nv_bfloat16* o1, __nv_bfloat16* o2,
                       float s0)
{
    extern __shared__ char smem[];
    const int z = blockIdx.z;
    if (z == 2) {
        gemm_body<2>(A2, B2, b2, o2, 1.0f, smem);          // V: fp16 split out
    } else if (z == 1) {
        gemm_body<1>(A1, B1, b1, o1, 1.0f, smem);          // K: bf16 split out
    } else {
        gemm_body<1>(A0, B0, b0, o0, s0, smem);            // Q: bf16 split, scaled
    }
}

__global__ __launch_bounds__(256)
void hmma_gemm_out_kernel(const __half* __restrict__ A,
                          const __half* __restrict__ B,
                          const float* __restrict__ bias,
                          float* __restrict__ out)
{
    extern __shared__ char smem[];
    gemm_body<0>(A, B, bias, out, 1.0f, smem);
}

// ---------------------------------------------------------------------------
// Flash attention (causal), heavy-first scheduling.
// S: bf16 3-term split. PV: P fp16 single x V fp16 split.
// Epilogue: fp16 split [oh|ol] activations for the O projection.
// ---------------------------------------------------------------------------
__device__ __forceinline__ void fl_load_kv(uint32_t stage, const __nv_bfloat16* Kb,
                                           const __nv_bfloat16* Vb, int k0, int tid)
{
#pragma unroll
    for (int i = 0; i < 4; i++) {
        int id = tid + i * 256;
        int row = id >> 4, ch = id & 15;
        uint32_t o = (ch < 8) ? SMEM_SWIZZLE_128B((uint32_t)(row*128 + ch*16))
                              : 8192u + SMEM_SWIZZLE_128B((uint32_t)(row*128 + (ch-8)*16));
        cp16(stage + o, Kb + ((size_t)(k0 + row) << 7) + ch * 8);
    }
#pragma unroll
    for (int i = 0; i < 4; i++) {
        int id = tid + i * 256;
        int row = id >> 4, ch = id & 15;
        uint32_t o = (ch < 8) ? SMEM_SWIZZLE_128B((uint32_t)(row*128 + ch*16))
                              : 8192u + SMEM_SWIZZLE_128B((uint32_t)(row*128 + (ch-8)*16));
        cp16(stage + 16384u + o, Vb + ((size_t)(k0 + row) << 7) + ch * 8);
    }
}

__global__ __launch_bounds__(256)
void flash_hmma_kernel(const __nv_bfloat16* __restrict__ Qg,
                       const __nv_bfloat16* __restrict__ Kg,
                       const __nv_bfloat16* __restrict__ Vg,
                       __half* __restrict__ Xout)
{
    extern __shared__ char smem[];
    const uint32_t sb = smem_to_u32(smem);
    const int tid = threadIdx.x, wid = tid >> 5, lane = tid & 31;
    const int bh = blockIdx.x;
    const int qt = gridDim.y - 1 - blockIdx.y;     // heavy tiles first
    const int q0 = qt * 128;
    const int qbase = q0 + wid * 16;
    const int ntiles = 2 * qt + 2;

    const __nv_bfloat16* Qb = Qg + (((size_t)bh * TT + q0) << 7);
    const __nv_bfloat16* Kb = Kg + ((size_t)bh * TT << 7);
    const __nv_bfloat16* Vb = Vg + ((size_t)bh * TT << 7);

#pragma unroll
    for (int i = 0; i < 8; i++) {
        int id = tid + i * 256;
        int row = id >> 4, ch = id & 15;
        uint32_t o = (ch < 8) ? FL_QH + SMEM_SWIZZLE_128B((uint32_t)(row*128 + ch*16))
                              : FL_QL + SMEM_SWIZZLE_128B((uint32_t)(row*128 + (ch-8)*16));
        cp16(sb + o, Qb + ((size_t)row << 7) + ch * 8);
    }
    cp_commit();
    fl_load_kv(sb + FL_STG, Kb, Vb, 0, tid);
    cp_commit();

    const int ahi = (lane >> 4) & 1;
    const int arow = wid * 16 + (lane & 15);
    const uint32_t arb = (uint32_t)arow * 128;
    const uint32_t ax  = (uint32_t)(arow & 7) * 16;
    const int bsel = (lane >> 3) & 1;
    const int bRowP = (((lane >> 4) & 1) << 3) + (lane & 7);
    uint32_t bpb[4];
#pragma unroll
    for (int p = 0; p < 4; p++) bpb[p] = (uint32_t)(bRowP + p * 16) * 128;
    const uint32_t bpx = (uint32_t)(lane & 7) * 16;
    const int vhi = (lane >> 4) & 1;
    uint32_t vpb[4];
#pragma unroll
    for (int kc = 0; kc < 4; kc++)
        vpb[kc] = (uint32_t)(kc * 16 + (lane & 15)) * 128;
    const uint32_t vpx = (uint32_t)(lane & 7) * 16;

    float oacc[8][4];
#pragma unroll
    for (int nt = 0; nt < 8; nt++)
#pragma unroll
        for (int e = 0; e < 4; e++) oacc[nt][e] = 0.f;
    float m0 = -1e30f, m1 = -1e30f, l0 = 0.f, l1 = 0.f;

    for (int j = 0; j < ntiles; j++) {
        const int k0 = j * 64;
        if (j + 1 < ntiles) {
            fl_load_kv(sb + FL_STG + ((j + 1) & 1) * 32768u, Kb, Vb, (j + 1) * 64, tid);
            cp_commit();
            asm volatile("cp.async.wait_group 1;" ::: "memory");
        } else {
            asm volatile("cp.async.wait_group 0;" ::: "memory");
        }
        __syncthreads();
        const uint32_t stage = sb + FL_STG + (j & 1) * 32768u;

        if (k0 <= qbase + 15) {
            float sacc[8][4];
#pragma unroll
            for (int nt = 0; nt < 8; nt++)
#pragma unroll
                for (int e = 0; e < 4; e++) sacc[nt][e] = 0.f;

            // S = qh*kh + ql*kh + qh*kl  (paired K loads)
#pragma unroll
            for (int ks = 0; ks < 4; ks++) {
                const uint32_t koff = (((uint32_t)((ks*2 + ahi)*16)) ^ ax);
                const uint32_t bko  = (((uint32_t)((ks*2 + bsel)*16)) ^ bpx);
                uint32_t Ah[4], Al[4];
                ldsm_x4(Ah, sb + FL_QH + arb + koff);
                ldsm_x4(Al, sb + FL_QL + arb + koff);
#pragma unroll
                for (int p = 0; p < 4; p++) {
                    uint32_t Bh[4], Bl[4];
                    ldsm_x4(Bh, stage + bpb[p] + bko);
                    ldsm_x4(Bl, stage + 8192u + bpb[p] + bko);
                    mma_bf16(sacc[2*p],   Ah, Bh);
                    mma_bf16(sacc[2*p],   Al, Bh);
                    mma_bf16(sacc[2*p],   Ah, Bl);
                    mma_bf16(sacc[2*p+1], Ah, Bh + 2);
                    mma_bf16(sacc[2*p+1], Al, Bh + 2);
                    mma_bf16(sacc[2*p+1], Ah, Bl + 2);
                }
            }

            // causal mask
            const int qg0 = qbase + (lane >> 2);
            const int qg1 = qg0 + 8;
            if (k0 + 63 > qbase) {
#pragma unroll
                for (int nt = 0; nt < 8; nt++) {
                    int kgb = k0 + nt * 8 + (lane & 3) * 2;
                    if (kgb     > qg0) sacc[nt][0] = -1e30f;
                    if (kgb + 1 > qg0) sacc[nt][1] = -1e30f;
                    if (kgb     > qg1) sacc[nt][2] = -1e30f;
                    if (kgb + 1 > qg1) sacc[nt][3] = -1e30f;
                }
            }

            // online softmax (log2 domain)
            float mx0 = -1e30f, mx1 = -1e30f;
#pragma unroll
            for (int nt = 0; nt < 8; nt++) {
                mx0 = fmaxf(mx0, fmaxf(sacc[nt][0], sacc[nt][1]));
                mx1 = fmaxf(mx1, fmaxf(sacc[nt][2], sacc[nt][3]));
            }
            mx0 = fmaxf(mx0, __shfl_xor_sync(0xffffffffu, mx0, 1));
            mx0 = fmaxf(mx0, __shfl_xor_sync(0xffffffffu, mx0, 2));
            mx1 = fmaxf(mx1, __shfl_xor_sync(0xffffffffu, mx1, 1));
            mx1 = fmaxf(mx1, __shfl_xor_sync(0xffffffffu, mx1, 2));
            const float nm0 = fmaxf(m0, mx0), nm1 = fmaxf(m1, mx1);
            const float sc0 = exp2f(m0 - nm0), sc1 = exp2f(m1 - nm1);
            float sum0 = 0.f, sum1 = 0.f;
#pragma unroll
            for (int nt = 0; nt < 8; nt++) {
                sacc[nt][0] = exp2f(sacc[nt][0] - nm0); sum0 += sacc[nt][0];
                sacc[nt][1] = exp2f(sacc[nt][1] - nm0); sum0 += sacc[nt][1];
                sacc[nt][2] = exp2f(sacc[nt][2] - nm1); sum1 += sacc[nt][2];
                sacc[nt][3] = exp2f(sacc[nt][3] - nm1); sum1 += sacc[nt][3];
            }
            sum0 += __shfl_xor_sync(0xffffffffu, sum0, 1);
            sum0 += __shfl_xor_sync(0xffffffffu, sum0, 2);
            sum1 += __shfl_xor_sync(0xffffffffu, sum1, 1);
            sum1 += __shfl_xor_sync(0xffffffffu, sum1, 2);
            l0 = l0 * sc0 + sum0;  l1 = l1 * sc1 + sum1;
            m0 = nm0;  m1 = nm1;
#pragma unroll
            for (int nt = 0; nt < 8; nt++) {
                oacc[nt][0] *= sc0; oacc[nt][1] *= sc0;
                oacc[nt][2] *= sc1; oacc[nt][3] *= sc1;
            }

            // P -> single fp16 fragments
            uint32_t phg[8], phg8[8];
#pragma unroll
            for (int nt = 0; nt < 8; nt++) {
                phg[nt]  = packf16_2(sacc[nt][0], sacc[nt][1]);
                phg8[nt] = packf16_2(sacc[nt][2], sacc[nt][3]);
            }

            // O += P*Vh + P*Vl  (V fp16 split; paired V loads)
#pragma unroll
            for (int kc = 0; kc < 4; kc++) {
                uint32_t Af[4];
                Af[0] = phg[2*kc];   Af[1] = phg8[2*kc];
                Af[2] = phg[2*kc+1]; Af[3] = phg8[2*kc+1];
#pragma unroll
                for (int p = 0; p < 4; p++) {
                    const uint32_t voff = vpb[kc] + (((uint32_t)((2*p + vhi)*16)) ^ vpx);
                    uint32_t Vh[4], Vl[4];
                    ldsm_x4_trans(Vh, stage + 16384u + voff);
                    ldsm_x4_trans(Vl, stage + 24576u + voff);
                    mma_f16(oacc[2*p],   Af, Vh);
                    mma_f16(oacc[2*p],   Af, Vl);
                    mma_f16(oacc[2*p+1], Af, Vh + 2);
                    mma_f16(oacc[2*p+1], Af, Vl + 2);
                }
            }
        }
        __syncthreads();
    }

    // epilogue: normalize, fp16 split, write [oh|ol] activations (stride GK2)
    const int b = bh >> 4, h = bh & 15;
    const int t0 = qbase + (lane >> 2);
    const int t1 = t0 + 8;
    const size_t r0 = (size_t)(b * TT + t0) * GK2;
    const size_t r1 = (size_t)(b * TT + t1) * GK2;
    const float i0 = 1.f / l0, i1 = 1.f / l1;
    const int cbase = h * 64 + (lane & 3) * 2;
#pragma unroll
    for (int nt = 0; nt < 8; nt++) {
        int c = cbase + nt * 8;
        float v0 = oacc[nt][0] * i0, v1 = oacc[nt][1] * i0;
        float w0 = oacc[nt][2] * i1, w1 = oacc[nt][3] * i1;
        __half a0 = __float2half_rn(v0), a1 = __float2half_rn(v1);
        __half b0 = __float2half_rn(w0), b1 = __float2half_rn(w1);
        *(uint32_t*)(Xout + r0 + c)        = packhh(a0, a1);
        *(uint32_t*)(Xout + r0 + 1024 + c) = packf16_2(v0 - __half2float(a0),
                                                       v1 - __half2float(a1));
        *(uint32_t*)(Xout + r1 + c)        = packhh(b0, b1);
        *(uint32_t*)(Xout + r1 + 1024 + c) = packf16_2(w0 - __half2float(b0),
                                                       w1 - __half2float(b1));
    }
}

// ---------------------------------------------------------------------------
extern "C" void kernel_launch(void* const* d_in, const int* in_sizes, int n_in,
                              void* d_out, int out_size)
{
    const float* q  = (const float*)d_in[0];
    const float* k  = (const float*)d_in[1];
    const float* v  = (const float*)d_in[2];
    const float* wq = (const float*)d_in[3];
    const float* bq = (const float*)d_in[4];
    const float* wk = (const float*)d_in[5];
    const float* bk = (const float*)d_in[6];
    const float* wv = (const float*)d_in[7];
    const float* bv = (const float*)d_in[8];
    const float* wo = (const float*)d_in[9];
    const float* bo = (const float*)d_in[10];
    float* out = (float*)d_out;

    __nv_bfloat16 *gqc, *gkc, *gvc;
    __half *gx0, *gx1, *gx2, *gw0, *gw1, *gw2, *gw3;
    cudaGetSymbolAddress((void**)&gqc, g_qc);
    cudaGetSymbolAddress((void**)&gkc, g_kc);
    cudaGetSymbolAddress((void**)&gvc, g_vc);
    cudaGetSymbolAddress((void**)&gx0, g_x0);
    cudaGetSymbolAddress((void**)&gx1, g_x1);
    cudaGetSymbolAddress((void**)&gx2, g_x2);
    cudaGetSymbolAddress((void**)&gw0, g_w0);
    cudaGetSymbolAddress((void**)&gw1, g_w1);
    cudaGetSymbolAddress((void**)&gw2, g_w2);
    cudaGetSymbolAddress((void**)&gw3, g_w3);

    cudaFuncSetAttribute(hmma_gemm3_kernel,
                         cudaFuncAttributeMaxDynamicSharedMemorySize, GEMM_SMEM_SZ);
    cudaFuncSetAttribute(hmma_gemm_out_kernel,
                         cudaFuncAttributeMaxDynamicSharedMemorySize, GEMM_SMEM_SZ);
    cudaFuncSetAttribute(flash_hmma_kernel,
                         cudaFuncAttributeMaxDynamicSharedMemorySize, FL_SMEM);

    // Converts: activations (q,k,v) fp16 split; weights single fp16
    convert_act3_kernel<<<dim3(MM, 3), 256>>>(q, k, v, gx0, gx1, gx2);
    convert_w4_kernel<<<dim3(DD, 4), 256>>>(wq, wk, wv, wo, gw0, gw1, gw2, gw3);

    // Batched QKV projections (Q pre-scaled; V emitted as fp16 split)
    hmma_gemm3_kernel<<<dim3(DD/128, MM/128, 3), 256, GEMM_SMEM_SZ>>>(
        gx0, gx1, gx2, gw0, gw1, gw2, bq, bk, bv, gqc, gkc, gvc, QSCALE);

    // Attention (heavy q-tiles first; writes fp16 split activations into gx0)
    flash_hmma_kernel<<<dim3(BB*HH, TT/128), 256, FL_SMEM>>>(gqc, gkc, gvc, gx0);

    // Output projection
    hmma_gemm_out_kernel<<<dim3(DD/128, MM/128), 256, GEMM_SMEM_SZ>>>(gx0, gw3, bo, out);
}

// round 17
// speedup vs baseline: 6.8718x; 1.4683x over previous
#include <cuda_runtime.h>
#include <cuda_bf16.h>
#include <cuda_fp16.h>
#include <cstdint>
#include <cstddef>

// Problem constants
#define BB   4
#define TT   2048
#define DD   1024
#define HH   16
#define HDIM 64
#define MM   (BB*TT)   // 8192
#define BKC  64        // fp16 per pipeline chunk (128B rows, SW128)
#define NCH  16        // 1024/BKC
#define STAGES 3
#define STAGE_BYTES 32768
#define GEMM_SMEM_SZ (STAGES*STAGE_BYTES)   // 96KB

// Flash smem layout (dynamic, 96KB)
#define FL_QH   0u
#define FL_QL   16384u
#define FL_STG  32768u
#define FL_SMEM 98304

// Q projection scale: (1/sqrt(64)) * log2(e)  -> scores in log2 domain
#define QSCALE 0.1803368801111204f

// Scratch (device globals; no allocation allowed)
__device__ __nv_bfloat16 g_qc[(size_t)BB*HH*TT*128];  // [b][h][t][hi|lo] bf16 split
__device__ __nv_bfloat16 g_kc[(size_t)BB*HH*TT*128];  // bf16 split
__device__ __nv_bfloat16 g_vc[(size_t)BB*HH*TT*128];  // fp16 split (reinterpreted)
__device__ __half g_x0[(size_t)MM*1024];              // activations single fp16
__device__ __half g_x1[(size_t)MM*1024];
__device__ __half g_x2[(size_t)MM*1024];
__device__ __half g_w0[(size_t)DD*1024];              // weights single fp16
__device__ __half g_w1[(size_t)DD*1024];
__device__ __half g_w2[(size_t)DD*1024];
__device__ __half g_w3[(size_t)DD*1024];

// ---------------------------------------------------------------------------
// Portable PTX helpers
// ---------------------------------------------------------------------------
__device__ __forceinline__ uint32_t smem_to_u32(const void* p) {
    uint32_t a;
    asm("{ .reg .u64 t; cvta.to.shared.u64 t, %1; cvt.u32.u64 %0, t; }" : "=r"(a) : "l"(p));
    return a;
}
__device__ __forceinline__ void cp16(uint32_t saddr, const void* g) {
    asm volatile("cp.async.cg.shared.global [%0], [%1], 16;" :: "r"(saddr), "l"(g));
}
__device__ __forceinline__ void cp_commit() {
    asm volatile("cp.async.commit_group;" ::: "memory");
}
__device__ __forceinline__ void ldsm_x4(uint32_t* r, uint32_t addr) {
    asm volatile("ldmatrix.sync.aligned.m8n8.x4.shared.b16 {%0,%1,%2,%3}, [%4];"
        : "=r"(r[0]), "=r"(r[1]), "=r"(r[2]), "=r"(r[3]) : "r"(addr));
}
__device__ __forceinline__ void ldsm_x4_trans(uint32_t* r, uint32_t addr) {
    asm volatile("ldmatrix.sync.aligned.m8n8.x4.trans.shared.b16 {%0,%1,%2,%3}, [%4];"
        : "=r"(r[0]), "=r"(r[1]), "=r"(r[2]), "=r"(r[3]) : "r"(addr));
}
__device__ __forceinline__ void mma_bf16(float* c, const uint32_t* a, const uint32_t* b) {
    asm volatile("mma.sync.aligned.m16n8k16.row.col.f32.bf16.bf16.f32 "
        "{%0,%1,%2,%3}, {%4,%5,%6,%7}, {%8,%9}, {%0,%1,%2,%3};"
        : "+f"(c[0]), "+f"(c[1]), "+f"(c[2]), "+f"(c[3])
        : "r"(a[0]), "r"(a[1]), "r"(a[2]), "r"(a[3]), "r"(b[0]), "r"(b[1]));
}
__device__ __forceinline__ void mma_f16(float* c, const uint32_t* a, const uint32_t* b) {
    asm volatile("mma.sync.aligned.m16n8k16.row.col.f32.f16.f16.f32 "
        "{%0,%1,%2,%3}, {%4,%5,%6,%7}, {%8,%9}, {%0,%1,%2,%3};"
        : "+f"(c[0]), "+f"(c[1]), "+f"(c[2]), "+f"(c[3])
        : "r"(a[0]), "r"(a[1]), "r"(a[2]), "r"(a[3]), "r"(b[0]), "r"(b[1]));
}
// pack {lo,hi} f32 -> bf16x2 / f16x2 (lo in bits[15:0])
__device__ __forceinline__ uint32_t packbf2(float lo, float hi) {
    uint32_t r;
    asm("cvt.rn.bf16x2.f32 %0, %1, %2;" : "=r"(r) : "f"(hi), "f"(lo));
    return r;
}
__device__ __forceinline__ uint32_t packf16_2(float lo, float hi) {
    uint32_t r;
    asm("cvt.rn.f16x2.f32 %0, %1, %2;" : "=r"(r) : "f"(hi), "f"(lo));
    return r;
}
__device__ __forceinline__ uint32_t packh2(__nv_bfloat16 a, __nv_bfloat16 b) {
    __nv_bfloat162 t = __halves2bfloat162(a, b);
    return *reinterpret_cast<uint32_t*>(&t);
}
__device__ __forceinline__ uint32_t packhh(__half a, __half b) {
    __half2 t = __halves2half2(a, b);
    return *reinterpret_cast<uint32_t*>(&t);
}
#define SMEM_SWIZZLE_128B(off) ((off) ^ (((off) >> 3) & 0x70))

// ---------------------------------------------------------------------------
// Conversions: plain fp32 -> fp16 casts (activations and weights).
// ---------------------------------------------------------------------------
__global__ void convert_act3_kernel(const float* __restrict__ q,
                                    const float* __restrict__ k,
                                    const float* __restrict__ v,
                                    __half* __restrict__ o0,
                                    __half* __restrict__ o1,
                                    __half* __restrict__ o2)
{
    const float* in = (blockIdx.y == 0) ? q : (blockIdx.y == 1) ? k : v;
    __half* out = (blockIdx.y == 0) ? o0 : (blockIdx.y == 1) ? o1 : o2;
    size_t i = ((size_t)blockIdx.x * 256 + threadIdx.x) * 4;
    float4 x = *(const float4*)(in + i);
    *(uint32_t*)(out + i)     = packf16_2(x.x, x.y);
    *(uint32_t*)(out + i + 2) = packf16_2(x.z, x.w);
}

__global__ void convert_w4_kernel(const float* __restrict__ w0,
                                  const float* __restrict__ w1,
                                  const float* __restrict__ w2,
                                  const float* __restrict__ w3,
                                  __half* __restrict__ o0,
                                  __half* __restrict__ o1,
                                  __half* __restrict__ o2,
                                  __half* __restrict__ o3)
{
    const float* in = (blockIdx.y == 0) ? w0 : (blockIdx.y == 1) ? w1
                    : (blockIdx.y == 2) ? w2 : w3;
    __half* out = (blockIdx.y == 0) ? o0 : (blockIdx.y == 1) ? o1
                : (blockIdx.y == 2) ? o2 : o3;
    size_t i = ((size_t)blockIdx.x * 256 + threadIdx.x) * 4;
    float4 x = *(const float4*)(in + i);
    *(uint32_t*)(out + i)     = packf16_2(x.x, x.y);
    *(uint32_t*)(out + i + 2) = packf16_2(x.z, x.w);
}

// ---------------------------------------------------------------------------
// HMMA GEMM core (128x128 CTA tile), fp16 single x fp16 single, K=1024.
// OUT_MODE 0: fp32 [m][1024].  1: split bf16 head layout, scaled.
// 2: split fp16 head layout (V).
// ---------------------------------------------------------------------------
template<int OUT_MODE>
__device__ __forceinline__ void gemm_body(const __half* __restrict__ A,
                                          const __half* __restrict__ B,
                                          const float* __restrict__ bias,
                                          void* __restrict__ outv, float scale,
                                          char* smem)
{
    const uint32_t sb = smem_to_u32(smem);
    const int tid  = threadIdx.x;
    const int wid  = tid >> 5, lane = tid & 31;
    const int warp_m = wid >> 2;
    const int warp_n = wid & 3;
    const int bm = blockIdx.y * 128, bn = blockIdx.x * 128;

    const __half* Ag[4];
    const __half* Bg[4];
    uint32_t sOffA[4], sOffB[4];
#pragma unroll
    for (int i = 0; i < 4; i++) {
        int id = tid + i * 256;
        int grow = id >> 3, gch = id & 7;
        Ag[i] = A + (size_t)(bm + grow) * 1024 + gch * 8;
        Bg[i] = B + (size_t)(bn + grow) * 1024 + gch * 8;
        sOffA[i] = SMEM_SWIZZLE_128B((uint32_t)(grow * 128 + gch * 16));
        sOffB[i] = sOffA[i] + 16384;
    }

#pragma unroll
    for (int s = 0; s < 2; s++) {
        uint32_t base = sb + s * STAGE_BYTES;
        int k0 = s * BKC;
#pragma unroll
        for (int i = 0; i < 4; i++) {
            cp16(base + sOffA[i], Ag[i] + k0);
            cp16(base + sOffB[i], Bg[i] + k0);
        }
        cp_commit();
    }

    uint32_t arbase[4], axor[4];
    const int ahi = (lane >> 4) & 1;
#pragma unroll
    for (int mi = 0; mi < 4; mi++) {
        int row = warp_m * 64 + mi * 16 + (lane & 15);
        arbase[mi] = (uint32_t)row * 128;
        axor[mi]   = (uint32_t)(row & 7) * 16;
    }
    const int bsel = (lane >> 3) & 1;
    const int bRowP = warp_n * 32 + (((lane >> 4) & 1) << 3) + (lane & 7);
    uint32_t bpbase[2];
#pragma unroll
    for (int p = 0; p < 2; p++)
        bpbase[p] = (uint32_t)(bRowP + p * 16) * 128 + 16384;
    const uint32_t bpxor = (uint32_t)(lane & 7) * 16;

    float acc[4][4][4];
#pragma unroll
    for (int mi = 0; mi < 4; mi++)
#pragma unroll
        for (int ni = 0; ni < 4; ni++)
#pragma unroll
            for (int e = 0; e < 4; e++) acc[mi][ni][e] = 0.f;

    for (int c = 0; c < NCH; c++) {
        if (c < NCH - 1) asm volatile("cp.async.wait_group 1;" ::: "memory");
        else             asm volatile("cp.async.wait_group 0;" ::: "memory");
        __syncthreads();

        if (c + 2 < NCH) {
            uint32_t base = sb + ((c + 2) % STAGES) * STAGE_BYTES;
            int k0 = (c + 2) * BKC;
#pragma unroll
            for (int i = 0; i < 4; i++) {
                cp16(base + sOffA[i], Ag[i] + k0);
                cp16(base + sOffB[i], Bg[i] + k0);
            }
            cp_commit();
        }

        const uint32_t stage = sb + (c % STAGES) * STAGE_BYTES;
#pragma unroll
        for (int ks = 0; ks < 4; ks++) {
            uint32_t af[4][4], bf[2][4];
#pragma unroll
            for (int mi = 0; mi < 4; mi++)
                ldsm_x4(af[mi], stage + arbase[mi] +
                        ((uint32_t)((ks * 2 + ahi) * 16) ^ axor[mi]));
#pragma unroll
            for (int p = 0; p < 2; p++)
                ldsm_x4(bf[p], stage + bpbase[p] +
                        ((uint32_t)((ks * 2 + bsel) * 16) ^ bpxor));
#pragma unroll
            for (int mi = 0; mi < 4; mi++)
#pragma unroll
                for (int ni = 0; ni < 4; ni++)
                    mma_f16(acc[mi][ni], af[mi], &bf[ni >> 1][(ni & 1) * 2]);
        }
    }

    const int qrow = lane >> 2;
    const int qcol = (lane & 3) * 2;
#pragma unroll
    for (int mi = 0; mi < 4; mi++) {
        int m_lo = bm + warp_m * 64 + mi * 16 + qrow;
        int m_hi = m_lo + 8;
#pragma unroll
        for (int ni = 0; ni < 4; ni++) {
            int n = bn + warp_n * 32 + ni * 8 + qcol;
            float2 bv = *(const float2*)(bias + n);
            float x0 = acc[mi][ni][0] + bv.x, y0 = acc[mi][ni][1] + bv.y;
            float x1 = acc[mi][ni][2] + bv.x, y1 = acc[mi][ni][3] + bv.y;
            if (OUT_MODE >= 1) {
                x0 *= scale; y0 *= scale; x1 *= scale; y1 *= scale;
                char* out = (char*)outv;
                int hh = n >> 6, d0 = n & (HDIM - 1);
                int b0 = m_lo >> 11, t0 = m_lo & (TT - 1);
                int b1 = m_hi >> 11, t1 = m_hi & (TT - 1);
                size_t base0 = (((size_t)((b0*HH + hh)*TT + t0)) << 8);  // 128 elems * 2B
                size_t base1 = (((size_t)((b1*HH + hh)*TT + t1)) << 8);
                if (OUT_MODE == 1) {
                    __nv_bfloat16 hx0 = __float2bfloat16(x0), hy0 = __float2bfloat16(y0);
                    __nv_bfloat16 hx1 = __float2bfloat16(x1), hy1 = __float2bfloat16(y1);
                    *(uint32_t*)(out + base0 + d0*2)       = packh2(hx0, hy0);
                    *(uint32_t*)(out + base0 + 128 + d0*2) = packbf2(x0 - __bfloat162float(hx0),
                                                                     y0 - __bfloat162float(hy0));
                    *(uint32_t*)(out + base1 + d0*2)       = packh2(hx1, hy1);
                    *(uint32_t*)(out + base1 + 128 + d0*2) = packbf2(x1 - __bfloat162float(hx1),
                                                                     y1 - __bfloat162float(hy1));
                } else {
                    __half hx0 = __float2half_rn(x0), hy0 = __float2half_rn(y0);
                    __half hx1 = __float2half_rn(x1), hy1 = __float2half_rn(y1);
                    *(uint32_t*)(out + base0 + d0*2)       = packhh(hx0, hy0);
                    *(uint32_t*)(out + base0 + 128 + d0*2) = packf16_2(x0 - __half2float(hx0),
                                                                       y0 - __half2float(hy0));
                    *(uint32_t*)(out + base1 + d0*2)       = packhh(hx1, hy1);
                    *(uint32_t*)(out + base1 + 128 + d0*2) = packf16_2(x1 - __half2float(hx1),
                                                                       y1 - __half2float(hy1));
                }
            } else {
                float* out = (float*)outv;
                float2 lo; lo.x = x0; lo.y = y0;
                float2 hi; hi.x = x1; hi.y = y1;
                *(float2*)(out + (size_t)m_lo * DD + n) = lo;
                *(float2*)(out + (size_t)m_hi * DD + n) = hi;
            }
        }
    }
}

__global__ __launch_bounds__(256)
void hmma_gemm3_kernel(const __half* A0, const __half* A1, const __half* A2,
                       const __half* B0, const __half* B1, const __half* B2,
                       const float* b0, const float* b1, const float* b2,
                       __nv_bfloat16* o0, __nv_bfloat16* o1, __nv_bfloat16* o2,
                       float s0)
{
    extern __shared__ char smem[];
    const int z = blockIdx.z;
    if (z == 2) {
        gemm_body<2>(A2, B2, b2, o2, 1.0f, smem);          // V: fp16 split out
    } else if (z == 1) {
        gemm_body<1>(A1, B1, b1, o1, 1.0f, smem);          // K: bf16 split out
    } else {
        gemm_body<1>(A0, B0, b0, o0, s0, smem);            // Q: bf16 split, scaled
    }
}

__global__ __launch_bounds__(256)
void hmma_gemm_out_kernel(const __half* __restrict__ A,
                          const __half* __restrict__ B,
                          const float* __restrict__ bias,
                          float* __restrict__ out)
{
    extern __shared__ char smem[];
    gemm_body<0>(A, B, bias, out, 1.0f, smem);
}

// ---------------------------------------------------------------------------
// Flash attention (causal), heavy-first scheduling.
// S: bf16 3-term split. PV: P fp16 single x V fp16 split.
// Epilogue: single fp16 activations for the O projection.
// ---------------------------------------------------------------------------
__device__ __forceinline__ void fl_load_kv(uint32_t stage, const __nv_bfloat16* Kb,
                                           const __nv_bfloat16* Vb, int k0, int tid)
{
#pragma unroll
    for (int i = 0; i < 4; i++) {
        int id = tid + i * 256;
        int row = id >> 4, ch = id & 15;
        uint32_t o = (ch < 8) ? SMEM_SWIZZLE_128B((uint32_t)(row*128 + ch*16))
                              : 8192u + SMEM_SWIZZLE_128B((uint32_t)(row*128 + (ch-8)*16));
        cp16(stage + o, Kb + ((size_t)(k0 + row) << 7) + ch * 8);
    }
#pragma unroll
    for (int i = 0; i < 4; i++) {
        int id = tid + i * 256;
        int row = id >> 4, ch = id & 15;
        uint32_t o = (ch < 8) ? SMEM_SWIZZLE_128B((uint32_t)(row*128 + ch*16))
                              : 8192u + SMEM_SWIZZLE_128B((uint32_t)(row*128 + (ch-8)*16));
        cp16(stage + 16384u + o, Vb + ((size_t)(k0 + row) << 7) + ch * 8);
    }
}

__global__ __launch_bounds__(256)
void flash_hmma_kernel(const __nv_bfloat16* __restrict__ Qg,
                       const __nv_bfloat16* __restrict__ Kg,
                       const __nv_bfloat16* __restrict__ Vg,
                       __half* __restrict__ Xout)
{
    extern __shared__ char smem[];
    const uint32_t sb = smem_to_u32(smem);
    const int tid = threadIdx.x, wid = tid >> 5, lane = tid & 31;
    const int bh = blockIdx.x;
    const int qt = gridDim.y - 1 - blockIdx.y;     // heavy tiles first
    const int q0 = qt * 128;
    const int qbase = q0 + wid * 16;
    const int ntiles = 2 * qt + 2;

    const __nv_bfloat16* Qb = Qg + (((size_t)bh * TT + q0) << 7);
    const __nv_bfloat16* Kb = Kg + ((size_t)bh * TT << 7);
    const __nv_bfloat16* Vb = Vg + ((size_t)bh * TT << 7);

#pragma unroll
    for (int i = 0; i < 8; i++) {
        int id = tid + i * 256;
        int row = id >> 4, ch = id & 15;
        uint32_t o = (ch < 8) ? FL_QH + SMEM_SWIZZLE_128B((uint32_t)(row*128 + ch*16))
                              : FL_QL + SMEM_SWIZZLE_128B((uint32_t)(row*128 + (ch-8)*16));
        cp16(sb + o, Qb + ((size_t)row << 7) + ch * 8);
    }
    cp_commit();
    fl_load_kv(sb + FL_STG, Kb, Vb, 0, tid);
    cp_commit();

    const int ahi = (lane >> 4) & 1;
    const int arow = wid * 16 + (lane & 15);
    const uint32_t arb = (uint32_t)arow * 128;
    const uint32_t ax  = (uint32_t)(arow & 7) * 16;
    const int bsel = (lane >> 3) & 1;
    const int bRowP = (((lane >> 4) & 1) << 3) + (lane & 7);
    uint32_t bpb[4];
#pragma unroll
    for (int p = 0; p < 4; p++) bpb[p] = (uint32_t)(bRowP + p * 16) * 128;
    const uint32_t bpx = (uint32_t)(lane & 7) * 16;
    const int vhi = (lane >> 4) & 1;
    uint32_t vpb[4];
#pragma unroll
    for (int kc = 0; kc < 4; kc++)
        vpb[kc] = (uint32_t)(kc * 16 + (lane & 15)) * 128;
    const uint32_t vpx = (uint32_t)(lane & 7) * 16;

    float oacc[8][4];
#pragma unroll
    for (int nt = 0; nt < 8; nt++)
#pragma unroll
        for (int e = 0; e < 4; e++) oacc[nt][e] = 0.f;
    float m0 = -1e30f, m1 = -1e30f, l0 = 0.f, l1 = 0.f;

    for (int j = 0; j < ntiles; j++) {
        const int k0 = j * 64;
        if (j + 1 < ntiles) {
            fl_load_kv(sb + FL_STG + ((j + 1) & 1) * 32768u, Kb, Vb, (j + 1) * 64, tid);
            cp_commit();
            asm volatile("cp.async.wait_group 1;" ::: "memory");
        } else {
            asm volatile("cp.async.wait_group 0;" ::: "memory");
        }
        __syncthreads();
        const uint32_t stage = sb + FL_STG + (j & 1) * 32768u;

        if (k0 <= qbase + 15) {
            float sacc[8][4];
#pragma unroll
            for (int nt = 0; nt < 8; nt++)
#pragma unroll
                for (int e = 0; e < 4; e++) sacc[nt][e] = 0.f;

            // S = qh*kh + ql*kh + qh*kl  (paired K loads)
#pragma unroll
            for (int ks = 0; ks < 4; ks++) {
                const uint32_t koff = (((uint32_t)((ks*2 + ahi)*16)) ^ ax);
                const uint32_t bko  = (((uint32_t)((ks*2 + bsel)*16)) ^ bpx);
                uint32_t Ah[4], Al[4];
                ldsm_x4(Ah, sb + FL_QH + arb + koff);
                ldsm_x4(Al, sb + FL_QL + arb + koff);
#pragma unroll
                for (int p = 0; p < 4; p++) {
                    uint32_t Bh[4], Bl[4];
                    ldsm_x4(Bh, stage + bpb[p] + bko);
                    ldsm_x4(Bl, stage + 8192u + bpb[p] + bko);
                    mma_bf16(sacc[2*p],   Ah, Bh);
                    mma_bf16(sacc[2*p],   Al, Bh);
                    mma_bf16(sacc[2*p],   Ah, Bl);
                    mma_bf16(sacc[2*p+1], Ah, Bh + 2);
                    mma_bf16(sacc[2*p+1], Al, Bh + 2);
                    mma_bf16(sacc[2*p+1], Ah, Bl + 2);
                }
            }

            // causal mask
            const int qg0 = qbase + (lane >> 2);
            const int qg1 = qg0 + 8;
            if (k0 + 63 > qbase) {
#pragma unroll
                for (int nt = 0; nt < 8; nt++) {
                    int kgb = k0 + nt * 8 + (lane & 3) * 2;
                    if (kgb     > qg0) sacc[nt][0] = -1e30f;
                    if (kgb + 1 > qg0) sacc[nt][1] = -1e30f;
                    if (kgb     > qg1) sacc[nt][2] = -1e30f;
                    if (kgb + 1 > qg1) sacc[nt][3] = -1e30f;
                }
            }

            // online softmax (log2 domain)
            float mx0 = -1e30f, mx1 = -1e30f;
#pragma unroll
            for (int nt = 0; nt < 8; nt++) {
                mx0 = fmaxf(mx0, fmaxf(sacc[nt][0], sacc[nt][1]));
                mx1 = fmaxf(mx1, fmaxf(sacc[nt][2], sacc[nt][3]));
            }
            mx0 = fmaxf(mx0, __shfl_xor_sync(0xffffffffu, mx0, 1));
            mx0 = fmaxf(mx0, __shfl_xor_sync(0xffffffffu, mx0, 2));
            mx1 = fmaxf(mx1, __shfl_xor_sync(0xffffffffu, mx1, 1));
            mx1 = fmaxf(mx1, __shfl_xor_sync(0xffffffffu, mx1, 2));
            const float nm0 = fmaxf(m0, mx0), nm1 = fmaxf(m1, mx1);
            const float sc0 = exp2f(m0 - nm0), sc1 = exp2f(m1 - nm1);
            float sum0 = 0.f, sum1 = 0.f;
#pragma unroll
            for (int nt = 0; nt < 8; nt++) {
                sacc[nt][0] = exp2f(sacc[nt][0] - nm0); sum0 += sacc[nt][0];
                sacc[nt][1] = exp2f(sacc[nt][1] - nm0); sum0 += sacc[nt][1];
                sacc[nt][2] = exp2f(sacc[nt][2] - nm1); sum1 += sacc[nt][2];
                sacc[nt][3] = exp2f(sacc[nt][3] - nm1); sum1 += sacc[nt][3];
            }
            sum0 += __shfl_xor_sync(0xffffffffu, sum0, 1);
            sum0 += __shfl_xor_sync(0xffffffffu, sum0, 2);
            sum1 += __shfl_xor_sync(0xffffffffu, sum1, 1);
            sum1 += __shfl_xor_sync(0xffffffffu, sum1, 2);
            l0 = l0 * sc0 + sum0;  l1 = l1 * sc1 + sum1;
            m0 = nm0;  m1 = nm1;
#pragma unroll
            for (int nt = 0; nt < 8; nt++) {
                oacc[nt][0] *= sc0; oacc[nt][1] *= sc0;
                oacc[nt][2] *= sc1; oacc[nt][3] *= sc1;
            }

            // P -> single fp16 fragments
            uint32_t phg[8], phg8[8];
#pragma unroll
            for (int nt = 0; nt < 8; nt++) {
                phg[nt]  = packf16_2(sacc[nt][0], sacc[nt][1]);
                phg8[nt] = packf16_2(sacc[nt][2], sacc[nt][3]);
            }

            // O += P*Vh + P*Vl  (V fp16 split; paired V loads)
#pragma unroll
            for (int kc = 0; kc < 4; kc++) {
                uint32_t Af[4];
                Af[0] = phg[2*kc];   Af[1] = phg8[2*kc];
                Af[2] = phg[2*kc+1]; Af[3] = phg8[2*kc+1];
#pragma unroll
                for (int p = 0; p < 4; p++) {
                    const uint32_t voff = vpb[kc] + (((uint32_t)((2*p + vhi)*16)) ^ vpx);
                    uint32_t Vh[4], Vl[4];
                    ldsm_x4_trans(Vh, stage + 16384u + voff);
                    ldsm_x4_trans(Vl, stage + 24576u + voff);
                    mma_f16(oacc[2*p],   Af, Vh);
                    mma_f16(oacc[2*p],   Af, Vl);
                    mma_f16(oacc[2*p+1], Af, Vh + 2);
                    mma_f16(oacc[2*p+1], Af, Vl + 2);
                }
            }
        }
        __syncthreads();
    }

    // epilogue: normalize, single fp16, write activations (stride 1024)
    const int b = bh >> 4, h = bh & 15;
    const int t0 = qbase + (lane >> 2);
    const int t1 = t0 + 8;
    const size_t r0 = (size_t)(b * TT + t0) * 1024;
    const size_t r1 = (size_t)(b * TT + t1) * 1024;
    const float i0 = 1.f / l0, i1 = 1.f / l1;
    const int cbase = h * 64 + (lane & 3) * 2;
#pragma unroll
    for (int nt = 0; nt < 8; nt++) {
        int c = cbase + nt * 8;
        *(uint32_t*)(Xout + r0 + c) = packf16_2(oacc[nt][0] * i0, oacc[nt][1] * i0);
        *(uint32_t*)(Xout + r1 + c) = packf16_2(oacc[nt][2] * i1, oacc[nt][3] * i1);
    }
}

// ---------------------------------------------------------------------------
extern "C" void kernel_launch(void* const* d_in, const int* in_sizes, int n_in,
                              void* d_out, int out_size)
{
    const float* q  = (const float*)d_in[0];
    const float* k  = (const float*)d_in[1];
    const float* v  = (const float*)d_in[2];
    const float* wq = (const float*)d_in[3];
    const float* bq = (const float*)d_in[4];
    const float* wk = (const float*)d_in[5];
    const float* bk = (const float*)d_in[6];
    const float* wv = (const float*)d_in[7];
    const float* bv = (const float*)d_in[8];
    const float* wo = (const float*)d_in[9];
    const float* bo = (const float*)d_in[10];
    float* out = (float*)d_out;

    __nv_bfloat16 *gqc, *gkc, *gvc;
    __half *gx0, *gx1, *gx2, *gw0, *gw1, *gw2, *gw3;
    cudaGetSymbolAddress((void**)&gqc, g_qc);
    cudaGetSymbolAddress((void**)&gkc, g_kc);
    cudaGetSymbolAddress((void**)&gvc, g_vc);
    cudaGetSymbolAddress((void**)&gx0, g_x0);
    cudaGetSymbolAddress((void**)&gx1, g_x1);
    cudaGetSymbolAddress((void**)&gx2, g_x2);
    cudaGetSymbolAddress((void**)&gw0, g_w0);
    cudaGetSymbolAddress((void**)&gw1, g_w1);
    cudaGetSymbolAddress((void**)&gw2, g_w2);
    cudaGetSymbolAddress((void**)&gw3, g_w3);

    cudaFuncSetAttribute(hmma_gemm3_kernel,
                         cudaFuncAttributeMaxDynamicSharedMemorySize, GEMM_SMEM_SZ);
    cudaFuncSetAttribute(hmma_gemm_out_kernel,
                         cudaFuncAttributeMaxDynamicSharedMemorySize, GEMM_SMEM_SZ);
    cudaFuncSetAttribute(flash_hmma_kernel,
                         cudaFuncAttributeMaxDynamicSharedMemorySize, FL_SMEM);

    // Converts: plain fp16 casts (grid: rows*1024/1024 blocks of 256x4 elems)
    convert_act3_kernel<<<dim3(MM * 1024 / 1024, 3), 256>>>(q, k, v, gx0, gx1, gx2);
    convert_w4_kernel<<<dim3(DD * 1024 / 1024, 4), 256>>>(wq, wk, wv, wo, gw0, gw1, gw2, gw3);

    // Batched QKV projections (Q pre-scaled; V emitted as fp16 split)
    hmma_gemm3_kernel<<<dim3(DD/128, MM/128, 3), 256, GEMM_SMEM_SZ>>>(
        gx0, gx1, gx2, gw0, gw1, gw2, bq, bk, bv, gqc, gkc, gvc, QSCALE);

    // Attention (heavy q-tiles first; writes fp16 activations into gx0)
    flash_hmma_kernel<<<dim3(BB*HH, TT/128), 256, FL_SMEM>>>(gqc, gkc, gvc, gx0);

    // Output projection
    hmma_gemm_out_kernel<<<dim3(DD/128, MM/128), 256, GEMM_SMEM_SZ>>>(gx0, gw3, bo, out);
}